// round 10
// baseline (speedup 1.0000x reference)
#include <cuda_runtime.h>
#include <cuda_fp16.h>
#include <math.h>
#include <stdint.h>

#define Bb 2
#define Ss 2048
#define Dd 4096
#define Hh 32
#define HDh 128
#define HALFh 64
#define ALa 10
#define Mtok (Bb*Ss)

// ---- wide fused fp16x3 GEMM config: 256x128 CTA, 8 warps of 64x64 ----
#define GBM 256
#define GBN 128
#define BKh 64                       // halves per K-chunk = 128B row
#define HROWB 144                    // smem row bytes (128 data + 16 pad)
#define OPA (GBM*HROWB)              // A operand (256 rows) = 36864 B
#define OPBB (GBN*HROWB)             // B operand (128 rows) = 18432 B
#define STAGE_B (2*OPA + 2*OPBB)     // 110592 B
#define NSTAGE 2
#define GEMM_SMEM (NSTAGE*STAGE_B)   // 221184 B

// ---- flash config ----
#define FQ 128
#define FKV 64
#define FROWB 272                    // 128 halves + 8 pad = 272 B
#define QHOFF 0
#define QLOFF (128*FROWB)
#define KHOFF (QLOFF + 128*FROWB)
#define KLOFF (KHOFF + 64*FROWB)
#define VHOFF (KLOFF + 64*FROWB)
#define VLOFF (VHOFF + 64*FROWB)
#define FLASH_SMEM (VLOFF + 64*FROWB)   // 139264 B

#define KSPL 8

// ---------------- scratch (static device globals) ----------------
__device__ float g_q[Mtok*Dd];
__device__ float g_k[Mtok*Dd];
__device__ float g_v[Mtok*Dd];
__device__ float g_attn[Mtok*Dd];
__device__ float g_ak[Bb*ALa*Dd];
__device__ float g_av[Bb*ALa*Dd];
__device__ float g_pk[KSPL*Bb*ALa*Dd];
__device__ float g_pv[KSPL*Bb*ALa*Dd];

__device__ __half g_ah[Mtok*Dd];   // x split; later holds attn split
__device__ __half g_al[Mtok*Dd];
__device__ __half g_wqh[Dd*Dd], g_wql[Dd*Dd];
__device__ __half g_wkh[Dd*Dd], g_wkl[Dd*Dd];
__device__ __half g_wvh[Dd*Dd], g_wvl[Dd*Dd];
__device__ __half g_woh[Dd*Dd], g_wol[Dd*Dd];
__device__ __half g_qh[Mtok*Dd], g_ql[Mtok*Dd];
__device__ __half g_kh[Mtok*Dd], g_kl[Mtok*Dd];
__device__ __half g_vh[Mtok*Dd], g_vl[Mtok*Dd];

// ---------------- helpers ----------------
__device__ __forceinline__ uint32_t s2u(const void* p){
    uint32_t r;
    asm("{ .reg .u64 t; cvta.to.shared.u64 t, %1; cvt.u32.u64 %0, t; }" : "=r"(r) : "l"(p));
    return r;
}

__device__ __forceinline__ void ldsm_x4(uint32_t* r, uint32_t addr){
    asm volatile("ldmatrix.sync.aligned.m8n8.x4.shared.b16 {%0,%1,%2,%3}, [%4];"
                 : "=r"(r[0]), "=r"(r[1]), "=r"(r[2]), "=r"(r[3]) : "r"(addr));
}
__device__ __forceinline__ void ldsm_x4t(uint32_t* r, uint32_t addr){
    asm volatile("ldmatrix.sync.aligned.m8n8.x4.trans.shared.b16 {%0,%1,%2,%3}, [%4];"
                 : "=r"(r[0]), "=r"(r[1]), "=r"(r[2]), "=r"(r[3]) : "r"(addr));
}

__device__ __forceinline__ void mma_h(float* d, const uint32_t* a, uint32_t b0, uint32_t b1){
    asm volatile(
        "mma.sync.aligned.m16n8k16.row.col.f32.f16.f16.f32 "
        "{%0,%1,%2,%3}, {%4,%5,%6,%7}, {%8,%9}, {%0,%1,%2,%3};"
        : "+f"(d[0]), "+f"(d[1]), "+f"(d[2]), "+f"(d[3])
        : "r"(a[0]), "r"(a[1]), "r"(a[2]), "r"(a[3]), "r"(b0), "r"(b1));
}

__device__ __forceinline__ uint32_t packh2(float lo, float hi){
    uint32_t r;
    asm("cvt.rn.f16x2.f32 %0, %1, %2;" : "=r"(r) : "f"(hi), "f"(lo));
    return r;
}

__device__ __forceinline__ void split_pack(float f0, float f1, uint32_t& hi, uint32_t& lo){
    __half h0 = __float2half_rn(f0), h1 = __float2half_rn(f1);
    __half2 hh = __halves2half2(h0, h1);
    hi = *reinterpret_cast<uint32_t*>(&hh);
    lo = packh2(f0 - __half2float(h0), f1 - __half2float(h1));
}

// ---------------- convert: fp32 -> fp16 hi/lo ----------------
__global__ void conv_split(const float* __restrict__ s, __half* __restrict__ hi,
                           __half* __restrict__ lo, int n)
{
    int i = (blockIdx.x*256 + threadIdx.x) * 4;
    if (i >= n) return;
    float4 v = *(const float4*)(s + i);
    __half h0 = __float2half_rn(v.x), h1 = __float2half_rn(v.y);
    __half h2 = __float2half_rn(v.z), h3 = __float2half_rn(v.w);
    *(__half2*)(hi + i)     = __halves2half2(h0, h1);
    *(__half2*)(hi + i + 2) = __halves2half2(h2, h3);
    *(__half2*)(lo + i)     = __halves2half2(__float2half_rn(v.x - __half2float(h0)),
                                             __float2half_rn(v.y - __half2float(h1)));
    *(__half2*)(lo + i + 2) = __halves2half2(__float2half_rn(v.z - __half2float(h2)),
                                             __float2half_rn(v.w - __half2float(h3)));
}

// ---------------- wide fused fp16x3 NT GEMM (M multiple of 256) ----------------
__global__ __launch_bounds__(256, 1) void gemm_h3w(
    const __half* __restrict__ Ah, const __half* __restrict__ Al,
    const __half* __restrict__ Bh, const __half* __restrict__ Bl,
    float* __restrict__ C, int M, int N, int K)
{
    extern __shared__ char smg[];
    const uint32_t sbase = s2u(smg);
    const int t = threadIdx.x;
    const int m0 = blockIdx.y * GBM;
    const int n0 = blockIdx.x * GBN;
    const int NCH = K / BKh;

    const int lane = t & 31;
    const int wid  = t >> 5;
    const int wm   = wid & 3;            // 4 warps along M (64 rows each)
    const int wn   = wid >> 2;           // 2 warps along N (64 cols each)

    float d[4][8][4];
    #pragma unroll
    for (int mt = 0; mt < 4; mt++)
        #pragma unroll
        for (int nt = 0; nt < 8; nt++)
            #pragma unroll
            for (int c = 0; c < 4; c++) d[mt][nt][c] = 0.f;

    const uint32_t aRow = (uint32_t)(wm*64 + (lane & 7) + ((lane >> 3) & 1)*8);
    const uint32_t aKof = (uint32_t)(((lane >> 4) & 1) << 4);
    const uint32_t bRow = (uint32_t)(wn*64 + (lane & 7) + ((lane >> 4) & 1)*8);
    const uint32_t bKof = (uint32_t)(((lane >> 3) & 1) << 4);

    const int ldr = t >> 3;      // 0..31
    const int ldq = t & 7;       // 16B chunk within 128B row

    auto prefetch = [&](int chunk, int stage){
        const int k0 = chunk * BKh;
        const uint32_t st = sbase + (uint32_t)stage * STAGE_B;
        #pragma unroll
        for (int i = 0; i < 8; i++) {        // A: 256 rows
            int row = ldr + i*32;
            size_t goa = (size_t)(m0 + row) * K + k0 + ldq*8;
            uint32_t so = (uint32_t)row * HROWB + (uint32_t)ldq * 16u;
            asm volatile("cp.async.cg.shared.global [%0], [%1], 16;" :: "r"(st + so), "l"(Ah + goa));
            asm volatile("cp.async.cg.shared.global [%0], [%1], 16;" :: "r"(st + OPA + so), "l"(Al + goa));
        }
        #pragma unroll
        for (int i = 0; i < 4; i++) {        // B: 128 rows
            int row = ldr + i*32;
            size_t gob = (size_t)(n0 + row) * K + k0 + ldq*8;
            uint32_t so = (uint32_t)row * HROWB + (uint32_t)ldq * 16u;
            asm volatile("cp.async.cg.shared.global [%0], [%1], 16;" :: "r"(st + 2*OPA + so), "l"(Bh + gob));
            asm volatile("cp.async.cg.shared.global [%0], [%1], 16;" :: "r"(st + 2*OPA + OPBB + so), "l"(Bl + gob));
        }
        asm volatile("cp.async.commit_group;" ::: "memory");
    };

    prefetch(0, 0);
    prefetch(1, 1);

    int stage = 0;
    for (int n = 0; n < NCH; n++) {
        asm volatile("cp.async.wait_group %0;" :: "n"(NSTAGE-1) : "memory");
        __syncthreads();

        const uint32_t st = sbase + (uint32_t)stage * STAGE_B;
        const uint32_t sAh = st, sAl = st + OPA, sBh = st + 2*OPA, sBl = st + 2*OPA + OPBB;

        #pragma unroll
        for (int ks = 0; ks < 4; ks++) {
            const uint32_t kb = (uint32_t)ks * 32u;
            uint32_t ah[4][4], al[4][4];
            #pragma unroll
            for (int mt = 0; mt < 4; mt++) {
                ldsm_x4(ah[mt], sAh + (aRow + mt*16u)*HROWB + aKof + kb);
                ldsm_x4(al[mt], sAl + (aRow + mt*16u)*HROWB + aKof + kb);
            }
            #pragma unroll
            for (int np = 0; np < 4; np++) {
                uint32_t bh[4], bl[4];
                ldsm_x4(bh, sBh + (bRow + np*16u)*HROWB + bKof + kb);
                ldsm_x4(bl, sBl + (bRow + np*16u)*HROWB + bKof + kb);
                #pragma unroll
                for (int mt = 0; mt < 4; mt++) {
                    mma_h(d[mt][2*np],   ah[mt], bh[0], bh[1]);
                    mma_h(d[mt][2*np],   ah[mt], bl[0], bl[1]);
                    mma_h(d[mt][2*np],   al[mt], bh[0], bh[1]);
                    mma_h(d[mt][2*np+1], ah[mt], bh[2], bh[3]);
                    mma_h(d[mt][2*np+1], ah[mt], bl[2], bl[3]);
                    mma_h(d[mt][2*np+1], al[mt], bh[2], bh[3]);
                }
            }
        }
        __syncthreads();

        int pn = n + NSTAGE; if (pn >= NCH) pn = 0;
        prefetch(pn, stage);
        stage ^= 1;
    }

    const int g  = lane >> 2;
    const int tq = lane & 3;
    #pragma unroll
    for (int mt = 0; mt < 4; mt++) {
        int row = m0 + wm*64 + mt*16 + g;
        #pragma unroll
        for (int nt = 0; nt < 8; nt++) {
            int col = n0 + wn*64 + nt*8 + 2*tq;
            *(float2*)&C[(size_t)row * N + col]     = make_float2(d[mt][nt][0], d[mt][nt][1]);
            *(float2*)&C[(size_t)(row+8) * N + col] = make_float2(d[mt][nt][2], d[mt][nt][3]);
        }
    }
}

// ---------------- skinny adapter GEMM (M=20, fp32, split-K) ----------------
__global__ __launch_bounds__(128) void gemm_skinny(
    const float* __restrict__ Aad, const float* __restrict__ wk, const float* __restrict__ wv)
{
    __shared__ float As[20][33];
    __shared__ float Bs[128][33];
    const int t = threadIdx.x;
    const int n0 = blockIdx.x * 128;
    const int kz = blockIdx.y;
    const float* W = blockIdx.z ? wv : wk;
    float* P = (blockIdx.z ? g_pv : g_pk) + (size_t)kz * (20*4096);

    float acc[20];
    #pragma unroll
    for (int m = 0; m < 20; m++) acc[m] = 0.f;

    for (int k0 = kz*512; k0 < kz*512 + 512; k0 += 32) {
        for (int i = t; i < 640; i += 128) {
            int r = i >> 5, c = i & 31;
            As[r][c] = Aad[(size_t)r*4096 + k0 + c];
        }
        #pragma unroll
        for (int i = 0; i < 8; i++) {
            int idx = t + i*128;
            int r = idx >> 3, cq = idx & 7;
            float4 v = *(const float4*)&W[(size_t)(n0 + r)*4096 + k0 + cq*4];
            Bs[r][cq*4+0] = v.x; Bs[r][cq*4+1] = v.y;
            Bs[r][cq*4+2] = v.z; Bs[r][cq*4+3] = v.w;
        }
        __syncthreads();
        #pragma unroll
        for (int k = 0; k < 32; k++) {
            float bv = Bs[t][k];
            #pragma unroll
            for (int m = 0; m < 20; m++) acc[m] += As[m][k] * bv;
        }
        __syncthreads();
    }
    #pragma unroll
    for (int m = 0; m < 20; m++) P[(size_t)m*4096 + n0 + t] = acc[m];
}

__global__ void skinny_reduce()
{
    int i = blockIdx.x*256 + threadIdx.x;
    if (i >= 20*4096) return;
    float sk = 0.f, sv = 0.f;
    #pragma unroll
    for (int z = 0; z < KSPL; z++) {
        sk += g_pk[(size_t)z*(20*4096) + i];
        sv += g_pv[(size_t)z*(20*4096) + i];
    }
    g_ak[i] = sk;
    g_av[i] = sv;
}

// ---------------- RoPE (fp32 in place) + split to fp16 hi/lo ----------------
__global__ void rope_split(float* __restrict__ T, __half* __restrict__ Th, __half* __restrict__ Tl,
                           const float* __restrict__ cosT, const float* __restrict__ sinT)
{
    int idx = blockIdx.x * blockDim.x + threadIdx.x;
    if (idx >= Bb*Ss*Hh*HALFh) return;
    int p = idx & (HALFh - 1);
    int s = (idx >> 11) & (Ss - 1);
    float c  = cosT[s*HALFh + p];
    float sn = sinT[s*HALFh + p];
    float2 v = *(float2*)&T[2*(size_t)idx];
    float2 r;
    r.x = v.x * c - v.y * sn;
    r.y = v.x * sn + v.y * c;
    *(float2*)&T[2*(size_t)idx] = r;
    __half h0 = __float2half_rn(r.x), h1 = __float2half_rn(r.y);
    *(__half2*)(Th + 2*(size_t)idx) = __halves2half2(h0, h1);
    *(__half2*)(Tl + 2*(size_t)idx) = __halves2half2(__float2half_rn(r.x - __half2float(h0)),
                                                     __float2half_rn(r.y - __half2float(h1)));
}

// ---------------- flash attention via fp16x3 mma.sync ----------------
__global__ __launch_bounds__(256, 1) void flash_h()
{
    extern __shared__ char fsm[];
    const uint32_t sb = s2u(fsm);
    const int t = threadIdx.x, lane = t & 31, w = t >> 5;
    const int bh = blockIdx.y, b = bh >> 5, h = bh & 31;
    const int q0 = (int)(gridDim.x - 1 - blockIdx.x) * FQ;
    const size_t headbase = (size_t)b * Ss * Dd + (size_t)h * HDh;
    const int g = lane >> 2, tq = lane & 3;
    const float rscale = 0.08838834764831844f;
    const float NEGINF = __int_as_float(0xff800000);

    {
        const __half* qh = g_qh + headbase + (size_t)q0 * Dd;
        const __half* ql = g_ql + headbase + (size_t)q0 * Dd;
        #pragma unroll
        for (int i = 0; i < 8; i++) {
            int idx = t + i*256;
            int r = idx >> 4, cq = idx & 15;
            asm volatile("cp.async.cg.shared.global [%0], [%1], 16;"
                :: "r"(sb + QHOFF + (uint32_t)(r*FROWB + cq*16)), "l"(qh + (size_t)r*Dd + cq*8));
            asm volatile("cp.async.cg.shared.global [%0], [%1], 16;"
                :: "r"(sb + QLOFF + (uint32_t)(r*FROWB + cq*16)), "l"(ql + (size_t)r*Dd + cq*8));
        }
        asm volatile("cp.async.commit_group;" ::: "memory");
    }

    const uint32_t aRow = (uint32_t)(w*16 + (lane & 7) + ((lane >> 3) & 1)*8);
    const uint32_t aKof = (uint32_t)(((lane >> 4) & 1) << 4);
    const uint32_t bRow = (uint32_t)((lane & 7) + ((lane >> 4) & 1)*8);
    const uint32_t bKof = (uint32_t)(((lane >> 3) & 1) << 4);
    const uint32_t vRow = (uint32_t)((lane & 7) + ((lane >> 3) & 1)*8);
    const uint32_t vDof = (uint32_t)(((lane >> 4) & 1) << 4);

    float o[16][4];
    #pragma unroll
    for (int nt = 0; nt < 16; nt++) { o[nt][0]=o[nt][1]=o[nt][2]=o[nt][3]=0.f; }
    float m0r = -1e30f, m1r = -1e30f, l0r = 0.f, l1r = 0.f;

    const int ig0 = q0 + w*16 + g;
    const int ig1 = ig0 + 8;

    for (int j0 = 0; j0 < q0 + FQ; j0 += FKV) {
        __syncthreads();
        {
            const __half* kh = g_kh + headbase + (size_t)j0 * Dd;
            const __half* kl = g_kl + headbase + (size_t)j0 * Dd;
            const __half* vh = g_vh + headbase + (size_t)j0 * Dd;
            const __half* vl = g_vl + headbase + (size_t)j0 * Dd;
            #pragma unroll
            for (int i = 0; i < 4; i++) {
                int idx = t + i*256;
                int r = idx >> 4, cq = idx & 15;
                uint32_t so = (uint32_t)(r*FROWB + cq*16);
                size_t go = (size_t)r*Dd + cq*8;
                asm volatile("cp.async.cg.shared.global [%0], [%1], 16;" :: "r"(sb + KHOFF + so), "l"(kh + go));
                asm volatile("cp.async.cg.shared.global [%0], [%1], 16;" :: "r"(sb + KLOFF + so), "l"(kl + go));
                asm volatile("cp.async.cg.shared.global [%0], [%1], 16;" :: "r"(sb + VHOFF + so), "l"(vh + go));
                asm volatile("cp.async.cg.shared.global [%0], [%1], 16;" :: "r"(sb + VLOFF + so), "l"(vl + go));
            }
            asm volatile("cp.async.commit_group;" ::: "memory");
        }
        asm volatile("cp.async.wait_group 0;" ::: "memory");
        __syncthreads();

        float s[8][4];
        #pragma unroll
        for (int nt = 0; nt < 8; nt++) { s[nt][0]=s[nt][1]=s[nt][2]=s[nt][3]=0.f; }
        #pragma unroll
        for (int ks = 0; ks < 8; ks++) {
            const uint32_t kb = (uint32_t)ks * 32u;
            uint32_t ah[4], al_[4];
            ldsm_x4(ah,  sb + QHOFF + aRow*FROWB + aKof + kb);
            ldsm_x4(al_, sb + QLOFF + aRow*FROWB + aKof + kb);
            #pragma unroll
            for (int np = 0; np < 4; np++) {
                uint32_t bhf[4], blf[4];
                ldsm_x4(bhf, sb + KHOFF + (bRow + np*16u)*FROWB + bKof + kb);
                ldsm_x4(blf, sb + KLOFF + (bRow + np*16u)*FROWB + bKof + kb);
                mma_h(s[2*np],   ah,  bhf[0], bhf[1]);
                mma_h(s[2*np],   ah,  blf[0], blf[1]);
                mma_h(s[2*np],   al_, bhf[0], bhf[1]);
                mma_h(s[2*np+1], ah,  bhf[2], bhf[3]);
                mma_h(s[2*np+1], ah,  blf[2], blf[3]);
                mma_h(s[2*np+1], al_, bhf[2], bhf[3]);
            }
        }

        float mx0 = -1e30f, mx1 = -1e30f;
        #pragma unroll
        for (int nt = 0; nt < 8; nt++) {
            int jg = j0 + nt*8 + 2*tq;
            s[nt][0] = (jg   > ig0) ? NEGINF : s[nt][0]*rscale;
            s[nt][1] = (jg+1 > ig0) ? NEGINF : s[nt][1]*rscale;
            s[nt][2] = (jg   > ig1) ? NEGINF : s[nt][2]*rscale;
            s[nt][3] = (jg+1 > ig1) ? NEGINF : s[nt][3]*rscale;
            mx0 = fmaxf(mx0, fmaxf(s[nt][0], s[nt][1]));
            mx1 = fmaxf(mx1, fmaxf(s[nt][2], s[nt][3]));
        }
        mx0 = fmaxf(mx0, __shfl_xor_sync(0xffffffffu, mx0, 1));
        mx0 = fmaxf(mx0, __shfl_xor_sync(0xffffffffu, mx0, 2));
        mx1 = fmaxf(mx1, __shfl_xor_sync(0xffffffffu, mx1, 1));
        mx1 = fmaxf(mx1, __shfl_xor_sync(0xffffffffu, mx1, 2));
        float mn0 = fmaxf(m0r, mx0), mn1 = fmaxf(m1r, mx1);
        float co0 = __expf(m0r - mn0), co1 = __expf(m1r - mn1);
        float sum0 = 0.f, sum1 = 0.f;
        #pragma unroll
        for (int nt = 0; nt < 8; nt++) {
            s[nt][0] = __expf(s[nt][0] - mn0);
            s[nt][1] = __expf(s[nt][1] - mn0);
            s[nt][2] = __expf(s[nt][2] - mn1);
            s[nt][3] = __expf(s[nt][3] - mn1);
            sum0 += s[nt][0] + s[nt][1];
            sum1 += s[nt][2] + s[nt][3];
        }
        sum0 += __shfl_xor_sync(0xffffffffu, sum0, 1);
        sum0 += __shfl_xor_sync(0xffffffffu, sum0, 2);
        sum1 += __shfl_xor_sync(0xffffffffu, sum1, 1);
        sum1 += __shfl_xor_sync(0xffffffffu, sum1, 2);
        l0r = l0r * co0 + sum0;  m0r = mn0;
        l1r = l1r * co1 + sum1;  m1r = mn1;

        #pragma unroll
        for (int nt = 0; nt < 16; nt++) {
            o[nt][0] *= co0; o[nt][1] *= co0;
            o[nt][2] *= co1; o[nt][3] *= co1;
        }

        #pragma unroll
        for (int ks = 0; ks < 4; ks++) {
            uint32_t ph[4], pl[4];
            split_pack(s[2*ks][0],   s[2*ks][1],   ph[0], pl[0]);
            split_pack(s[2*ks][2],   s[2*ks][3],   ph[1], pl[1]);
            split_pack(s[2*ks+1][0], s[2*ks+1][1], ph[2], pl[2]);
            split_pack(s[2*ks+1][2], s[2*ks+1][3], ph[3], pl[3]);
            const uint32_t krow = (uint32_t)(ks*16) + vRow;
            #pragma unroll
            for (int np = 0; np < 8; np++) {
                uint32_t vhf[4], vlf[4];
                ldsm_x4t(vhf, sb + VHOFF + krow*FROWB + (uint32_t)(np*32) + vDof);
                ldsm_x4t(vlf, sb + VLOFF + krow*FROWB + (uint32_t)(np*32) + vDof);
                mma_h(o[2*np],   ph, vhf[0], vhf[1]);
                mma_h(o[2*np],   ph, vlf[0], vlf[1]);
                mma_h(o[2*np],   pl, vhf[0], vhf[1]);
                mma_h(o[2*np+1], ph, vhf[2], vhf[3]);
                mma_h(o[2*np+1], ph, vlf[2], vlf[3]);
                mma_h(o[2*np+1], pl, vhf[2], vhf[3]);
            }
        }
    }

    float inv0 = 1.f / l0r, inv1 = 1.f / l1r;
    float* Og = g_attn + headbase + (size_t)(q0 + w*16) * Dd;
    #pragma unroll
    for (int nt = 0; nt < 16; nt++) {
        *(float2*)&Og[(size_t)g*Dd     + nt*8 + 2*tq] = make_float2(o[nt][0]*inv0, o[nt][1]*inv0);
        *(float2*)&Og[(size_t)(g+8)*Dd + nt*8 + 2*tq] = make_float2(o[nt][2]*inv1, o[nt][3]*inv1);
    }
}

// ---------------- adapter attention (+ writes fp16 split of final attn) ----------------
__global__ __launch_bounds__(128) void adapter_kernel(const float* __restrict__ gate)
{
    __shared__ __align__(16) float ak[ALa][HDh];
    __shared__ __align__(16) float av[ALa][HDh];
    const int t = threadIdx.x;
    const int bh = blockIdx.y;
    const int b = bh >> 5, h = bh & 31;
    const int s0 = blockIdx.x * 4;

    #pragma unroll
    for (int r = 0; r < ALa; r++) {
        int idx = t + r*128;
        int j = idx >> 7, d = idx & 127;
        ak[j][d] = g_ak[(size_t)(b*ALa + j) * Dd + h*HDh + d];
        av[j][d] = g_av[(size_t)(b*ALa + j) * Dd + h*HDh + d];
    }
    __syncthreads();

    const int w = t >> 5, lane = t & 31;
    const int s = s0 + w;
    const size_t base = (size_t)(b*Ss + s) * Dd + h*HDh;
    const float rscale = 0.08838834764831844f;

    float4 qv = *(const float4*)&g_q[base + lane*4];
    float sc[ALa];
    #pragma unroll
    for (int j = 0; j < ALa; j++) {
        float d0 = qv.x*ak[j][lane*4+0] + qv.y*ak[j][lane*4+1]
                 + qv.z*ak[j][lane*4+2] + qv.w*ak[j][lane*4+3];
        #pragma unroll
        for (int off = 16; off >= 1; off >>= 1)
            d0 += __shfl_xor_sync(0xffffffffu, d0, off);
        sc[j] = d0 * rscale;
    }
    float mx = sc[0];
    #pragma unroll
    for (int j = 1; j < ALa; j++) mx = fmaxf(mx, sc[j]);
    float sum = 0.f;
    #pragma unroll
    for (int j = 0; j < ALa; j++) { sc[j] = __expf(sc[j] - mx); sum += sc[j]; }
    float inv = 1.f / sum;
    float gg = tanhf(gate[h]);

    float acc[4] = {0.f, 0.f, 0.f, 0.f};
    #pragma unroll
    for (int j = 0; j < ALa; j++) {
        float p = sc[j] * inv;
        acc[0] += p * av[j][lane*4+0];
        acc[1] += p * av[j][lane*4+1];
        acc[2] += p * av[j][lane*4+2];
        acc[3] += p * av[j][lane*4+3];
    }
    float4 ov = *(float4*)&g_attn[base + lane*4];
    ov.x += gg*acc[0]; ov.y += gg*acc[1]; ov.z += gg*acc[2]; ov.w += gg*acc[3];
    *(float4*)&g_attn[base + lane*4] = ov;

    // split final attn to fp16 hi/lo for the output projection
    __half h0 = __float2half_rn(ov.x), h1 = __float2half_rn(ov.y);
    __half h2 = __float2half_rn(ov.z), h3 = __float2half_rn(ov.w);
    *(__half2*)(g_ah + base + lane*4)     = __halves2half2(h0, h1);
    *(__half2*)(g_ah + base + lane*4 + 2) = __halves2half2(h2, h3);
    *(__half2*)(g_al + base + lane*4)     = __halves2half2(__float2half_rn(ov.x - __half2float(h0)),
                                                           __float2half_rn(ov.y - __half2float(h1)));
    *(__half2*)(g_al + base + lane*4 + 2) = __halves2half2(__float2half_rn(ov.z - __half2float(h2)),
                                                           __float2half_rn(ov.w - __half2float(h3)));
}

// ---------------- host ----------------
extern "C" void kernel_launch(void* const* d_in, const int* in_sizes, int n_in,
                              void* d_out, int out_size)
{
    (void)in_sizes; (void)n_in; (void)out_size;
    const float* x       = (const float*)d_in[0];
    const float* cosT    = (const float*)d_in[2];
    const float* sinT    = (const float*)d_in[3];
    const float* wq      = (const float*)d_in[4];
    const float* wk      = (const float*)d_in[5];
    const float* wv      = (const float*)d_in[6];
    const float* wo      = (const float*)d_in[7];
    const float* gate    = (const float*)d_in[8];
    const float* adapter = (const float*)d_in[9];
    float* out = (float*)d_out;

    float *qp, *kp, *vp, *attnp;
    __half *ahp, *alp, *wqh, *wql, *wkh, *wkl, *wvh, *wvl, *woh, *wol;
    __half *qhp, *qlp, *khp, *klp, *vhp, *vlp;
    cudaGetSymbolAddress((void**)&qp,    g_q);
    cudaGetSymbolAddress((void**)&kp,    g_k);
    cudaGetSymbolAddress((void**)&vp,    g_v);
    cudaGetSymbolAddress((void**)&attnp, g_attn);
    cudaGetSymbolAddress((void**)&ahp,  g_ah);  cudaGetSymbolAddress((void**)&alp,  g_al);
    cudaGetSymbolAddress((void**)&wqh,  g_wqh); cudaGetSymbolAddress((void**)&wql,  g_wql);
    cudaGetSymbolAddress((void**)&wkh,  g_wkh); cudaGetSymbolAddress((void**)&wkl,  g_wkl);
    cudaGetSymbolAddress((void**)&wvh,  g_wvh); cudaGetSymbolAddress((void**)&wvl,  g_wvl);
    cudaGetSymbolAddress((void**)&woh,  g_woh); cudaGetSymbolAddress((void**)&wol,  g_wol);
    cudaGetSymbolAddress((void**)&qhp,  g_qh);  cudaGetSymbolAddress((void**)&qlp,  g_ql);
    cudaGetSymbolAddress((void**)&khp,  g_kh);  cudaGetSymbolAddress((void**)&klp,  g_kl);
    cudaGetSymbolAddress((void**)&vhp,  g_vh);  cudaGetSymbolAddress((void**)&vlp,  g_vl);

    cudaFuncSetAttribute(gemm_h3w, cudaFuncAttributeMaxDynamicSharedMemorySize, GEMM_SMEM);
    cudaFuncSetAttribute(flash_h, cudaFuncAttributeMaxDynamicSharedMemorySize, FLASH_SMEM);

    const int nXW = Mtok*Dd;
    const int cgrid = nXW/4/256;

    conv_split<<<cgrid, 256>>>(x,  ahp, alp, nXW);
    conv_split<<<cgrid, 256>>>(wq, wqh, wql, Dd*Dd);
    conv_split<<<cgrid, 256>>>(wk, wkh, wkl, Dd*Dd);
    conv_split<<<cgrid, 256>>>(wv, wvh, wvl, Dd*Dd);
    conv_split<<<cgrid, 256>>>(wo, woh, wol, Dd*Dd);

    dim3 gbig(Dd/GBN, Mtok/GBM);
    gemm_h3w<<<gbig, 256, GEMM_SMEM>>>(ahp, alp, wqh, wql, qp, Mtok, Dd, Dd);
    gemm_h3w<<<gbig, 256, GEMM_SMEM>>>(ahp, alp, wkh, wkl, kp, Mtok, Dd, Dd);
    gemm_h3w<<<gbig, 256, GEMM_SMEM>>>(ahp, alp, wvh, wvl, vp, Mtok, Dd, Dd);

    gemm_skinny<<<dim3(Dd/128, KSPL, 2), 128>>>(adapter, wk, wv);
    skinny_reduce<<<(20*4096 + 255)/256, 256>>>();

    int npairs = Bb*Ss*Hh*HALFh;
    rope_split<<<npairs/256, 256>>>(qp, qhp, qlp, cosT, sinT);
    rope_split<<<npairs/256, 256>>>(kp, khp, klp, cosT, sinT);
    conv_split<<<cgrid, 256>>>(vp, vhp, vlp, nXW);

    flash_h<<<dim3(Ss/FQ, Bb*Hh), 256, FLASH_SMEM>>>();
    adapter_kernel<<<dim3(Ss/4, Bb*Hh), 128>>>(gate);

    gemm_h3w<<<gbig, 256, GEMM_SMEM>>>(ahp, alp, woh, wol, out, Mtok, Dd, Dd);
}

// round 11
// speedup vs baseline: 1.0399x; 1.0399x over previous
#include <cuda_runtime.h>
#include <cuda_fp16.h>
#include <math.h>
#include <stdint.h>

#define Bb 2
#define Ss 2048
#define Dd 4096
#define Hh 32
#define HDh 128
#define HALFh 64
#define ALa 10
#define Mtok (Bb*Ss)

// ---- fused fp16x3 GEMM config (R9 proven) ----
#define BM 128
#define BN 128
#define BKh 64                       // halves per K-chunk = 128B row
#define HROWB 144                    // smem row bytes (128 data + 16 pad)
#define OPB (128*HROWB)              // one operand = 18432 B
#define STAGE_B (4*OPB)              // Ah, Al, Bh, Bl = 73728 B
#define NSTAGE 3
#define GEMM_SMEM (NSTAGE*STAGE_B)   // 221184 B

// ---- flash config (double-buffered KV) ----
#define FQ 128
#define FKV 64
#define FROWB 272                    // 128 halves + 8 pad = 272 B
#define QHOFF 0
#define QLOFF (128*FROWB)
#define KV0 (QLOFF + 128*FROWB)      // KV stages base
#define KVSTG (4*64*FROWB)           // one stage: KH,KL,VH,VL = 69632 B
#define KLO (64*FROWB)
#define VHO (2*64*FROWB)
#define VLO (3*64*FROWB)
#define FLASH_SMEM (KV0 + 2*KVSTG)   // 208896 B

#define KSPL 8

// ---------------- scratch (static device globals) ----------------
__device__ float g_q[Mtok*Dd];
__device__ float g_k[Mtok*Dd];
__device__ float g_v[Mtok*Dd];
__device__ float g_attn[Mtok*Dd];
__device__ float g_ak[Bb*ALa*Dd];
__device__ float g_av[Bb*ALa*Dd];
__device__ float g_pk[KSPL*Bb*ALa*Dd];
__device__ float g_pv[KSPL*Bb*ALa*Dd];

__device__ __half g_ah[Mtok*Dd];   // x split; later holds attn split
__device__ __half g_al[Mtok*Dd];
__device__ __half g_wqh[Dd*Dd], g_wql[Dd*Dd];
__device__ __half g_wkh[Dd*Dd], g_wkl[Dd*Dd];
__device__ __half g_wvh[Dd*Dd], g_wvl[Dd*Dd];
__device__ __half g_woh[Dd*Dd], g_wol[Dd*Dd];
__device__ __half g_qh[Mtok*Dd], g_ql[Mtok*Dd];
__device__ __half g_kh[Mtok*Dd], g_kl[Mtok*Dd];
__device__ __half g_vh[Mtok*Dd], g_vl[Mtok*Dd];

// ---------------- helpers ----------------
__device__ __forceinline__ uint32_t s2u(const void* p){
    uint32_t r;
    asm("{ .reg .u64 t; cvta.to.shared.u64 t, %1; cvt.u32.u64 %0, t; }" : "=r"(r) : "l"(p));
    return r;
}

__device__ __forceinline__ void ldsm_x4(uint32_t* r, uint32_t addr){
    asm volatile("ldmatrix.sync.aligned.m8n8.x4.shared.b16 {%0,%1,%2,%3}, [%4];"
                 : "=r"(r[0]), "=r"(r[1]), "=r"(r[2]), "=r"(r[3]) : "r"(addr));
}
__device__ __forceinline__ void ldsm_x4t(uint32_t* r, uint32_t addr){
    asm volatile("ldmatrix.sync.aligned.m8n8.x4.trans.shared.b16 {%0,%1,%2,%3}, [%4];"
                 : "=r"(r[0]), "=r"(r[1]), "=r"(r[2]), "=r"(r[3]) : "r"(addr));
}

__device__ __forceinline__ void mma_h(float* d, const uint32_t* a, uint32_t b0, uint32_t b1){
    asm volatile(
        "mma.sync.aligned.m16n8k16.row.col.f32.f16.f16.f32 "
        "{%0,%1,%2,%3}, {%4,%5,%6,%7}, {%8,%9}, {%0,%1,%2,%3};"
        : "+f"(d[0]), "+f"(d[1]), "+f"(d[2]), "+f"(d[3])
        : "r"(a[0]), "r"(a[1]), "r"(a[2]), "r"(a[3]), "r"(b0), "r"(b1));
}

__device__ __forceinline__ uint32_t packh2(float lo, float hi){
    uint32_t r;
    asm("cvt.rn.f16x2.f32 %0, %1, %2;" : "=r"(r) : "f"(hi), "f"(lo));
    return r;
}

__device__ __forceinline__ void split_pack(float f0, float f1, uint32_t& hi, uint32_t& lo){
    __half h0 = __float2half_rn(f0), h1 = __float2half_rn(f1);
    __half2 hh = __halves2half2(h0, h1);
    hi = *reinterpret_cast<uint32_t*>(&hh);
    lo = packh2(f0 - __half2float(h0), f1 - __half2float(h1));
}

// ---------------- convert: fp32 -> fp16 hi/lo ----------------
__global__ void conv_split(const float* __restrict__ s, __half* __restrict__ hi,
                           __half* __restrict__ lo, int n)
{
    int i = (blockIdx.x*256 + threadIdx.x) * 4;
    if (i >= n) return;
    float4 v = *(const float4*)(s + i);
    __half h0 = __float2half_rn(v.x), h1 = __float2half_rn(v.y);
    __half h2 = __float2half_rn(v.z), h3 = __float2half_rn(v.w);
    *(__half2*)(hi + i)     = __halves2half2(h0, h1);
    *(__half2*)(hi + i + 2) = __halves2half2(h2, h3);
    *(__half2*)(lo + i)     = __halves2half2(__float2half_rn(v.x - __half2float(h0)),
                                             __float2half_rn(v.y - __half2float(h1)));
    *(__half2*)(lo + i + 2) = __halves2half2(__float2half_rn(v.z - __half2float(h2)),
                                             __float2half_rn(v.w - __half2float(h3)));
}

// ---------------- fused fp16x3 NT GEMM: one K pass, 3 MMA terms (R9 proven) ----------------
__global__ __launch_bounds__(256) void gemm_h3f(
    const __half* __restrict__ Ah, const __half* __restrict__ Al,
    const __half* __restrict__ Bh, const __half* __restrict__ Bl,
    float* __restrict__ C, int M, int N, int K)
{
    extern __shared__ char smg[];
    const uint32_t sbase = s2u(smg);
    const int t = threadIdx.x;
    const int m0 = blockIdx.y * BM;
    const int n0 = blockIdx.x * BN;
    const int NCH = K / BKh;

    const int lane = t & 31;
    const int wid  = t >> 5;
    const int wm   = wid & 3;
    const int wn   = wid >> 2;

    float d[2][8][4];
    #pragma unroll
    for (int mt = 0; mt < 2; mt++)
        #pragma unroll
        for (int nt = 0; nt < 8; nt++)
            #pragma unroll
            for (int c = 0; c < 4; c++) d[mt][nt][c] = 0.f;

    const uint32_t aRow = (uint32_t)(wm*32 + (lane & 7) + ((lane >> 3) & 1)*8);
    const uint32_t aKof = (uint32_t)(((lane >> 4) & 1) << 4);
    const uint32_t bRow = (uint32_t)(wn*64 + (lane & 7) + ((lane >> 4) & 1)*8);
    const uint32_t bKof = (uint32_t)(((lane >> 3) & 1) << 4);

    const int ldr = t >> 3;
    const int ldq = t & 7;

    auto prefetch = [&](int chunk, int stage){
        const int k0 = chunk * BKh;
        const uint32_t st = sbase + (uint32_t)stage * STAGE_B;
        #pragma unroll
        for (int i = 0; i < 4; i++) {
            int row = ldr + i*32;
            int ar = m0 + row; if (ar > M-1) ar = M-1;
            size_t goa = (size_t)ar * K + k0 + ldq*8;
            size_t gob = (size_t)(n0 + row) * K + k0 + ldq*8;
            uint32_t so = (uint32_t)row * HROWB + (uint32_t)ldq * 16u;
            asm volatile("cp.async.cg.shared.global [%0], [%1], 16;" :: "r"(st + 0*OPB + so), "l"(Ah + goa));
            asm volatile("cp.async.cg.shared.global [%0], [%1], 16;" :: "r"(st + 1*OPB + so), "l"(Al + goa));
            asm volatile("cp.async.cg.shared.global [%0], [%1], 16;" :: "r"(st + 2*OPB + so), "l"(Bh + gob));
            asm volatile("cp.async.cg.shared.global [%0], [%1], 16;" :: "r"(st + 3*OPB + so), "l"(Bl + gob));
        }
        asm volatile("cp.async.commit_group;" ::: "memory");
    };

    prefetch(0, 0);
    prefetch(1, 1);
    prefetch(2, 2);

    int stage = 0;
    for (int n = 0; n < NCH; n++) {
        asm volatile("cp.async.wait_group %0;" :: "n"(NSTAGE-1) : "memory");
        __syncthreads();

        const uint32_t st = sbase + (uint32_t)stage * STAGE_B;
        const uint32_t sAh = st, sAl = st + OPB, sBh = st + 2*OPB, sBl = st + 3*OPB;

        #pragma unroll
        for (int ks = 0; ks < 4; ks++) {
            const uint32_t kb = (uint32_t)ks * 32u;
            uint32_t ah[2][4], al[2][4];
            #pragma unroll
            for (int mt = 0; mt < 2; mt++) {
                ldsm_x4(ah[mt], sAh + (aRow + mt*16u)*HROWB + aKof + kb);
                ldsm_x4(al[mt], sAl + (aRow + mt*16u)*HROWB + aKof + kb);
            }
            #pragma unroll
            for (int np = 0; np < 4; np++) {
                uint32_t bh[4], bl[4];
                ldsm_x4(bh, sBh + (bRow + np*16u)*HROWB + bKof + kb);
                ldsm_x4(bl, sBl + (bRow + np*16u)*HROWB + bKof + kb);
                #pragma unroll
                for (int mt = 0; mt < 2; mt++) {
                    mma_h(d[mt][2*np],   ah[mt], bh[0], bh[1]);
                    mma_h(d[mt][2*np],   ah[mt], bl[0], bl[1]);
                    mma_h(d[mt][2*np],   al[mt], bh[0], bh[1]);
                    mma_h(d[mt][2*np+1], ah[mt], bh[2], bh[3]);
                    mma_h(d[mt][2*np+1], ah[mt], bl[2], bl[3]);
                    mma_h(d[mt][2*np+1], al[mt], bh[2], bh[3]);
                }
            }
        }
        __syncthreads();

        int pn = n + NSTAGE; if (pn >= NCH) pn = 0;
        prefetch(pn, stage);
        stage++; if (stage == NSTAGE) stage = 0;
    }

    const int g  = lane >> 2;
    const int tq = lane & 3;
    #pragma unroll
    for (int mt = 0; mt < 2; mt++) {
        int row = m0 + wm*32 + mt*16 + g;
        #pragma unroll
        for (int nt = 0; nt < 8; nt++) {
            int col = n0 + wn*64 + nt*8 + 2*tq;
            if (row < M)
                *(float2*)&C[(size_t)row * N + col] = make_float2(d[mt][nt][0], d[mt][nt][1]);
            if (row + 8 < M)
                *(float2*)&C[(size_t)(row+8) * N + col] = make_float2(d[mt][nt][2], d[mt][nt][3]);
        }
    }
}

// ---------------- skinny adapter GEMM (M=20, fp32, split-K) ----------------
__global__ __launch_bounds__(128) void gemm_skinny(
    const float* __restrict__ Aad, const float* __restrict__ wk, const float* __restrict__ wv)
{
    __shared__ float As[20][33];
    __shared__ float Bs[128][33];
    const int t = threadIdx.x;
    const int n0 = blockIdx.x * 128;
    const int kz = blockIdx.y;
    const float* W = blockIdx.z ? wv : wk;
    float* P = (blockIdx.z ? g_pv : g_pk) + (size_t)kz * (20*4096);

    float acc[20];
    #pragma unroll
    for (int m = 0; m < 20; m++) acc[m] = 0.f;

    for (int k0 = kz*512; k0 < kz*512 + 512; k0 += 32) {
        for (int i = t; i < 640; i += 128) {
            int r = i >> 5, c = i & 31;
            As[r][c] = Aad[(size_t)r*4096 + k0 + c];
        }
        #pragma unroll
        for (int i = 0; i < 8; i++) {
            int idx = t + i*128;
            int r = idx >> 3, cq = idx & 7;
            float4 v = *(const float4*)&W[(size_t)(n0 + r)*4096 + k0 + cq*4];
            Bs[r][cq*4+0] = v.x; Bs[r][cq*4+1] = v.y;
            Bs[r][cq*4+2] = v.z; Bs[r][cq*4+3] = v.w;
        }
        __syncthreads();
        #pragma unroll
        for (int k = 0; k < 32; k++) {
            float bv = Bs[t][k];
            #pragma unroll
            for (int m = 0; m < 20; m++) acc[m] += As[m][k] * bv;
        }
        __syncthreads();
    }
    #pragma unroll
    for (int m = 0; m < 20; m++) P[(size_t)m*4096 + n0 + t] = acc[m];
}

__global__ void skinny_reduce()
{
    int i = blockIdx.x*256 + threadIdx.x;
    if (i >= 20*4096) return;
    float sk = 0.f, sv = 0.f;
    #pragma unroll
    for (int z = 0; z < KSPL; z++) {
        sk += g_pk[(size_t)z*(20*4096) + i];
        sv += g_pv[(size_t)z*(20*4096) + i];
    }
    g_ak[i] = sk;
    g_av[i] = sv;
}

// ---------------- RoPE (fp32 in place) + split to fp16 hi/lo ----------------
__global__ void rope_split(float* __restrict__ T, __half* __restrict__ Th, __half* __restrict__ Tl,
                           const float* __restrict__ cosT, const float* __restrict__ sinT)
{
    int idx = blockIdx.x * blockDim.x + threadIdx.x;
    if (idx >= Bb*Ss*Hh*HALFh) return;
    int p = idx & (HALFh - 1);
    int s = (idx >> 11) & (Ss - 1);
    float c  = cosT[s*HALFh + p];
    float sn = sinT[s*HALFh + p];
    float2 v = *(float2*)&T[2*(size_t)idx];
    float2 r;
    r.x = v.x * c - v.y * sn;
    r.y = v.x * sn + v.y * c;
    *(float2*)&T[2*(size_t)idx] = r;
    __half h0 = __float2half_rn(r.x), h1 = __float2half_rn(r.y);
    *(__half2*)(Th + 2*(size_t)idx) = __halves2half2(h0, h1);
    *(__half2*)(Tl + 2*(size_t)idx) = __halves2half2(__float2half_rn(r.x - __half2float(h0)),
                                                     __float2half_rn(r.y - __half2float(h1)));
}

// ---------------- flash attention via fp16x3 mma.sync, double-buffered KV ----------------
__global__ __launch_bounds__(256, 1) void flash_h()
{
    extern __shared__ char fsm[];
    const uint32_t sb = s2u(fsm);
    const int t = threadIdx.x, lane = t & 31, w = t >> 5;
    const int bh = blockIdx.y, b = bh >> 5, h = bh & 31;
    const int q0 = (int)(gridDim.x - 1 - blockIdx.x) * FQ;
    const size_t headbase = (size_t)b * Ss * Dd + (size_t)h * HDh;
    const int g = lane >> 2, tq = lane & 3;
    const float rscale = 0.08838834764831844f;
    const float NEGINF = __int_as_float(0xff800000);
    const int niter = (q0 + FQ) / FKV;        // >= 2 always

    auto prefetch_kv = [&](int j0, int st){
        const uint32_t kv = sb + KV0 + (uint32_t)st * KVSTG;
        const __half* kh = g_kh + headbase + (size_t)j0 * Dd;
        const __half* kl = g_kl + headbase + (size_t)j0 * Dd;
        const __half* vh = g_vh + headbase + (size_t)j0 * Dd;
        const __half* vl = g_vl + headbase + (size_t)j0 * Dd;
        #pragma unroll
        for (int i = 0; i < 4; i++) {
            int idx = t + i*256;
            int r = idx >> 4, cq = idx & 15;
            uint32_t so = (uint32_t)(r*FROWB + cq*16);
            size_t go = (size_t)r*Dd + cq*8;
            asm volatile("cp.async.cg.shared.global [%0], [%1], 16;" :: "r"(kv + so),       "l"(kh + go));
            asm volatile("cp.async.cg.shared.global [%0], [%1], 16;" :: "r"(kv + KLO + so), "l"(kl + go));
            asm volatile("cp.async.cg.shared.global [%0], [%1], 16;" :: "r"(kv + VHO + so), "l"(vh + go));
            asm volatile("cp.async.cg.shared.global [%0], [%1], 16;" :: "r"(kv + VLO + so), "l"(vl + go));
        }
        asm volatile("cp.async.commit_group;" ::: "memory");
    };

    // prologue: Q (hi/lo) + first KV tile, one group
    {
        const __half* qh = g_qh + headbase + (size_t)q0 * Dd;
        const __half* ql = g_ql + headbase + (size_t)q0 * Dd;
        #pragma unroll
        for (int i = 0; i < 8; i++) {
            int idx = t + i*256;
            int r = idx >> 4, cq = idx & 15;
            asm volatile("cp.async.cg.shared.global [%0], [%1], 16;"
                :: "r"(sb + QHOFF + (uint32_t)(r*FROWB + cq*16)), "l"(qh + (size_t)r*Dd + cq*8));
            asm volatile("cp.async.cg.shared.global [%0], [%1], 16;"
                :: "r"(sb + QLOFF + (uint32_t)(r*FROWB + cq*16)), "l"(ql + (size_t)r*Dd + cq*8));
        }
        prefetch_kv(0, 0);   // commits Q + KV0 together
    }

    const uint32_t aRow = (uint32_t)(w*16 + (lane & 7) + ((lane >> 3) & 1)*8);
    const uint32_t aKof = (uint32_t)(((lane >> 4) & 1) << 4);
    const uint32_t bRow = (uint32_t)((lane & 7) + ((lane >> 4) & 1)*8);
    const uint32_t bKof = (uint32_t)(((lane >> 3) & 1) << 4);
    const uint32_t vRow = (uint32_t)((lane & 7) + ((lane >> 3) & 1)*8);
    const uint32_t vDof = (uint32_t)(((lane >> 4) & 1) << 4);

    float o[16][4];
    #pragma unroll
    for (int nt = 0; nt < 16; nt++) { o[nt][0]=o[nt][1]=o[nt][2]=o[nt][3]=0.f; }
    float m0r = -1e30f, m1r = -1e30f, l0r = 0.f, l1r = 0.f;

    const int ig0 = q0 + w*16 + g;
    const int ig1 = ig0 + 8;

    for (int n = 0; n < niter; n++) {
        const int j0 = n * FKV;
        const int s_ = n & 1;

        asm volatile("cp.async.wait_group 0;" ::: "memory");
        __syncthreads();   // data visible to all; prior iter's reads of other stage done

        if (n + 1 < niter) prefetch_kv(j0 + FKV, 1 - s_);

        const uint32_t kv = sb + KV0 + (uint32_t)s_ * KVSTG;

        float s[8][4];
        #pragma unroll
        for (int nt = 0; nt < 8; nt++) { s[nt][0]=s[nt][1]=s[nt][2]=s[nt][3]=0.f; }
        #pragma unroll
        for (int ks = 0; ks < 8; ks++) {
            const uint32_t kb = (uint32_t)ks * 32u;
            uint32_t ah[4], al_[4];
            ldsm_x4(ah,  sb + QHOFF + aRow*FROWB + aKof + kb);
            ldsm_x4(al_, sb + QLOFF + aRow*FROWB + aKof + kb);
            #pragma unroll
            for (int np = 0; np < 4; np++) {
                uint32_t bhf[4], blf[4];
                ldsm_x4(bhf, kv + (bRow + np*16u)*FROWB + bKof + kb);
                ldsm_x4(blf, kv + KLO + (bRow + np*16u)*FROWB + bKof + kb);
                mma_h(s[2*np],   ah,  bhf[0], bhf[1]);
                mma_h(s[2*np],   ah,  blf[0], blf[1]);
                mma_h(s[2*np],   al_, bhf[0], bhf[1]);
                mma_h(s[2*np+1], ah,  bhf[2], bhf[3]);
                mma_h(s[2*np+1], ah,  blf[2], blf[3]);
                mma_h(s[2*np+1], al_, bhf[2], bhf[3]);
            }
        }

        float mx0 = -1e30f, mx1 = -1e30f;
        #pragma unroll
        for (int nt = 0; nt < 8; nt++) {
            int jg = j0 + nt*8 + 2*tq;
            s[nt][0] = (jg   > ig0) ? NEGINF : s[nt][0]*rscale;
            s[nt][1] = (jg+1 > ig0) ? NEGINF : s[nt][1]*rscale;
            s[nt][2] = (jg   > ig1) ? NEGINF : s[nt][2]*rscale;
            s[nt][3] = (jg+1 > ig1) ? NEGINF : s[nt][3]*rscale;
            mx0 = fmaxf(mx0, fmaxf(s[nt][0], s[nt][1]));
            mx1 = fmaxf(mx1, fmaxf(s[nt][2], s[nt][3]));
        }
        mx0 = fmaxf(mx0, __shfl_xor_sync(0xffffffffu, mx0, 1));
        mx0 = fmaxf(mx0, __shfl_xor_sync(0xffffffffu, mx0, 2));
        mx1 = fmaxf(mx1, __shfl_xor_sync(0xffffffffu, mx1, 1));
        mx1 = fmaxf(mx1, __shfl_xor_sync(0xffffffffu, mx1, 2));
        float mn0 = fmaxf(m0r, mx0), mn1 = fmaxf(m1r, mx1);
        float co0 = __expf(m0r - mn0), co1 = __expf(m1r - mn1);
        float sum0 = 0.f, sum1 = 0.f;
        #pragma unroll
        for (int nt = 0; nt < 8; nt++) {
            s[nt][0] = __expf(s[nt][0] - mn0);
            s[nt][1] = __expf(s[nt][1] - mn0);
            s[nt][2] = __expf(s[nt][2] - mn1);
            s[nt][3] = __expf(s[nt][3] - mn1);
            sum0 += s[nt][0] + s[nt][1];
            sum1 += s[nt][2] + s[nt][3];
        }
        sum0 += __shfl_xor_sync(0xffffffffu, sum0, 1);
        sum0 += __shfl_xor_sync(0xffffffffu, sum0, 2);
        sum1 += __shfl_xor_sync(0xffffffffu, sum1, 1);
        sum1 += __shfl_xor_sync(0xffffffffu, sum1, 2);
        l0r = l0r * co0 + sum0;  m0r = mn0;
        l1r = l1r * co1 + sum1;  m1r = mn1;

        #pragma unroll
        for (int nt = 0; nt < 16; nt++) {
            o[nt][0] *= co0; o[nt][1] *= co0;
            o[nt][2] *= co1; o[nt][3] *= co1;
        }

        #pragma unroll
        for (int ks = 0; ks < 4; ks++) {
            uint32_t ph[4], pl[4];
            split_pack(s[2*ks][0],   s[2*ks][1],   ph[0], pl[0]);
            split_pack(s[2*ks][2],   s[2*ks][3],   ph[1], pl[1]);
            split_pack(s[2*ks+1][0], s[2*ks+1][1], ph[2], pl[2]);
            split_pack(s[2*ks+1][2], s[2*ks+1][3], ph[3], pl[3]);
            const uint32_t krow = (uint32_t)(ks*16) + vRow;
            #pragma unroll
            for (int np = 0; np < 8; np++) {
                uint32_t vhf[4], vlf[4];
                ldsm_x4t(vhf, kv + VHO + krow*FROWB + (uint32_t)(np*32) + vDof);
                ldsm_x4t(vlf, kv + VLO + krow*FROWB + (uint32_t)(np*32) + vDof);
                mma_h(o[2*np],   ph, vhf[0], vhf[1]);
                mma_h(o[2*np],   ph, vlf[0], vlf[1]);
                mma_h(o[2*np],   pl, vhf[0], vhf[1]);
                mma_h(o[2*np+1], ph, vhf[2], vhf[3]);
                mma_h(o[2*np+1], ph, vlf[2], vlf[3]);
                mma_h(o[2*np+1], pl, vhf[2], vhf[3]);
            }
        }
        __syncthreads();   // all warps done with stage s_ before it is overwritten next+1
    }

    float inv0 = 1.f / l0r, inv1 = 1.f / l1r;
    float* Og = g_attn + headbase + (size_t)(q0 + w*16) * Dd;
    #pragma unroll
    for (int nt = 0; nt < 16; nt++) {
        *(float2*)&Og[(size_t)g*Dd     + nt*8 + 2*tq] = make_float2(o[nt][0]*inv0, o[nt][1]*inv0);
        *(float2*)&Og[(size_t)(g+8)*Dd + nt*8 + 2*tq] = make_float2(o[nt][2]*inv1, o[nt][3]*inv1);
    }
}

// ---------------- adapter attention (+ writes fp16 split of final attn) ----------------
__global__ __launch_bounds__(128) void adapter_kernel(const float* __restrict__ gate)
{
    __shared__ __align__(16) float ak[ALa][HDh];
    __shared__ __align__(16) float av[ALa][HDh];
    const int t = threadIdx.x;
    const int bh = blockIdx.y;
    const int b = bh >> 5, h = bh & 31;
    const int s0 = blockIdx.x * 4;

    #pragma unroll
    for (int r = 0; r < ALa; r++) {
        int idx = t + r*128;
        int j = idx >> 7, d = idx & 127;
        ak[j][d] = g_ak[(size_t)(b*ALa + j) * Dd + h*HDh + d];
        av[j][d] = g_av[(size_t)(b*ALa + j) * Dd + h*HDh + d];
    }
    __syncthreads();

    const int w = t >> 5, lane = t & 31;
    const int s = s0 + w;
    const size_t base = (size_t)(b*Ss + s) * Dd + h*HDh;
    const float rscale = 0.08838834764831844f;

    float4 qv = *(const float4*)&g_q[base + lane*4];
    float sc[ALa];
    #pragma unroll
    for (int j = 0; j < ALa; j++) {
        float d0 = qv.x*ak[j][lane*4+0] + qv.y*ak[j][lane*4+1]
                 + qv.z*ak[j][lane*4+2] + qv.w*ak[j][lane*4+3];
        #pragma unroll
        for (int off = 16; off >= 1; off >>= 1)
            d0 += __shfl_xor_sync(0xffffffffu, d0, off);
        sc[j] = d0 * rscale;
    }
    float mx = sc[0];
    #pragma unroll
    for (int j = 1; j < ALa; j++) mx = fmaxf(mx, sc[j]);
    float sum = 0.f;
    #pragma unroll
    for (int j = 0; j < ALa; j++) { sc[j] = __expf(sc[j] - mx); sum += sc[j]; }
    float inv = 1.f / sum;
    float gg = tanhf(gate[h]);

    float acc[4] = {0.f, 0.f, 0.f, 0.f};
    #pragma unroll
    for (int j = 0; j < ALa; j++) {
        float p = sc[j] * inv;
        acc[0] += p * av[j][lane*4+0];
        acc[1] += p * av[j][lane*4+1];
        acc[2] += p * av[j][lane*4+2];
        acc[3] += p * av[j][lane*4+3];
    }
    float4 ov = *(float4*)&g_attn[base + lane*4];
    ov.x += gg*acc[0]; ov.y += gg*acc[1]; ov.z += gg*acc[2]; ov.w += gg*acc[3];
    *(float4*)&g_attn[base + lane*4] = ov;

    __half h0 = __float2half_rn(ov.x), h1 = __float2half_rn(ov.y);
    __half h2 = __float2half_rn(ov.z), h3 = __float2half_rn(ov.w);
    *(__half2*)(g_ah + base + lane*4)     = __halves2half2(h0, h1);
    *(__half2*)(g_ah + base + lane*4 + 2) = __halves2half2(h2, h3);
    *(__half2*)(g_al + base + lane*4)     = __halves2half2(__float2half_rn(ov.x - __half2float(h0)),
                                                           __float2half_rn(ov.y - __half2float(h1)));
    *(__half2*)(g_al + base + lane*4 + 2) = __halves2half2(__float2half_rn(ov.z - __half2float(h2)),
                                                           __float2half_rn(ov.w - __half2float(h3)));
}

// ---------------- host ----------------
extern "C" void kernel_launch(void* const* d_in, const int* in_sizes, int n_in,
                              void* d_out, int out_size)
{
    (void)in_sizes; (void)n_in; (void)out_size;
    const float* x       = (const float*)d_in[0];
    const float* cosT    = (const float*)d_in[2];
    const float* sinT    = (const float*)d_in[3];
    const float* wq      = (const float*)d_in[4];
    const float* wk      = (const float*)d_in[5];
    const float* wv      = (const float*)d_in[6];
    const float* wo      = (const float*)d_in[7];
    const float* gate    = (const float*)d_in[8];
    const float* adapter = (const float*)d_in[9];
    float* out = (float*)d_out;

    float *qp, *kp, *vp, *attnp;
    __half *ahp, *alp, *wqh, *wql, *wkh, *wkl, *wvh, *wvl, *woh, *wol;
    __half *qhp, *qlp, *khp, *klp, *vhp, *vlp;
    cudaGetSymbolAddress((void**)&qp,    g_q);
    cudaGetSymbolAddress((void**)&kp,    g_k);
    cudaGetSymbolAddress((void**)&vp,    g_v);
    cudaGetSymbolAddress((void**)&attnp, g_attn);
    cudaGetSymbolAddress((void**)&ahp,  g_ah);  cudaGetSymbolAddress((void**)&alp,  g_al);
    cudaGetSymbolAddress((void**)&wqh,  g_wqh); cudaGetSymbolAddress((void**)&wql,  g_wql);
    cudaGetSymbolAddress((void**)&wkh,  g_wkh); cudaGetSymbolAddress((void**)&wkl,  g_wkl);
    cudaGetSymbolAddress((void**)&wvh,  g_wvh); cudaGetSymbolAddress((void**)&wvl,  g_wvl);
    cudaGetSymbolAddress((void**)&woh,  g_woh); cudaGetSymbolAddress((void**)&wol,  g_wol);
    cudaGetSymbolAddress((void**)&qhp,  g_qh);  cudaGetSymbolAddress((void**)&qlp,  g_ql);
    cudaGetSymbolAddress((void**)&khp,  g_kh);  cudaGetSymbolAddress((void**)&klp,  g_kl);
    cudaGetSymbolAddress((void**)&vhp,  g_vh);  cudaGetSymbolAddress((void**)&vlp,  g_vl);

    cudaFuncSetAttribute(gemm_h3f, cudaFuncAttributeMaxDynamicSharedMemorySize, GEMM_SMEM);
    cudaFuncSetAttribute(flash_h, cudaFuncAttributeMaxDynamicSharedMemorySize, FLASH_SMEM);

    const int nXW = Mtok*Dd;
    const int cgrid = nXW/4/256;

    conv_split<<<cgrid, 256>>>(x,  ahp, alp, nXW);
    conv_split<<<cgrid, 256>>>(wq, wqh, wql, Dd*Dd);
    conv_split<<<cgrid, 256>>>(wk, wkh, wkl, Dd*Dd);
    conv_split<<<cgrid, 256>>>(wv, wvh, wvl, Dd*Dd);
    conv_split<<<cgrid, 256>>>(wo, woh, wol, Dd*Dd);

    dim3 gbig(Dd/BN, Mtok/BM);
    gemm_h3f<<<gbig, 256, GEMM_SMEM>>>(ahp, alp, wqh, wql, qp, Mtok, Dd, Dd);
    gemm_h3f<<<gbig, 256, GEMM_SMEM>>>(ahp, alp, wkh, wkl, kp, Mtok, Dd, Dd);
    gemm_h3f<<<gbig, 256, GEMM_SMEM>>>(ahp, alp, wvh, wvl, vp, Mtok, Dd, Dd);

    gemm_skinny<<<dim3(Dd/128, KSPL, 2), 128>>>(adapter, wk, wv);
    skinny_reduce<<<(20*4096 + 255)/256, 256>>>();

    int npairs = Bb*Ss*Hh*HALFh;
    rope_split<<<npairs/256, 256>>>(qp, qhp, qlp, cosT, sinT);
    rope_split<<<npairs/256, 256>>>(kp, khp, klp, cosT, sinT);
    conv_split<<<cgrid, 256>>>(vp, vhp, vlp, nXW);

    flash_h<<<dim3(Ss/FQ, Bb*Hh), 256, FLASH_SMEM>>>();
    adapter_kernel<<<dim3(Ss/4, Bb*Hh), 128>>>(gate);

    gemm_h3f<<<gbig, 256, GEMM_SMEM>>>(ahp, alp, woh, wol, out, Mtok, Dd, Dd);
}

// round 12
// speedup vs baseline: 1.3039x; 1.2538x over previous
#include <cuda_runtime.h>
#include <cuda_fp16.h>
#include <math.h>
#include <stdint.h>

#define Bb 2
#define Ss 2048
#define Dd 4096
#define Hh 32
#define HDh 128
#define HALFh 64
#define ALa 10
#define Mtok (Bb*Ss)

// ---- fp16 GEMM common ----
#define BM 128
#define BN 128
#define BKh 64                       // halves per K-chunk = 128B row
#define HROWB 144                    // smem row bytes (128 data + 16 pad)
#define OPB (128*HROWB)              // one operand = 18432 B

// 3-term (out-projection): Ah, Al, Bh, Bl; 3 stages
#define STAGE3_B (4*OPB)
#define NST3 3
#define GEMM3_SMEM (NST3*STAGE3_B)   // 221184 B

// 2-term (QKV): Ah, Al, Bh; 4 stages
#define STAGE2_B (3*OPB)
#define NST2 4
#define GEMM2_SMEM (NST2*STAGE2_B)   // 221184 B

// ---- flash config (double-buffered KV: KH,KL,VH) ----
#define FQ 128
#define FKV 64
#define FROWB 272                    // 128 halves + 8 pad
#define QHOFF 0
#define QLOFF (128*FROWB)
#define KV0 (QLOFF + 128*FROWB)
#define KVSTG (3*64*FROWB)           // 52224 B
#define KLO (64*FROWB)
#define VHO (2*64*FROWB)
#define FLASH_SMEM (KV0 + 2*KVSTG)   // 174080 B

#define KSPL 8

// ---------------- scratch (static device globals) ----------------
__device__ float g_q[Mtok*Dd];
__device__ float g_k[Mtok*Dd];
__device__ float g_v[Mtok*Dd];
__device__ float g_attn[Mtok*Dd];
__device__ float g_ak[Bb*ALa*Dd];
__device__ float g_av[Bb*ALa*Dd];
__device__ float g_pk[KSPL*Bb*ALa*Dd];
__device__ float g_pv[KSPL*Bb*ALa*Dd];

__device__ __half g_ah[Mtok*Dd];   // x split; later holds attn split
__device__ __half g_al[Mtok*Dd];
__device__ __half g_wqh[Dd*Dd];
__device__ __half g_wkh[Dd*Dd];
__device__ __half g_wvh[Dd*Dd];
__device__ __half g_woh[Dd*Dd], g_wol[Dd*Dd];
__device__ __half g_qh[Mtok*Dd], g_ql[Mtok*Dd];
__device__ __half g_kh[Mtok*Dd], g_kl[Mtok*Dd];
__device__ __half g_vh[Mtok*Dd];

// ---------------- helpers ----------------
__device__ __forceinline__ uint32_t s2u(const void* p){
    uint32_t r;
    asm("{ .reg .u64 t; cvta.to.shared.u64 t, %1; cvt.u32.u64 %0, t; }" : "=r"(r) : "l"(p));
    return r;
}

__device__ __forceinline__ void ldsm_x4(uint32_t* r, uint32_t addr){
    asm volatile("ldmatrix.sync.aligned.m8n8.x4.shared.b16 {%0,%1,%2,%3}, [%4];"
                 : "=r"(r[0]), "=r"(r[1]), "=r"(r[2]), "=r"(r[3]) : "r"(addr));
}
__device__ __forceinline__ void ldsm_x4t(uint32_t* r, uint32_t addr){
    asm volatile("ldmatrix.sync.aligned.m8n8.x4.trans.shared.b16 {%0,%1,%2,%3}, [%4];"
                 : "=r"(r[0]), "=r"(r[1]), "=r"(r[2]), "=r"(r[3]) : "r"(addr));
}

__device__ __forceinline__ void mma_h(float* d, const uint32_t* a, uint32_t b0, uint32_t b1){
    asm volatile(
        "mma.sync.aligned.m16n8k16.row.col.f32.f16.f16.f32 "
        "{%0,%1,%2,%3}, {%4,%5,%6,%7}, {%8,%9}, {%0,%1,%2,%3};"
        : "+f"(d[0]), "+f"(d[1]), "+f"(d[2]), "+f"(d[3])
        : "r"(a[0]), "r"(a[1]), "r"(a[2]), "r"(a[3]), "r"(b0), "r"(b1));
}

__device__ __forceinline__ uint32_t packh2(float lo, float hi){
    uint32_t r;
    asm("cvt.rn.f16x2.f32 %0, %1, %2;" : "=r"(r) : "f"(hi), "f"(lo));
    return r;
}

__device__ __forceinline__ void split_pack(float f0, float f1, uint32_t& hi, uint32_t& lo){
    __half h0 = __float2half_rn(f0), h1 = __float2half_rn(f1);
    __half2 hh = __halves2half2(h0, h1);
    hi = *reinterpret_cast<uint32_t*>(&hh);
    lo = packh2(f0 - __half2float(h0), f1 - __half2float(h1));
}

// ---------------- conversions ----------------
__global__ void conv_split(const float* __restrict__ s, __half* __restrict__ hi,
                           __half* __restrict__ lo, int n)
{
    int i = (blockIdx.x*256 + threadIdx.x) * 4;
    if (i >= n) return;
    float4 v = *(const float4*)(s + i);
    __half h0 = __float2half_rn(v.x), h1 = __float2half_rn(v.y);
    __half h2 = __float2half_rn(v.z), h3 = __float2half_rn(v.w);
    *(__half2*)(hi + i)     = __halves2half2(h0, h1);
    *(__half2*)(hi + i + 2) = __halves2half2(h2, h3);
    *(__half2*)(lo + i)     = __halves2half2(__float2half_rn(v.x - __half2float(h0)),
                                             __float2half_rn(v.y - __half2float(h1)));
    *(__half2*)(lo + i + 2) = __halves2half2(__float2half_rn(v.z - __half2float(h2)),
                                             __float2half_rn(v.w - __half2float(h3)));
}

__global__ void conv_hi(const float* __restrict__ s, __half* __restrict__ hi, int n)
{
    int i = (blockIdx.x*256 + threadIdx.x) * 4;
    if (i >= n) return;
    float4 v = *(const float4*)(s + i);
    *(__half2*)(hi + i)     = __halves2half2(__float2half_rn(v.x), __float2half_rn(v.y));
    *(__half2*)(hi + i + 2) = __halves2half2(__float2half_rn(v.z), __float2half_rn(v.w));
}

// ---------------- 2-term fp16 NT GEMM (QKV): C = (Ah+Al) @ Bh^T ----------------
__global__ __launch_bounds__(256) void gemm_h2f(
    const __half* __restrict__ Ah, const __half* __restrict__ Al,
    const __half* __restrict__ Bh,
    float* __restrict__ C, int M, int N, int K)
{
    extern __shared__ char smg[];
    const uint32_t sbase = s2u(smg);
    const int t = threadIdx.x;
    const int m0 = blockIdx.y * BM;
    const int n0 = blockIdx.x * BN;
    const int NCH = K / BKh;

    const int lane = t & 31;
    const int wid  = t >> 5;
    const int wm   = wid & 3;
    const int wn   = wid >> 2;

    float d[2][8][4];
    #pragma unroll
    for (int mt = 0; mt < 2; mt++)
        #pragma unroll
        for (int nt = 0; nt < 8; nt++)
            #pragma unroll
            for (int c = 0; c < 4; c++) d[mt][nt][c] = 0.f;

    const uint32_t aRow = (uint32_t)(wm*32 + (lane & 7) + ((lane >> 3) & 1)*8);
    const uint32_t aKof = (uint32_t)(((lane >> 4) & 1) << 4);
    const uint32_t bRow = (uint32_t)(wn*64 + (lane & 7) + ((lane >> 4) & 1)*8);
    const uint32_t bKof = (uint32_t)(((lane >> 3) & 1) << 4);

    const int ldr = t >> 3;
    const int ldq = t & 7;

    auto prefetch = [&](int chunk, int stage){
        const int k0 = chunk * BKh;
        const uint32_t st = sbase + (uint32_t)stage * STAGE2_B;
        #pragma unroll
        for (int i = 0; i < 4; i++) {
            int row = ldr + i*32;
            int ar = m0 + row; if (ar > M-1) ar = M-1;
            size_t goa = (size_t)ar * K + k0 + ldq*8;
            size_t gob = (size_t)(n0 + row) * K + k0 + ldq*8;
            uint32_t so = (uint32_t)row * HROWB + (uint32_t)ldq * 16u;
            asm volatile("cp.async.cg.shared.global [%0], [%1], 16;" :: "r"(st + 0*OPB + so), "l"(Ah + goa));
            asm volatile("cp.async.cg.shared.global [%0], [%1], 16;" :: "r"(st + 1*OPB + so), "l"(Al + goa));
            asm volatile("cp.async.cg.shared.global [%0], [%1], 16;" :: "r"(st + 2*OPB + so), "l"(Bh + gob));
        }
        asm volatile("cp.async.commit_group;" ::: "memory");
    };

    #pragma unroll
    for (int p = 0; p < NST2; p++) prefetch(p, p);

    int stage = 0;
    for (int n = 0; n < NCH; n++) {
        asm volatile("cp.async.wait_group %0;" :: "n"(NST2-1) : "memory");
        __syncthreads();

        const uint32_t st = sbase + (uint32_t)stage * STAGE2_B;
        const uint32_t sAh = st, sAl = st + OPB, sBh = st + 2*OPB;

        #pragma unroll
        for (int ks = 0; ks < 4; ks++) {
            const uint32_t kb = (uint32_t)ks * 32u;
            uint32_t ah[2][4], al[2][4];
            #pragma unroll
            for (int mt = 0; mt < 2; mt++) {
                ldsm_x4(ah[mt], sAh + (aRow + mt*16u)*HROWB + aKof + kb);
                ldsm_x4(al[mt], sAl + (aRow + mt*16u)*HROWB + aKof + kb);
            }
            #pragma unroll
            for (int np = 0; np < 4; np++) {
                uint32_t bh[4];
                ldsm_x4(bh, sBh + (bRow + np*16u)*HROWB + bKof + kb);
                #pragma unroll
                for (int mt = 0; mt < 2; mt++) {
                    mma_h(d[mt][2*np],   ah[mt], bh[0], bh[1]);
                    mma_h(d[mt][2*np],   al[mt], bh[0], bh[1]);
                    mma_h(d[mt][2*np+1], ah[mt], bh[2], bh[3]);
                    mma_h(d[mt][2*np+1], al[mt], bh[2], bh[3]);
                }
            }
        }
        __syncthreads();

        int pn = n + NST2; if (pn >= NCH) pn = 0;
        prefetch(pn, stage);
        stage++; if (stage == NST2) stage = 0;
    }

    const int g  = lane >> 2;
    const int tq = lane & 3;
    #pragma unroll
    for (int mt = 0; mt < 2; mt++) {
        int row = m0 + wm*32 + mt*16 + g;
        #pragma unroll
        for (int nt = 0; nt < 8; nt++) {
            int col = n0 + wn*64 + nt*8 + 2*tq;
            if (row < M)
                *(float2*)&C[(size_t)row * N + col] = make_float2(d[mt][nt][0], d[mt][nt][1]);
            if (row + 8 < M)
                *(float2*)&C[(size_t)(row+8) * N + col] = make_float2(d[mt][nt][2], d[mt][nt][3]);
        }
    }
}

// ---------------- 3-term fp16 NT GEMM (out-projection, R9 proven) ----------------
__global__ __launch_bounds__(256) void gemm_h3f(
    const __half* __restrict__ Ah, const __half* __restrict__ Al,
    const __half* __restrict__ Bh, const __half* __restrict__ Bl,
    float* __restrict__ C, int M, int N, int K)
{
    extern __shared__ char smg[];
    const uint32_t sbase = s2u(smg);
    const int t = threadIdx.x;
    const int m0 = blockIdx.y * BM;
    const int n0 = blockIdx.x * BN;
    const int NCH = K / BKh;

    const int lane = t & 31;
    const int wid  = t >> 5;
    const int wm   = wid & 3;
    const int wn   = wid >> 2;

    float d[2][8][4];
    #pragma unroll
    for (int mt = 0; mt < 2; mt++)
        #pragma unroll
        for (int nt = 0; nt < 8; nt++)
            #pragma unroll
            for (int c = 0; c < 4; c++) d[mt][nt][c] = 0.f;

    const uint32_t aRow = (uint32_t)(wm*32 + (lane & 7) + ((lane >> 3) & 1)*8);
    const uint32_t aKof = (uint32_t)(((lane >> 4) & 1) << 4);
    const uint32_t bRow = (uint32_t)(wn*64 + (lane & 7) + ((lane >> 4) & 1)*8);
    const uint32_t bKof = (uint32_t)(((lane >> 3) & 1) << 4);

    const int ldr = t >> 3;
    const int ldq = t & 7;

    auto prefetch = [&](int chunk, int stage){
        const int k0 = chunk * BKh;
        const uint32_t st = sbase + (uint32_t)stage * STAGE3_B;
        #pragma unroll
        for (int i = 0; i < 4; i++) {
            int row = ldr + i*32;
            int ar = m0 + row; if (ar > M-1) ar = M-1;
            size_t goa = (size_t)ar * K + k0 + ldq*8;
            size_t gob = (size_t)(n0 + row) * K + k0 + ldq*8;
            uint32_t so = (uint32_t)row * HROWB + (uint32_t)ldq * 16u;
            asm volatile("cp.async.cg.shared.global [%0], [%1], 16;" :: "r"(st + 0*OPB + so), "l"(Ah + goa));
            asm volatile("cp.async.cg.shared.global [%0], [%1], 16;" :: "r"(st + 1*OPB + so), "l"(Al + goa));
            asm volatile("cp.async.cg.shared.global [%0], [%1], 16;" :: "r"(st + 2*OPB + so), "l"(Bh + gob));
            asm volatile("cp.async.cg.shared.global [%0], [%1], 16;" :: "r"(st + 3*OPB + so), "l"(Bl + gob));
        }
        asm volatile("cp.async.commit_group;" ::: "memory");
    };

    prefetch(0, 0);
    prefetch(1, 1);
    prefetch(2, 2);

    int stage = 0;
    for (int n = 0; n < NCH; n++) {
        asm volatile("cp.async.wait_group %0;" :: "n"(NST3-1) : "memory");
        __syncthreads();

        const uint32_t st = sbase + (uint32_t)stage * STAGE3_B;
        const uint32_t sAh = st, sAl = st + OPB, sBh = st + 2*OPB, sBl = st + 3*OPB;

        #pragma unroll
        for (int ks = 0; ks < 4; ks++) {
            const uint32_t kb = (uint32_t)ks * 32u;
            uint32_t ah[2][4], al[2][4];
            #pragma unroll
            for (int mt = 0; mt < 2; mt++) {
                ldsm_x4(ah[mt], sAh + (aRow + mt*16u)*HROWB + aKof + kb);
                ldsm_x4(al[mt], sAl + (aRow + mt*16u)*HROWB + aKof + kb);
            }
            #pragma unroll
            for (int np = 0; np < 4; np++) {
                uint32_t bh[4], bl[4];
                ldsm_x4(bh, sBh + (bRow + np*16u)*HROWB + bKof + kb);
                ldsm_x4(bl, sBl + (bRow + np*16u)*HROWB + bKof + kb);
                #pragma unroll
                for (int mt = 0; mt < 2; mt++) {
                    mma_h(d[mt][2*np],   ah[mt], bh[0], bh[1]);
                    mma_h(d[mt][2*np],   ah[mt], bl[0], bl[1]);
                    mma_h(d[mt][2*np],   al[mt], bh[0], bh[1]);
                    mma_h(d[mt][2*np+1], ah[mt], bh[2], bh[3]);
                    mma_h(d[mt][2*np+1], ah[mt], bl[2], bl[3]);
                    mma_h(d[mt][2*np+1], al[mt], bh[2], bh[3]);
                }
            }
        }
        __syncthreads();

        int pn = n + NST3; if (pn >= NCH) pn = 0;
        prefetch(pn, stage);
        stage++; if (stage == NST3) stage = 0;
    }

    const int g  = lane >> 2;
    const int tq = lane & 3;
    #pragma unroll
    for (int mt = 0; mt < 2; mt++) {
        int row = m0 + wm*32 + mt*16 + g;
        #pragma unroll
        for (int nt = 0; nt < 8; nt++) {
            int col = n0 + wn*64 + nt*8 + 2*tq;
            if (row < M)
                *(float2*)&C[(size_t)row * N + col] = make_float2(d[mt][nt][0], d[mt][nt][1]);
            if (row + 8 < M)
                *(float2*)&C[(size_t)(row+8) * N + col] = make_float2(d[mt][nt][2], d[mt][nt][3]);
        }
    }
}

// ---------------- skinny adapter GEMM (M=20, fp32, split-K) ----------------
__global__ __launch_bounds__(128) void gemm_skinny(
    const float* __restrict__ Aad, const float* __restrict__ wk, const float* __restrict__ wv)
{
    __shared__ float As[20][33];
    __shared__ float Bs[128][33];
    const int t = threadIdx.x;
    const int n0 = blockIdx.x * 128;
    const int kz = blockIdx.y;
    const float* W = blockIdx.z ? wv : wk;
    float* P = (blockIdx.z ? g_pv : g_pk) + (size_t)kz * (20*4096);

    float acc[20];
    #pragma unroll
    for (int m = 0; m < 20; m++) acc[m] = 0.f;

    for (int k0 = kz*512; k0 < kz*512 + 512; k0 += 32) {
        for (int i = t; i < 640; i += 128) {
            int r = i >> 5, c = i & 31;
            As[r][c] = Aad[(size_t)r*4096 + k0 + c];
        }
        #pragma unroll
        for (int i = 0; i < 8; i++) {
            int idx = t + i*128;
            int r = idx >> 3, cq = idx & 7;
            float4 v = *(const float4*)&W[(size_t)(n0 + r)*4096 + k0 + cq*4];
            Bs[r][cq*4+0] = v.x; Bs[r][cq*4+1] = v.y;
            Bs[r][cq*4+2] = v.z; Bs[r][cq*4+3] = v.w;
        }
        __syncthreads();
        #pragma unroll
        for (int k = 0; k < 32; k++) {
            float bv = Bs[t][k];
            #pragma unroll
            for (int m = 0; m < 20; m++) acc[m] += As[m][k] * bv;
        }
        __syncthreads();
    }
    #pragma unroll
    for (int m = 0; m < 20; m++) P[(size_t)m*4096 + n0 + t] = acc[m];
}

__global__ void skinny_reduce()
{
    int i = blockIdx.x*256 + threadIdx.x;
    if (i >= 20*4096) return;
    float sk = 0.f, sv = 0.f;
    #pragma unroll
    for (int z = 0; z < KSPL; z++) {
        sk += g_pk[(size_t)z*(20*4096) + i];
        sv += g_pv[(size_t)z*(20*4096) + i];
    }
    g_ak[i] = sk;
    g_av[i] = sv;
}

// ---------------- RoPE (fp32 in place) + split to fp16 hi/lo ----------------
__global__ void rope_split(float* __restrict__ T, __half* __restrict__ Th, __half* __restrict__ Tl,
                           const float* __restrict__ cosT, const float* __restrict__ sinT)
{
    int idx = blockIdx.x * blockDim.x + threadIdx.x;
    if (idx >= Bb*Ss*Hh*HALFh) return;
    int p = idx & (HALFh - 1);
    int s = (idx >> 11) & (Ss - 1);
    float c  = cosT[s*HALFh + p];
    float sn = sinT[s*HALFh + p];
    float2 v = *(float2*)&T[2*(size_t)idx];
    float2 r;
    r.x = v.x * c - v.y * sn;
    r.y = v.x * sn + v.y * c;
    *(float2*)&T[2*(size_t)idx] = r;
    __half h0 = __float2half_rn(r.x), h1 = __float2half_rn(r.y);
    *(__half2*)(Th + 2*(size_t)idx) = __halves2half2(h0, h1);
    *(__half2*)(Tl + 2*(size_t)idx) = __halves2half2(__float2half_rn(r.x - __half2float(h0)),
                                                     __float2half_rn(r.y - __half2float(h1)));
}

// ---------------- flash attention: QK 3-term, PV 2-term (Ph·Vh + Pl·Vh) ----------------
__global__ __launch_bounds__(256, 1) void flash_h()
{
    extern __shared__ char fsm[];
    const uint32_t sb = s2u(fsm);
    const int t = threadIdx.x, lane = t & 31, w = t >> 5;
    const int bh = blockIdx.y, b = bh >> 5, h = bh & 31;
    const int q0 = (int)(gridDim.x - 1 - blockIdx.x) * FQ;
    const size_t headbase = (size_t)b * Ss * Dd + (size_t)h * HDh;
    const int g = lane >> 2, tq = lane & 3;
    const float rscale = 0.08838834764831844f;
    const float NEGINF = __int_as_float(0xff800000);
    const int niter = (q0 + FQ) / FKV;

    auto prefetch_kv = [&](int j0, int st){
        const uint32_t kv = sb + KV0 + (uint32_t)st * KVSTG;
        const __half* kh = g_kh + headbase + (size_t)j0 * Dd;
        const __half* kl = g_kl + headbase + (size_t)j0 * Dd;
        const __half* vh = g_vh + headbase + (size_t)j0 * Dd;
        #pragma unroll
        for (int i = 0; i < 4; i++) {
            int idx = t + i*256;
            int r = idx >> 4, cq = idx & 15;
            uint32_t so = (uint32_t)(r*FROWB + cq*16);
            size_t go = (size_t)r*Dd + cq*8;
            asm volatile("cp.async.cg.shared.global [%0], [%1], 16;" :: "r"(kv + so),       "l"(kh + go));
            asm volatile("cp.async.cg.shared.global [%0], [%1], 16;" :: "r"(kv + KLO + so), "l"(kl + go));
            asm volatile("cp.async.cg.shared.global [%0], [%1], 16;" :: "r"(kv + VHO + so), "l"(vh + go));
        }
        asm volatile("cp.async.commit_group;" ::: "memory");
    };

    {
        const __half* qh = g_qh + headbase + (size_t)q0 * Dd;
        const __half* ql = g_ql + headbase + (size_t)q0 * Dd;
        #pragma unroll
        for (int i = 0; i < 8; i++) {
            int idx = t + i*256;
            int r = idx >> 4, cq = idx & 15;
            asm volatile("cp.async.cg.shared.global [%0], [%1], 16;"
                :: "r"(sb + QHOFF + (uint32_t)(r*FROWB + cq*16)), "l"(qh + (size_t)r*Dd + cq*8));
            asm volatile("cp.async.cg.shared.global [%0], [%1], 16;"
                :: "r"(sb + QLOFF + (uint32_t)(r*FROWB + cq*16)), "l"(ql + (size_t)r*Dd + cq*8));
        }
        prefetch_kv(0, 0);
    }

    const uint32_t aRow = (uint32_t)(w*16 + (lane & 7) + ((lane >> 3) & 1)*8);
    const uint32_t aKof = (uint32_t)(((lane >> 4) & 1) << 4);
    const uint32_t bRow = (uint32_t)((lane & 7) + ((lane >> 4) & 1)*8);
    const uint32_t bKof = (uint32_t)(((lane >> 3) & 1) << 4);
    const uint32_t vRow = (uint32_t)((lane & 7) + ((lane >> 3) & 1)*8);
    const uint32_t vDof = (uint32_t)(((lane >> 4) & 1) << 4);

    float o[16][4];
    #pragma unroll
    for (int nt = 0; nt < 16; nt++) { o[nt][0]=o[nt][1]=o[nt][2]=o[nt][3]=0.f; }
    float m0r = -1e30f, m1r = -1e30f, l0r = 0.f, l1r = 0.f;

    const int ig0 = q0 + w*16 + g;
    const int ig1 = ig0 + 8;

    for (int n = 0; n < niter; n++) {
        const int j0 = n * FKV;
        const int s_ = n & 1;

        asm volatile("cp.async.wait_group 0;" ::: "memory");
        __syncthreads();

        if (n + 1 < niter) prefetch_kv(j0 + FKV, 1 - s_);

        const uint32_t kv = sb + KV0 + (uint32_t)s_ * KVSTG;

        float s[8][4];
        #pragma unroll
        for (int nt = 0; nt < 8; nt++) { s[nt][0]=s[nt][1]=s[nt][2]=s[nt][3]=0.f; }
        #pragma unroll
        for (int ks = 0; ks < 8; ks++) {
            const uint32_t kb = (uint32_t)ks * 32u;
            uint32_t ah[4], al_[4];
            ldsm_x4(ah,  sb + QHOFF + aRow*FROWB + aKof + kb);
            ldsm_x4(al_, sb + QLOFF + aRow*FROWB + aKof + kb);
            #pragma unroll
            for (int np = 0; np < 4; np++) {
                uint32_t bhf[4], blf[4];
                ldsm_x4(bhf, kv + (bRow + np*16u)*FROWB + bKof + kb);
                ldsm_x4(blf, kv + KLO + (bRow + np*16u)*FROWB + bKof + kb);
                mma_h(s[2*np],   ah,  bhf[0], bhf[1]);
                mma_h(s[2*np],   ah,  blf[0], blf[1]);
                mma_h(s[2*np],   al_, bhf[0], bhf[1]);
                mma_h(s[2*np+1], ah,  bhf[2], bhf[3]);
                mma_h(s[2*np+1], ah,  blf[2], blf[3]);
                mma_h(s[2*np+1], al_, bhf[2], bhf[3]);
            }
        }

        float mx0 = -1e30f, mx1 = -1e30f;
        #pragma unroll
        for (int nt = 0; nt < 8; nt++) {
            int jg = j0 + nt*8 + 2*tq;
            s[nt][0] = (jg   > ig0) ? NEGINF : s[nt][0]*rscale;
            s[nt][1] = (jg+1 > ig0) ? NEGINF : s[nt][1]*rscale;
            s[nt][2] = (jg   > ig1) ? NEGINF : s[nt][2]*rscale;
            s[nt][3] = (jg+1 > ig1) ? NEGINF : s[nt][3]*rscale;
            mx0 = fmaxf(mx0, fmaxf(s[nt][0], s[nt][1]));
            mx1 = fmaxf(mx1, fmaxf(s[nt][2], s[nt][3]));
        }
        mx0 = fmaxf(mx0, __shfl_xor_sync(0xffffffffu, mx0, 1));
        mx0 = fmaxf(mx0, __shfl_xor_sync(0xffffffffu, mx0, 2));
        mx1 = fmaxf(mx1, __shfl_xor_sync(0xffffffffu, mx1, 1));
        mx1 = fmaxf(mx1, __shfl_xor_sync(0xffffffffu, mx1, 2));
        float mn0 = fmaxf(m0r, mx0), mn1 = fmaxf(m1r, mx1);
        float co0 = __expf(m0r - mn0), co1 = __expf(m1r - mn1);
        float sum0 = 0.f, sum1 = 0.f;
        #pragma unroll
        for (int nt = 0; nt < 8; nt++) {
            s[nt][0] = __expf(s[nt][0] - mn0);
            s[nt][1] = __expf(s[nt][1] - mn0);
            s[nt][2] = __expf(s[nt][2] - mn1);
            s[nt][3] = __expf(s[nt][3] - mn1);
            sum0 += s[nt][0] + s[nt][1];
            sum1 += s[nt][2] + s[nt][3];
        }
        sum0 += __shfl_xor_sync(0xffffffffu, sum0, 1);
        sum0 += __shfl_xor_sync(0xffffffffu, sum0, 2);
        sum1 += __shfl_xor_sync(0xffffffffu, sum1, 1);
        sum1 += __shfl_xor_sync(0xffffffffu, sum1, 2);
        l0r = l0r * co0 + sum0;  m0r = mn0;
        l1r = l1r * co1 + sum1;  m1r = mn1;

        #pragma unroll
        for (int nt = 0; nt < 16; nt++) {
            o[nt][0] *= co0; o[nt][1] *= co0;
            o[nt][2] *= co1; o[nt][3] *= co1;
        }

        #pragma unroll
        for (int ks = 0; ks < 4; ks++) {
            uint32_t ph[4], pl[4];
            split_pack(s[2*ks][0],   s[2*ks][1],   ph[0], pl[0]);
            split_pack(s[2*ks][2],   s[2*ks][3],   ph[1], pl[1]);
            split_pack(s[2*ks+1][0], s[2*ks+1][1], ph[2], pl[2]);
            split_pack(s[2*ks+1][2], s[2*ks+1][3], ph[3], pl[3]);
            const uint32_t krow = (uint32_t)(ks*16) + vRow;
            #pragma unroll
            for (int np = 0; np < 8; np++) {
                uint32_t vhf[4];
                ldsm_x4t(vhf, kv + VHO + krow*FROWB + (uint32_t)(np*32) + vDof);
                mma_h(o[2*np],   ph, vhf[0], vhf[1]);
                mma_h(o[2*np],   pl, vhf[0], vhf[1]);
                mma_h(o[2*np+1], ph, vhf[2], vhf[3]);
                mma_h(o[2*np+1], pl, vhf[2], vhf[3]);
            }
        }
        __syncthreads();
    }

    float inv0 = 1.f / l0r, inv1 = 1.f / l1r;
    float* Og = g_attn + headbase + (size_t)(q0 + w*16) * Dd;
    #pragma unroll
    for (int nt = 0; nt < 16; nt++) {
        *(float2*)&Og[(size_t)g*Dd     + nt*8 + 2*tq] = make_float2(o[nt][0]*inv0, o[nt][1]*inv0);
        *(float2*)&Og[(size_t)(g+8)*Dd + nt*8 + 2*tq] = make_float2(o[nt][2]*inv1, o[nt][3]*inv1);
    }
}

// ---------------- adapter attention (+ writes fp16 split of final attn) ----------------
__global__ __launch_bounds__(128) void adapter_kernel(const float* __restrict__ gate)
{
    __shared__ __align__(16) float ak[ALa][HDh];
    __shared__ __align__(16) float av[ALa][HDh];
    const int t = threadIdx.x;
    const int bh = blockIdx.y;
    const int b = bh >> 5, h = bh & 31;
    const int s0 = blockIdx.x * 4;

    #pragma unroll
    for (int r = 0; r < ALa; r++) {
        int idx = t + r*128;
        int j = idx >> 7, d = idx & 127;
        ak[j][d] = g_ak[(size_t)(b*ALa + j) * Dd + h*HDh + d];
        av[j][d] = g_av[(size_t)(b*ALa + j) * Dd + h*HDh + d];
    }
    __syncthreads();

    const int w = t >> 5, lane = t & 31;
    const int s = s0 + w;
    const size_t base = (size_t)(b*Ss + s) * Dd + h*HDh;
    const float rscale = 0.08838834764831844f;

    float4 qv = *(const float4*)&g_q[base + lane*4];
    float sc[ALa];
    #pragma unroll
    for (int j = 0; j < ALa; j++) {
        float d0 = qv.x*ak[j][lane*4+0] + qv.y*ak[j][lane*4+1]
                 + qv.z*ak[j][lane*4+2] + qv.w*ak[j][lane*4+3];
        #pragma unroll
        for (int off = 16; off >= 1; off >>= 1)
            d0 += __shfl_xor_sync(0xffffffffu, d0, off);
        sc[j] = d0 * rscale;
    }
    float mx = sc[0];
    #pragma unroll
    for (int j = 1; j < ALa; j++) mx = fmaxf(mx, sc[j]);
    float sum = 0.f;
    #pragma unroll
    for (int j = 0; j < ALa; j++) { sc[j] = __expf(sc[j] - mx); sum += sc[j]; }
    float inv = 1.f / sum;
    float gg = tanhf(gate[h]);

    float acc[4] = {0.f, 0.f, 0.f, 0.f};
    #pragma unroll
    for (int j = 0; j < ALa; j++) {
        float p = sc[j] * inv;
        acc[0] += p * av[j][lane*4+0];
        acc[1] += p * av[j][lane*4+1];
        acc[2] += p * av[j][lane*4+2];
        acc[3] += p * av[j][lane*4+3];
    }
    float4 ov = *(float4*)&g_attn[base + lane*4];
    ov.x += gg*acc[0]; ov.y += gg*acc[1]; ov.z += gg*acc[2]; ov.w += gg*acc[3];
    *(float4*)&g_attn[base + lane*4] = ov;

    __half h0 = __float2half_rn(ov.x), h1 = __float2half_rn(ov.y);
    __half h2 = __float2half_rn(ov.z), h3 = __float2half_rn(ov.w);
    *(__half2*)(g_ah + base + lane*4)     = __halves2half2(h0, h1);
    *(__half2*)(g_ah + base + lane*4 + 2) = __halves2half2(h2, h3);
    *(__half2*)(g_al + base + lane*4)     = __halves2half2(__float2half_rn(ov.x - __half2float(h0)),
                                                           __float2half_rn(ov.y - __half2float(h1)));
    *(__half2*)(g_al + base + lane*4 + 2) = __halves2half2(__float2half_rn(ov.z - __half2float(h2)),
                                                           __float2half_rn(ov.w - __half2float(h3)));
}

// ---------------- host ----------------
extern "C" void kernel_launch(void* const* d_in, const int* in_sizes, int n_in,
                              void* d_out, int out_size)
{
    (void)in_sizes; (void)n_in; (void)out_size;
    const float* x       = (const float*)d_in[0];
    const float* cosT    = (const float*)d_in[2];
    const float* sinT    = (const float*)d_in[3];
    const float* wq      = (const float*)d_in[4];
    const float* wk      = (const float*)d_in[5];
    const float* wv      = (const float*)d_in[6];
    const float* wo      = (const float*)d_in[7];
    const float* gate    = (const float*)d_in[8];
    const float* adapter = (const float*)d_in[9];
    float* out = (float*)d_out;

    float *qp, *kp, *vp, *attnp;
    __half *ahp, *alp, *wqh, *wkh, *wvh, *woh, *wol;
    __half *qhp, *qlp, *khp, *klp, *vhp;
    cudaGetSymbolAddress((void**)&qp,    g_q);
    cudaGetSymbolAddress((void**)&kp,    g_k);
    cudaGetSymbolAddress((void**)&vp,    g_v);
    cudaGetSymbolAddress((void**)&attnp, g_attn);
    cudaGetSymbolAddress((void**)&ahp,  g_ah);  cudaGetSymbolAddress((void**)&alp,  g_al);
    cudaGetSymbolAddress((void**)&wqh,  g_wqh);
    cudaGetSymbolAddress((void**)&wkh,  g_wkh);
    cudaGetSymbolAddress((void**)&wvh,  g_wvh);
    cudaGetSymbolAddress((void**)&woh,  g_woh); cudaGetSymbolAddress((void**)&wol,  g_wol);
    cudaGetSymbolAddress((void**)&qhp,  g_qh);  cudaGetSymbolAddress((void**)&qlp,  g_ql);
    cudaGetSymbolAddress((void**)&khp,  g_kh);  cudaGetSymbolAddress((void**)&klp,  g_kl);
    cudaGetSymbolAddress((void**)&vhp,  g_vh);

    cudaFuncSetAttribute(gemm_h2f, cudaFuncAttributeMaxDynamicSharedMemorySize, GEMM2_SMEM);
    cudaFuncSetAttribute(gemm_h3f, cudaFuncAttributeMaxDynamicSharedMemorySize, GEMM3_SMEM);
    cudaFuncSetAttribute(flash_h, cudaFuncAttributeMaxDynamicSharedMemorySize, FLASH_SMEM);

    const int nXW = Mtok*Dd;
    const int cgrid = nXW/4/256;

    conv_split<<<cgrid, 256>>>(x,  ahp, alp, nXW);
    conv_hi<<<cgrid, 256>>>(wq, wqh, Dd*Dd);
    conv_hi<<<cgrid, 256>>>(wk, wkh, Dd*Dd);
    conv_hi<<<cgrid, 256>>>(wv, wvh, Dd*Dd);
    conv_split<<<cgrid, 256>>>(wo, woh, wol, Dd*Dd);

    dim3 gbig(Dd/BN, Mtok/BM);
    gemm_h2f<<<gbig, 256, GEMM2_SMEM>>>(ahp, alp, wqh, qp, Mtok, Dd, Dd);
    gemm_h2f<<<gbig, 256, GEMM2_SMEM>>>(ahp, alp, wkh, kp, Mtok, Dd, Dd);
    gemm_h2f<<<gbig, 256, GEMM2_SMEM>>>(ahp, alp, wvh, vp, Mtok, Dd, Dd);

    gemm_skinny<<<dim3(Dd/128, KSPL, 2), 128>>>(adapter, wk, wv);
    skinny_reduce<<<(20*4096 + 255)/256, 256>>>();

    int npairs = Bb*Ss*Hh*HALFh;
    rope_split<<<npairs/256, 256>>>(qp, qhp, qlp, cosT, sinT);
    rope_split<<<npairs/256, 256>>>(kp, khp, klp, cosT, sinT);
    conv_hi<<<cgrid, 256>>>(vp, vhp, nXW);

    flash_h<<<dim3(Ss/FQ, Bb*Hh), 256, FLASH_SMEM>>>();
    adapter_kernel<<<dim3(Ss/4, Bb*Hh), 128>>>(gate);

    gemm_h3f<<<gbig, 256, GEMM3_SMEM>>>(ahp, alp, woh, wol, out, Mtok, Dd, Dd);
}

// round 14
// speedup vs baseline: 1.4299x; 1.0966x over previous
#include <cuda_runtime.h>
#include <cuda_fp16.h>
#include <math.h>
#include <stdint.h>

#define Bb 2
#define Ss 2048
#define Dd 4096
#define Hh 32
#define HDh 128
#define HALFh 64
#define ALa 10
#define Mtok (Bb*Ss)

// ---- fp16 GEMM common ----
#define BM 128
#define BN 128
#define BKh 64                       // halves per K-chunk = 128B row
#define HROWB 144                    // smem row bytes (128 data + 16 pad)
#define OPB (128*HROWB)              // one operand = 18432 B

// 2-term: Ah, Al, Bh; 4 stages
#define STAGE2_B (3*OPB)
#define NST2 4
#define GEMM2_SMEM (NST2*STAGE2_B)   // 221184 B

// ---- flash config (double-buffered KV: KH,KL,VH) ----
#define FQ 128
#define FKV 64
#define FROWB 272                    // 128 halves + 8 pad
#define QHOFF 0
#define QLOFF (128*FROWB)
#define KV0 (QLOFF + 128*FROWB)
#define KVSTG (3*64*FROWB)           // 52224 B
#define KLO (64*FROWB)
#define VHO (2*64*FROWB)
#define FLASH_SMEM (KV0 + 2*KVSTG)   // 174080 B

#define KSPL 8

// ---------------- scratch (static device globals) ----------------
__device__ float g_q[Mtok*Dd];
__device__ float g_k[Mtok*Dd];
__device__ float g_attn[Mtok*Dd];
__device__ float g_ak[Bb*ALa*Dd];
__device__ float g_av[Bb*ALa*Dd];
__device__ float g_pk[KSPL*Bb*ALa*Dd];
__device__ float g_pv[KSPL*Bb*ALa*Dd];

__device__ __half g_ah[Mtok*Dd];   // x split; later holds attn split
__device__ __half g_al[Mtok*Dd];
__device__ __half g_wqh[Dd*Dd];
__device__ __half g_wkh[Dd*Dd];
__device__ __half g_wvh[Dd*Dd];
__device__ __half g_woh[Dd*Dd];
__device__ __half g_qh[Mtok*Dd], g_ql[Mtok*Dd];
__device__ __half g_kh[Mtok*Dd], g_kl[Mtok*Dd];
__device__ __half g_vh[Mtok*Dd];

// ---------------- helpers ----------------
__device__ __forceinline__ uint32_t s2u(const void* p){
    uint32_t r;
    asm("{ .reg .u64 t; cvta.to.shared.u64 t, %1; cvt.u32.u64 %0, t; }" : "=r"(r) : "l"(p));
    return r;
}

__device__ __forceinline__ void ldsm_x4(uint32_t* r, uint32_t addr){
    asm volatile("ldmatrix.sync.aligned.m8n8.x4.shared.b16 {%0,%1,%2,%3}, [%4];"
                 : "=r"(r[0]), "=r"(r[1]), "=r"(r[2]), "=r"(r[3]) : "r"(addr));
}
__device__ __forceinline__ void ldsm_x4t(uint32_t* r, uint32_t addr){
    asm volatile("ldmatrix.sync.aligned.m8n8.x4.trans.shared.b16 {%0,%1,%2,%3}, [%4];"
                 : "=r"(r[0]), "=r"(r[1]), "=r"(r[2]), "=r"(r[3]) : "r"(addr));
}

__device__ __forceinline__ void mma_h(float* d, const uint32_t* a, uint32_t b0, uint32_t b1){
    asm volatile(
        "mma.sync.aligned.m16n8k16.row.col.f32.f16.f16.f32 "
        "{%0,%1,%2,%3}, {%4,%5,%6,%7}, {%8,%9}, {%0,%1,%2,%3};"
        : "+f"(d[0]), "+f"(d[1]), "+f"(d[2]), "+f"(d[3])
        : "r"(a[0]), "r"(a[1]), "r"(a[2]), "r"(a[3]), "r"(b0), "r"(b1));
}

__device__ __forceinline__ uint32_t packh2(float lo, float hi){
    uint32_t r;
    asm("cvt.rn.f16x2.f32 %0, %1, %2;" : "=r"(r) : "f"(hi), "f"(lo));
    return r;
}

__device__ __forceinline__ void split_pack(float f0, float f1, uint32_t& hi, uint32_t& lo){
    __half h0 = __float2half_rn(f0), h1 = __float2half_rn(f1);
    __half2 hh = __halves2half2(h0, h1);
    hi = *reinterpret_cast<uint32_t*>(&hh);
    lo = packh2(f0 - __half2float(h0), f1 - __half2float(h1));
}

// epilogue functors (no extended-lambda dependency)
struct OutF32 {
    float* C; int N;
    __device__ __forceinline__ void operator()(int row, int col, float v0, float v1) const {
        *(float2*)&C[(size_t)row * N + col] = make_float2(v0, v1);
    }
};
struct OutF16 {
    __half* C; int N;
    __device__ __forceinline__ void operator()(int row, int col, float v0, float v1) const {
        *(__half2*)&C[(size_t)row * N + col] =
            __halves2half2(__float2half_rn(v0), __float2half_rn(v1));
    }
};

// ---------------- conversions ----------------
__global__ void conv_split(const float* __restrict__ s, __half* __restrict__ hi,
                           __half* __restrict__ lo, int n)
{
    int i = (blockIdx.x*256 + threadIdx.x) * 4;
    if (i >= n) return;
    float4 v = *(const float4*)(s + i);
    __half h0 = __float2half_rn(v.x), h1 = __float2half_rn(v.y);
    __half h2 = __float2half_rn(v.z), h3 = __float2half_rn(v.w);
    *(__half2*)(hi + i)     = __halves2half2(h0, h1);
    *(__half2*)(hi + i + 2) = __halves2half2(h2, h3);
    *(__half2*)(lo + i)     = __halves2half2(__float2half_rn(v.x - __half2float(h0)),
                                             __float2half_rn(v.y - __half2float(h1)));
    *(__half2*)(lo + i + 2) = __halves2half2(__float2half_rn(v.z - __half2float(h2)),
                                             __float2half_rn(v.w - __half2float(h3)));
}

__global__ void conv_hi(const float* __restrict__ s, __half* __restrict__ hi, int n)
{
    int i = (blockIdx.x*256 + threadIdx.x) * 4;
    if (i >= n) return;
    float4 v = *(const float4*)(s + i);
    *(__half2*)(hi + i)     = __halves2half2(__float2half_rn(v.x), __float2half_rn(v.y));
    *(__half2*)(hi + i + 2) = __halves2half2(__float2half_rn(v.z), __float2half_rn(v.w));
}

// ---------------- 2-term fp16 NT GEMM core (templated epilogue) ----------------
template<typename OUTW>
__device__ __forceinline__ void gemm_h2_body(
    const __half* __restrict__ Ah, const __half* __restrict__ Al,
    const __half* __restrict__ Bh, OUTW outw, int M, int N, int K, char* smg)
{
    const uint32_t sbase = s2u(smg);
    const int t = threadIdx.x;
    const int m0 = blockIdx.y * BM;
    const int n0 = blockIdx.x * BN;
    const int NCH = K / BKh;

    const int lane = t & 31;
    const int wid  = t >> 5;
    const int wm   = wid & 3;
    const int wn   = wid >> 2;

    float d[2][8][4];
    #pragma unroll
    for (int mt = 0; mt < 2; mt++)
        #pragma unroll
        for (int nt = 0; nt < 8; nt++)
            #pragma unroll
            for (int c = 0; c < 4; c++) d[mt][nt][c] = 0.f;

    const uint32_t aRow = (uint32_t)(wm*32 + (lane & 7) + ((lane >> 3) & 1)*8);
    const uint32_t aKof = (uint32_t)(((lane >> 4) & 1) << 4);
    const uint32_t bRow = (uint32_t)(wn*64 + (lane & 7) + ((lane >> 4) & 1)*8);
    const uint32_t bKof = (uint32_t)(((lane >> 3) & 1) << 4);

    const int ldr = t >> 3;
    const int ldq = t & 7;

    auto prefetch = [&](int chunk, int stage){
        const int k0 = chunk * BKh;
        const uint32_t st = sbase + (uint32_t)stage * STAGE2_B;
        #pragma unroll
        for (int i = 0; i < 4; i++) {
            int row = ldr + i*32;
            int ar = m0 + row; if (ar > M-1) ar = M-1;
            size_t goa = (size_t)ar * K + k0 + ldq*8;
            size_t gob = (size_t)(n0 + row) * K + k0 + ldq*8;
            uint32_t so = (uint32_t)row * HROWB + (uint32_t)ldq * 16u;
            asm volatile("cp.async.cg.shared.global [%0], [%1], 16;" :: "r"(st + 0*OPB + so), "l"(Ah + goa));
            asm volatile("cp.async.cg.shared.global [%0], [%1], 16;" :: "r"(st + 1*OPB + so), "l"(Al + goa));
            asm volatile("cp.async.cg.shared.global [%0], [%1], 16;" :: "r"(st + 2*OPB + so), "l"(Bh + gob));
        }
        asm volatile("cp.async.commit_group;" ::: "memory");
    };

    #pragma unroll
    for (int p = 0; p < NST2; p++) prefetch(p, p);

    int stage = 0;
    for (int n = 0; n < NCH; n++) {
        asm volatile("cp.async.wait_group %0;" :: "n"(NST2-1) : "memory");
        __syncthreads();

        const uint32_t st = sbase + (uint32_t)stage * STAGE2_B;
        const uint32_t sAh = st, sAl = st + OPB, sBh = st + 2*OPB;

        #pragma unroll
        for (int ks = 0; ks < 4; ks++) {
            const uint32_t kb = (uint32_t)ks * 32u;
            uint32_t ah[2][4], al[2][4];
            #pragma unroll
            for (int mt = 0; mt < 2; mt++) {
                ldsm_x4(ah[mt], sAh + (aRow + mt*16u)*HROWB + aKof + kb);
                ldsm_x4(al[mt], sAl + (aRow + mt*16u)*HROWB + aKof + kb);
            }
            #pragma unroll
            for (int np = 0; np < 4; np++) {
                uint32_t bh[4];
                ldsm_x4(bh, sBh + (bRow + np*16u)*HROWB + bKof + kb);
                #pragma unroll
                for (int mt = 0; mt < 2; mt++) {
                    mma_h(d[mt][2*np],   ah[mt], bh[0], bh[1]);
                    mma_h(d[mt][2*np],   al[mt], bh[0], bh[1]);
                    mma_h(d[mt][2*np+1], ah[mt], bh[2], bh[3]);
                    mma_h(d[mt][2*np+1], al[mt], bh[2], bh[3]);
                }
            }
        }
        __syncthreads();

        int pn = n + NST2; if (pn >= NCH) pn = 0;
        prefetch(pn, stage);
        stage++; if (stage == NST2) stage = 0;
    }

    const int g  = lane >> 2;
    const int tq = lane & 3;
    #pragma unroll
    for (int mt = 0; mt < 2; mt++) {
        int row = m0 + wm*32 + mt*16 + g;
        #pragma unroll
        for (int nt = 0; nt < 8; nt++) {
            int col = n0 + wn*64 + nt*8 + 2*tq;
            if (row < M)     outw(row,     col, d[mt][nt][0], d[mt][nt][1]);
            if (row + 8 < M) outw(row + 8, col, d[mt][nt][2], d[mt][nt][3]);
        }
    }
}

__global__ __launch_bounds__(256) void gemm_h2f(
    const __half* __restrict__ Ah, const __half* __restrict__ Al,
    const __half* __restrict__ Bh, float* __restrict__ C, int M, int N, int K)
{
    extern __shared__ char smg[];
    OutF32 o{C, N};
    gemm_h2_body(Ah, Al, Bh, o, M, N, K, smg);
}

__global__ __launch_bounds__(256) void gemm_h2h(
    const __half* __restrict__ Ah, const __half* __restrict__ Al,
    const __half* __restrict__ Bh, __half* __restrict__ Ch, int M, int N, int K)
{
    extern __shared__ char smg[];
    OutF16 o{Ch, N};
    gemm_h2_body(Ah, Al, Bh, o, M, N, K, smg);
}

// ---------------- skinny adapter GEMM (M=20, fp32, split-K) ----------------
__global__ __launch_bounds__(128) void gemm_skinny(
    const float* __restrict__ Aad, const float* __restrict__ wk, const float* __restrict__ wv)
{
    __shared__ float As[20][33];
    __shared__ float Bs[128][33];
    const int t = threadIdx.x;
    const int n0 = blockIdx.x * 128;
    const int kz = blockIdx.y;
    const float* W = blockIdx.z ? wv : wk;
    float* P = (blockIdx.z ? g_pv : g_pk) + (size_t)kz * (20*4096);

    float acc[20];
    #pragma unroll
    for (int m = 0; m < 20; m++) acc[m] = 0.f;

    for (int k0 = kz*512; k0 < kz*512 + 512; k0 += 32) {
        for (int i = t; i < 640; i += 128) {
            int r = i >> 5, c = i & 31;
            As[r][c] = Aad[(size_t)r*4096 + k0 + c];
        }
        #pragma unroll
        for (int i = 0; i < 8; i++) {
            int idx = t + i*128;
            int r = idx >> 3, cq = idx & 7;
            float4 v = *(const float4*)&W[(size_t)(n0 + r)*4096 + k0 + cq*4];
            Bs[r][cq*4+0] = v.x; Bs[r][cq*4+1] = v.y;
            Bs[r][cq*4+2] = v.z; Bs[r][cq*4+3] = v.w;
        }
        __syncthreads();
        #pragma unroll
        for (int k = 0; k < 32; k++) {
            float bv = Bs[t][k];
            #pragma unroll
            for (int m = 0; m < 20; m++) acc[m] += As[m][k] * bv;
        }
        __syncthreads();
    }
    #pragma unroll
    for (int m = 0; m < 20; m++) P[(size_t)m*4096 + n0 + t] = acc[m];
}

__global__ void skinny_reduce()
{
    int i = blockIdx.x*256 + threadIdx.x;
    if (i >= 20*4096) return;
    float sk = 0.f, sv = 0.f;
    #pragma unroll
    for (int z = 0; z < KSPL; z++) {
        sk += g_pk[(size_t)z*(20*4096) + i];
        sv += g_pv[(size_t)z*(20*4096) + i];
    }
    g_ak[i] = sk;
    g_av[i] = sv;
}

// ---------------- RoPE (fp32 in place) + split to fp16 hi/lo ----------------
__global__ void rope_split(float* __restrict__ T, __half* __restrict__ Th, __half* __restrict__ Tl,
                           const float* __restrict__ cosT, const float* __restrict__ sinT)
{
    int idx = blockIdx.x * blockDim.x + threadIdx.x;
    if (idx >= Bb*Ss*Hh*HALFh) return;
    int p = idx & (HALFh - 1);
    int s = (idx >> 11) & (Ss - 1);
    float c  = cosT[s*HALFh + p];
    float sn = sinT[s*HALFh + p];
    float2 v = *(float2*)&T[2*(size_t)idx];
    float2 r;
    r.x = v.x * c - v.y * sn;
    r.y = v.x * sn + v.y * c;
    *(float2*)&T[2*(size_t)idx] = r;
    __half h0 = __float2half_rn(r.x), h1 = __float2half_rn(r.y);
    *(__half2*)(Th + 2*(size_t)idx) = __halves2half2(h0, h1);
    *(__half2*)(Tl + 2*(size_t)idx) = __halves2half2(__float2half_rn(r.x - __half2float(h0)),
                                                     __float2half_rn(r.y - __half2float(h1)));
}

// ---------------- flash attention: QK 3-term, PV 2-term ----------------
__global__ __launch_bounds__(256, 1) void flash_h()
{
    extern __shared__ char fsm[];
    const uint32_t sb = s2u(fsm);
    const int t = threadIdx.x, lane = t & 31, w = t >> 5;
    const int bh = blockIdx.y, b = bh >> 5, h = bh & 31;
    const int q0 = (int)(gridDim.x - 1 - blockIdx.x) * FQ;
    const size_t headbase = (size_t)b * Ss * Dd + (size_t)h * HDh;
    const int g = lane >> 2, tq = lane & 3;
    const float rscale = 0.08838834764831844f;
    const float NEGINF = __int_as_float(0xff800000);
    const int niter = (q0 + FQ) / FKV;

    auto prefetch_kv = [&](int j0, int st){
        const uint32_t kv = sb + KV0 + (uint32_t)st * KVSTG;
        const __half* kh = g_kh + headbase + (size_t)j0 * Dd;
        const __half* kl = g_kl + headbase + (size_t)j0 * Dd;
        const __half* vh = g_vh + headbase + (size_t)j0 * Dd;
        #pragma unroll
        for (int i = 0; i < 4; i++) {
            int idx = t + i*256;
            int r = idx >> 4, cq = idx & 15;
            uint32_t so = (uint32_t)(r*FROWB + cq*16);
            size_t go = (size_t)r*Dd + cq*8;
            asm volatile("cp.async.cg.shared.global [%0], [%1], 16;" :: "r"(kv + so),       "l"(kh + go));
            asm volatile("cp.async.cg.shared.global [%0], [%1], 16;" :: "r"(kv + KLO + so), "l"(kl + go));
            asm volatile("cp.async.cg.shared.global [%0], [%1], 16;" :: "r"(kv + VHO + so), "l"(vh + go));
        }
        asm volatile("cp.async.commit_group;" ::: "memory");
    };

    {
        const __half* qh = g_qh + headbase + (size_t)q0 * Dd;
        const __half* ql = g_ql + headbase + (size_t)q0 * Dd;
        #pragma unroll
        for (int i = 0; i < 8; i++) {
            int idx = t + i*256;
            int r = idx >> 4, cq = idx & 15;
            asm volatile("cp.async.cg.shared.global [%0], [%1], 16;"
                :: "r"(sb + QHOFF + (uint32_t)(r*FROWB + cq*16)), "l"(qh + (size_t)r*Dd + cq*8));
            asm volatile("cp.async.cg.shared.global [%0], [%1], 16;"
                :: "r"(sb + QLOFF + (uint32_t)(r*FROWB + cq*16)), "l"(ql + (size_t)r*Dd + cq*8));
        }
        prefetch_kv(0, 0);
    }

    const uint32_t aRow = (uint32_t)(w*16 + (lane & 7) + ((lane >> 3) & 1)*8);
    const uint32_t aKof = (uint32_t)(((lane >> 4) & 1) << 4);
    const uint32_t bRow = (uint32_t)((lane & 7) + ((lane >> 4) & 1)*8);
    const uint32_t bKof = (uint32_t)(((lane >> 3) & 1) << 4);
    const uint32_t vRow = (uint32_t)((lane & 7) + ((lane >> 3) & 1)*8);
    const uint32_t vDof = (uint32_t)(((lane >> 4) & 1) << 4);

    float o[16][4];
    #pragma unroll
    for (int nt = 0; nt < 16; nt++) { o[nt][0]=o[nt][1]=o[nt][2]=o[nt][3]=0.f; }
    float m0r = -1e30f, m1r = -1e30f, l0r = 0.f, l1r = 0.f;

    const int ig0 = q0 + w*16 + g;
    const int ig1 = ig0 + 8;

    for (int n = 0; n < niter; n++) {
        const int j0 = n * FKV;
        const int s_ = n & 1;

        asm volatile("cp.async.wait_group 0;" ::: "memory");
        __syncthreads();

        if (n + 1 < niter) prefetch_kv(j0 + FKV, 1 - s_);

        const uint32_t kv = sb + KV0 + (uint32_t)s_ * KVSTG;

        float s[8][4];
        #pragma unroll
        for (int nt = 0; nt < 8; nt++) { s[nt][0]=s[nt][1]=s[nt][2]=s[nt][3]=0.f; }
        #pragma unroll
        for (int ks = 0; ks < 8; ks++) {
            const uint32_t kb = (uint32_t)ks * 32u;
            uint32_t ah[4], al_[4];
            ldsm_x4(ah,  sb + QHOFF + aRow*FROWB + aKof + kb);
            ldsm_x4(al_, sb + QLOFF + aRow*FROWB + aKof + kb);
            #pragma unroll
            for (int np = 0; np < 4; np++) {
                uint32_t bhf[4], blf[4];
                ldsm_x4(bhf, kv + (bRow + np*16u)*FROWB + bKof + kb);
                ldsm_x4(blf, kv + KLO + (bRow + np*16u)*FROWB + bKof + kb);
                mma_h(s[2*np],   ah,  bhf[0], bhf[1]);
                mma_h(s[2*np],   ah,  blf[0], blf[1]);
                mma_h(s[2*np],   al_, bhf[0], bhf[1]);
                mma_h(s[2*np+1], ah,  bhf[2], bhf[3]);
                mma_h(s[2*np+1], ah,  blf[2], blf[3]);
                mma_h(s[2*np+1], al_, bhf[2], bhf[3]);
            }
        }

        float mx0 = -1e30f, mx1 = -1e30f;
        #pragma unroll
        for (int nt = 0; nt < 8; nt++) {
            int jg = j0 + nt*8 + 2*tq;
            s[nt][0] = (jg   > ig0) ? NEGINF : s[nt][0]*rscale;
            s[nt][1] = (jg+1 > ig0) ? NEGINF : s[nt][1]*rscale;
            s[nt][2] = (jg   > ig1) ? NEGINF : s[nt][2]*rscale;
            s[nt][3] = (jg+1 > ig1) ? NEGINF : s[nt][3]*rscale;
            mx0 = fmaxf(mx0, fmaxf(s[nt][0], s[nt][1]));
            mx1 = fmaxf(mx1, fmaxf(s[nt][2], s[nt][3]));
        }
        mx0 = fmaxf(mx0, __shfl_xor_sync(0xffffffffu, mx0, 1));
        mx0 = fmaxf(mx0, __shfl_xor_sync(0xffffffffu, mx0, 2));
        mx1 = fmaxf(mx1, __shfl_xor_sync(0xffffffffu, mx1, 1));
        mx1 = fmaxf(mx1, __shfl_xor_sync(0xffffffffu, mx1, 2));
        float mn0 = fmaxf(m0r, mx0), mn1 = fmaxf(m1r, mx1);
        float co0 = __expf(m0r - mn0), co1 = __expf(m1r - mn1);
        float sum0 = 0.f, sum1 = 0.f;
        #pragma unroll
        for (int nt = 0; nt < 8; nt++) {
            s[nt][0] = __expf(s[nt][0] - mn0);
            s[nt][1] = __expf(s[nt][1] - mn0);
            s[nt][2] = __expf(s[nt][2] - mn1);
            s[nt][3] = __expf(s[nt][3] - mn1);
            sum0 += s[nt][0] + s[nt][1];
            sum1 += s[nt][2] + s[nt][3];
        }
        sum0 += __shfl_xor_sync(0xffffffffu, sum0, 1);
        sum0 += __shfl_xor_sync(0xffffffffu, sum0, 2);
        sum1 += __shfl_xor_sync(0xffffffffu, sum1, 1);
        sum1 += __shfl_xor_sync(0xffffffffu, sum1, 2);
        l0r = l0r * co0 + sum0;  m0r = mn0;
        l1r = l1r * co1 + sum1;  m1r = mn1;

        #pragma unroll
        for (int nt = 0; nt < 16; nt++) {
            o[nt][0] *= co0; o[nt][1] *= co0;
            o[nt][2] *= co1; o[nt][3] *= co1;
        }

        #pragma unroll
        for (int ks = 0; ks < 4; ks++) {
            uint32_t ph[4], pl[4];
            split_pack(s[2*ks][0],   s[2*ks][1],   ph[0], pl[0]);
            split_pack(s[2*ks][2],   s[2*ks][3],   ph[1], pl[1]);
            split_pack(s[2*ks+1][0], s[2*ks+1][1], ph[2], pl[2]);
            split_pack(s[2*ks+1][2], s[2*ks+1][3], ph[3], pl[3]);
            const uint32_t krow = (uint32_t)(ks*16) + vRow;
            #pragma unroll
            for (int np = 0; np < 8; np++) {
                uint32_t vhf[4];
                ldsm_x4t(vhf, kv + VHO + krow*FROWB + (uint32_t)(np*32) + vDof);
                mma_h(o[2*np],   ph, vhf[0], vhf[1]);
                mma_h(o[2*np],   pl, vhf[0], vhf[1]);
                mma_h(o[2*np+1], ph, vhf[2], vhf[3]);
                mma_h(o[2*np+1], pl, vhf[2], vhf[3]);
            }
        }
        __syncthreads();
    }

    float inv0 = 1.f / l0r, inv1 = 1.f / l1r;
    float* Og = g_attn + headbase + (size_t)(q0 + w*16) * Dd;
    #pragma unroll
    for (int nt = 0; nt < 16; nt++) {
        *(float2*)&Og[(size_t)g*Dd     + nt*8 + 2*tq] = make_float2(o[nt][0]*inv0, o[nt][1]*inv0);
        *(float2*)&Og[(size_t)(g+8)*Dd + nt*8 + 2*tq] = make_float2(o[nt][2]*inv1, o[nt][3]*inv1);
    }
}

// ---------------- adapter attention (+ writes fp16 split of final attn) ----------------
__global__ __launch_bounds__(128) void adapter_kernel(const float* __restrict__ gate)
{
    __shared__ __align__(16) float ak[ALa][HDh];
    __shared__ __align__(16) float av[ALa][HDh];
    const int t = threadIdx.x;
    const int bh = blockIdx.y;
    const int b = bh >> 5, h = bh & 31;
    const int s0 = blockIdx.x * 4;

    #pragma unroll
    for (int r = 0; r < ALa; r++) {
        int idx = t + r*128;
        int j = idx >> 7, d = idx & 127;
        ak[j][d] = g_ak[(size_t)(b*ALa + j) * Dd + h*HDh + d];
        av[j][d] = g_av[(size_t)(b*ALa + j) * Dd + h*HDh + d];
    }
    __syncthreads();

    const int w = t >> 5, lane = t & 31;
    const int s = s0 + w;
    const size_t base = (size_t)(b*Ss + s) * Dd + h*HDh;
    const float rscale = 0.08838834764831844f;

    float4 qv = *(const float4*)&g_q[base + lane*4];
    float sc[ALa];
    #pragma unroll
    for (int j = 0; j < ALa; j++) {
        float d0 = qv.x*ak[j][lane*4+0] + qv.y*ak[j][lane*4+1]
                 + qv.z*ak[j][lane*4+2] + qv.w*ak[j][lane*4+3];
        #pragma unroll
        for (int off = 16; off >= 1; off >>= 1)
            d0 += __shfl_xor_sync(0xffffffffu, d0, off);
        sc[j] = d0 * rscale;
    }
    float mx = sc[0];
    #pragma unroll
    for (int j = 1; j < ALa; j++) mx = fmaxf(mx, sc[j]);
    float sum = 0.f;
    #pragma unroll
    for (int j = 0; j < ALa; j++) { sc[j] = __expf(sc[j] - mx); sum += sc[j]; }
    float inv = 1.f / sum;
    float gg = tanhf(gate[h]);

    float acc[4] = {0.f, 0.f, 0.f, 0.f};
    #pragma unroll
    for (int j = 0; j < ALa; j++) {
        float p = sc[j] * inv;
        acc[0] += p * av[j][lane*4+0];
        acc[1] += p * av[j][lane*4+1];
        acc[2] += p * av[j][lane*4+2];
        acc[3] += p * av[j][lane*4+3];
    }
    float4 ov = *(float4*)&g_attn[base + lane*4];
    ov.x += gg*acc[0]; ov.y += gg*acc[1]; ov.z += gg*acc[2]; ov.w += gg*acc[3];
    *(float4*)&g_attn[base + lane*4] = ov;

    __half h0 = __float2half_rn(ov.x), h1 = __float2half_rn(ov.y);
    __half h2 = __float2half_rn(ov.z), h3 = __float2half_rn(ov.w);
    *(__half2*)(g_ah + base + lane*4)     = __halves2half2(h0, h1);
    *(__half2*)(g_ah + base + lane*4 + 2) = __halves2half2(h2, h3);
    *(__half2*)(g_al + base + lane*4)     = __halves2half2(__float2half_rn(ov.x - __half2float(h0)),
                                                           __float2half_rn(ov.y - __half2float(h1)));
    *(__half2*)(g_al + base + lane*4 + 2) = __halves2half2(__float2half_rn(ov.z - __half2float(h2)),
                                                           __float2half_rn(ov.w - __half2float(h3)));
}

// ---------------- host ----------------
extern "C" void kernel_launch(void* const* d_in, const int* in_sizes, int n_in,
                              void* d_out, int out_size)
{
    (void)in_sizes; (void)n_in; (void)out_size;
    const float* x       = (const float*)d_in[0];
    const float* cosT    = (const float*)d_in[2];
    const float* sinT    = (const float*)d_in[3];
    const float* wq      = (const float*)d_in[4];
    const float* wk      = (const float*)d_in[5];
    const float* wv      = (const float*)d_in[6];
    const float* wo      = (const float*)d_in[7];
    const float* gate    = (const float*)d_in[8];
    const float* adapter = (const float*)d_in[9];
    float* out = (float*)d_out;

    float *qp, *kp;
    __half *ahp, *alp, *wqh, *wkh, *wvh, *woh;
    __half *qhp, *qlp, *khp, *klp, *vhp;
    cudaGetSymbolAddress((void**)&qp,    g_q);
    cudaGetSymbolAddress((void**)&kp,    g_k);
    cudaGetSymbolAddress((void**)&ahp,  g_ah);  cudaGetSymbolAddress((void**)&alp,  g_al);
    cudaGetSymbolAddress((void**)&wqh,  g_wqh);
    cudaGetSymbolAddress((void**)&wkh,  g_wkh);
    cudaGetSymbolAddress((void**)&wvh,  g_wvh);
    cudaGetSymbolAddress((void**)&woh,  g_woh);
    cudaGetSymbolAddress((void**)&qhp,  g_qh);  cudaGetSymbolAddress((void**)&qlp,  g_ql);
    cudaGetSymbolAddress((void**)&khp,  g_kh);  cudaGetSymbolAddress((void**)&klp,  g_kl);
    cudaGetSymbolAddress((void**)&vhp,  g_vh);

    cudaFuncSetAttribute(gemm_h2f, cudaFuncAttributeMaxDynamicSharedMemorySize, GEMM2_SMEM);
    cudaFuncSetAttribute(gemm_h2h, cudaFuncAttributeMaxDynamicSharedMemorySize, GEMM2_SMEM);
    cudaFuncSetAttribute(flash_h, cudaFuncAttributeMaxDynamicSharedMemorySize, FLASH_SMEM);

    const int nXW = Mtok*Dd;
    const int cgrid = nXW/4/256;

    conv_split<<<cgrid, 256>>>(x,  ahp, alp, nXW);
    conv_hi<<<cgrid, 256>>>(wq, wqh, Dd*Dd);
    conv_hi<<<cgrid, 256>>>(wk, wkh, Dd*Dd);
    conv_hi<<<cgrid, 256>>>(wv, wvh, Dd*Dd);
    conv_hi<<<cgrid, 256>>>(wo, woh, Dd*Dd);

    dim3 gbig(Dd/BN, Mtok/BM);
    gemm_h2f<<<gbig, 256, GEMM2_SMEM>>>(ahp, alp, wqh, qp, Mtok, Dd, Dd);
    gemm_h2f<<<gbig, 256, GEMM2_SMEM>>>(ahp, alp, wkh, kp, Mtok, Dd, Dd);
    gemm_h2h<<<gbig, 256, GEMM2_SMEM>>>(ahp, alp, wvh, vhp, Mtok, Dd, Dd);

    gemm_skinny<<<dim3(Dd/128, KSPL, 2), 128>>>(adapter, wk, wv);
    skinny_reduce<<<(20*4096 + 255)/256, 256>>>();

    int npairs = Bb*Ss*Hh*HALFh;
    rope_split<<<npairs/256, 256>>>(qp, qhp, qlp, cosT, sinT);
    rope_split<<<npairs/256, 256>>>(kp, khp, klp, cosT, sinT);

    flash_h<<<dim3(Ss/FQ, Bb*Hh), 256, FLASH_SMEM>>>();
    adapter_kernel<<<dim3(Ss/4, Bb*Hh), 128>>>(gate);

    gemm_h2f<<<gbig, 256, GEMM2_SMEM>>>(ahp, alp, woh, out, Mtok, Dd, Dd);
}

// round 15
// speedup vs baseline: 1.4413x; 1.0080x over previous
#include <cuda_runtime.h>
#include <cuda_fp16.h>
#include <math.h>
#include <stdint.h>

#define Bb 2
#define Ss 2048
#define Dd 4096
#define Hh 32
#define HDh 128
#define HALFh 64
#define ALa 10
#define Mtok (Bb*Ss)

// ---- fp16 GEMM common ----
#define BM 128
#define BN 128
#define BKh 64                       // halves per K-chunk = 128B row
#define HROWB 144                    // smem row bytes (128 data + 16 pad)
#define OPB (128*HROWB)              // one operand = 18432 B

// 2-term: Ah, Al, Bh; 4 stages
#define STAGE2_B (3*OPB)
#define NST2 4
#define GEMM2_SMEM (NST2*STAGE2_B)   // 221184 B

// ---- flash config: FQ=64, 128 threads, single-buffered KV, 2 CTAs/SM ----
#define FQ 64
#define FKV 64
#define FROWB 272                    // 128 halves + 8 pad
#define QHOFF 0
#define QLOFF (64*FROWB)             // 17408
#define KV0 (2*64*FROWB)             // 34816
#define KLO (64*FROWB)
#define VHO (2*64*FROWB)
#define FLASH_SMEM (KV0 + 3*64*FROWB)   // 87040 B

#define KSPL 8

// ---------------- scratch (static device globals) ----------------
__device__ float g_q[Mtok*Dd];
__device__ float g_k[Mtok*Dd];
__device__ float g_attn[Mtok*Dd];
__device__ float g_ak[Bb*ALa*Dd];
__device__ float g_av[Bb*ALa*Dd];
__device__ float g_pk[KSPL*Bb*ALa*Dd];
__device__ float g_pv[KSPL*Bb*ALa*Dd];

__device__ __half g_ah[Mtok*Dd];   // x split; later holds attn split
__device__ __half g_al[Mtok*Dd];
__device__ __half g_wqh[Dd*Dd];
__device__ __half g_wkh[Dd*Dd];
__device__ __half g_wvh[Dd*Dd];
__device__ __half g_woh[Dd*Dd];
__device__ __half g_qh[Mtok*Dd], g_ql[Mtok*Dd];
__device__ __half g_kh[Mtok*Dd], g_kl[Mtok*Dd];
__device__ __half g_vh[Mtok*Dd];

// ---------------- helpers ----------------
__device__ __forceinline__ uint32_t s2u(const void* p){
    uint32_t r;
    asm("{ .reg .u64 t; cvta.to.shared.u64 t, %1; cvt.u32.u64 %0, t; }" : "=r"(r) : "l"(p));
    return r;
}

__device__ __forceinline__ void ldsm_x4(uint32_t* r, uint32_t addr){
    asm volatile("ldmatrix.sync.aligned.m8n8.x4.shared.b16 {%0,%1,%2,%3}, [%4];"
                 : "=r"(r[0]), "=r"(r[1]), "=r"(r[2]), "=r"(r[3]) : "r"(addr));
}
__device__ __forceinline__ void ldsm_x4t(uint32_t* r, uint32_t addr){
    asm volatile("ldmatrix.sync.aligned.m8n8.x4.trans.shared.b16 {%0,%1,%2,%3}, [%4];"
                 : "=r"(r[0]), "=r"(r[1]), "=r"(r[2]), "=r"(r[3]) : "r"(addr));
}

__device__ __forceinline__ void mma_h(float* d, const uint32_t* a, uint32_t b0, uint32_t b1){
    asm volatile(
        "mma.sync.aligned.m16n8k16.row.col.f32.f16.f16.f32 "
        "{%0,%1,%2,%3}, {%4,%5,%6,%7}, {%8,%9}, {%0,%1,%2,%3};"
        : "+f"(d[0]), "+f"(d[1]), "+f"(d[2]), "+f"(d[3])
        : "r"(a[0]), "r"(a[1]), "r"(a[2]), "r"(a[3]), "r"(b0), "r"(b1));
}

__device__ __forceinline__ uint32_t packh2(float lo, float hi){
    uint32_t r;
    asm("cvt.rn.f16x2.f32 %0, %1, %2;" : "=r"(r) : "f"(hi), "f"(lo));
    return r;
}

__device__ __forceinline__ void split_pack(float f0, float f1, uint32_t& hi, uint32_t& lo){
    __half h0 = __float2half_rn(f0), h1 = __float2half_rn(f1);
    __half2 hh = __halves2half2(h0, h1);
    hi = *reinterpret_cast<uint32_t*>(&hh);
    lo = packh2(f0 - __half2float(h0), f1 - __half2float(h1));
}

// epilogue functors
struct OutF32 {
    float* C; int N;
    __device__ __forceinline__ void operator()(int row, int col, float v0, float v1) const {
        *(float2*)&C[(size_t)row * N + col] = make_float2(v0, v1);
    }
};
struct OutF16 {
    __half* C; int N;
    __device__ __forceinline__ void operator()(int row, int col, float v0, float v1) const {
        *(__half2*)&C[(size_t)row * N + col] =
            __halves2half2(__float2half_rn(v0), __float2half_rn(v1));
    }
};

// ---------------- conversions ----------------
__global__ void conv_split(const float* __restrict__ s, __half* __restrict__ hi,
                           __half* __restrict__ lo, int n)
{
    int i = (blockIdx.x*256 + threadIdx.x) * 4;
    if (i >= n) return;
    float4 v = *(const float4*)(s + i);
    __half h0 = __float2half_rn(v.x), h1 = __float2half_rn(v.y);
    __half h2 = __float2half_rn(v.z), h3 = __float2half_rn(v.w);
    *(__half2*)(hi + i)     = __halves2half2(h0, h1);
    *(__half2*)(hi + i + 2) = __halves2half2(h2, h3);
    *(__half2*)(lo + i)     = __halves2half2(__float2half_rn(v.x - __half2float(h0)),
                                             __float2half_rn(v.y - __half2float(h1)));
    *(__half2*)(lo + i + 2) = __halves2half2(__float2half_rn(v.z - __half2float(h2)),
                                             __float2half_rn(v.w - __half2float(h3)));
}

__global__ void conv_hi(const float* __restrict__ s, __half* __restrict__ hi, int n)
{
    int i = (blockIdx.x*256 + threadIdx.x) * 4;
    if (i >= n) return;
    float4 v = *(const float4*)(s + i);
    *(__half2*)(hi + i)     = __halves2half2(__float2half_rn(v.x), __float2half_rn(v.y));
    *(__half2*)(hi + i + 2) = __halves2half2(__float2half_rn(v.z), __float2half_rn(v.w));
}

// ---------------- 2-term fp16 NT GEMM core (templated epilogue) ----------------
template<typename OUTW>
__device__ __forceinline__ void gemm_h2_body(
    const __half* __restrict__ Ah, const __half* __restrict__ Al,
    const __half* __restrict__ Bh, OUTW outw, int M, int N, int K, char* smg)
{
    const uint32_t sbase = s2u(smg);
    const int t = threadIdx.x;
    const int m0 = blockIdx.y * BM;
    const int n0 = blockIdx.x * BN;
    const int NCH = K / BKh;

    const int lane = t & 31;
    const int wid  = t >> 5;
    const int wm   = wid & 3;
    const int wn   = wid >> 2;

    float d[2][8][4];
    #pragma unroll
    for (int mt = 0; mt < 2; mt++)
        #pragma unroll
        for (int nt = 0; nt < 8; nt++)
            #pragma unroll
            for (int c = 0; c < 4; c++) d[mt][nt][c] = 0.f;

    const uint32_t aRow = (uint32_t)(wm*32 + (lane & 7) + ((lane >> 3) & 1)*8);
    const uint32_t aKof = (uint32_t)(((lane >> 4) & 1) << 4);
    const uint32_t bRow = (uint32_t)(wn*64 + (lane & 7) + ((lane >> 4) & 1)*8);
    const uint32_t bKof = (uint32_t)(((lane >> 3) & 1) << 4);

    const int ldr = t >> 3;
    const int ldq = t & 7;

    auto prefetch = [&](int chunk, int stage){
        const int k0 = chunk * BKh;
        const uint32_t st = sbase + (uint32_t)stage * STAGE2_B;
        #pragma unroll
        for (int i = 0; i < 4; i++) {
            int row = ldr + i*32;
            int ar = m0 + row; if (ar > M-1) ar = M-1;
            size_t goa = (size_t)ar * K + k0 + ldq*8;
            size_t gob = (size_t)(n0 + row) * K + k0 + ldq*8;
            uint32_t so = (uint32_t)row * HROWB + (uint32_t)ldq * 16u;
            asm volatile("cp.async.cg.shared.global [%0], [%1], 16;" :: "r"(st + 0*OPB + so), "l"(Ah + goa));
            asm volatile("cp.async.cg.shared.global [%0], [%1], 16;" :: "r"(st + 1*OPB + so), "l"(Al + goa));
            asm volatile("cp.async.cg.shared.global [%0], [%1], 16;" :: "r"(st + 2*OPB + so), "l"(Bh + gob));
        }
        asm volatile("cp.async.commit_group;" ::: "memory");
    };

    #pragma unroll
    for (int p = 0; p < NST2; p++) prefetch(p, p);

    int stage = 0;
    for (int n = 0; n < NCH; n++) {
        asm volatile("cp.async.wait_group %0;" :: "n"(NST2-1) : "memory");
        __syncthreads();

        const uint32_t st = sbase + (uint32_t)stage * STAGE2_B;
        const uint32_t sAh = st, sAl = st + OPB, sBh = st + 2*OPB;

        #pragma unroll
        for (int ks = 0; ks < 4; ks++) {
            const uint32_t kb = (uint32_t)ks * 32u;
            uint32_t ah[2][4], al[2][4];
            #pragma unroll
            for (int mt = 0; mt < 2; mt++) {
                ldsm_x4(ah[mt], sAh + (aRow + mt*16u)*HROWB + aKof + kb);
                ldsm_x4(al[mt], sAl + (aRow + mt*16u)*HROWB + aKof + kb);
            }
            #pragma unroll
            for (int np = 0; np < 4; np++) {
                uint32_t bh[4];
                ldsm_x4(bh, sBh + (bRow + np*16u)*HROWB + bKof + kb);
                #pragma unroll
                for (int mt = 0; mt < 2; mt++) {
                    mma_h(d[mt][2*np],   ah[mt], bh[0], bh[1]);
                    mma_h(d[mt][2*np],   al[mt], bh[0], bh[1]);
                    mma_h(d[mt][2*np+1], ah[mt], bh[2], bh[3]);
                    mma_h(d[mt][2*np+1], al[mt], bh[2], bh[3]);
                }
            }
        }
        __syncthreads();

        int pn = n + NST2; if (pn >= NCH) pn = 0;
        prefetch(pn, stage);
        stage++; if (stage == NST2) stage = 0;
    }

    const int g  = lane >> 2;
    const int tq = lane & 3;
    #pragma unroll
    for (int mt = 0; mt < 2; mt++) {
        int row = m0 + wm*32 + mt*16 + g;
        #pragma unroll
        for (int nt = 0; nt < 8; nt++) {
            int col = n0 + wn*64 + nt*8 + 2*tq;
            if (row < M)     outw(row,     col, d[mt][nt][0], d[mt][nt][1]);
            if (row + 8 < M) outw(row + 8, col, d[mt][nt][2], d[mt][nt][3]);
        }
    }
}

__global__ __launch_bounds__(256) void gemm_h2f(
    const __half* __restrict__ Ah, const __half* __restrict__ Al,
    const __half* __restrict__ Bh, float* __restrict__ C, int M, int N, int K)
{
    extern __shared__ char smg[];
    OutF32 o{C, N};
    gemm_h2_body(Ah, Al, Bh, o, M, N, K, smg);
}

__global__ __launch_bounds__(256) void gemm_h2h(
    const __half* __restrict__ Ah, const __half* __restrict__ Al,
    const __half* __restrict__ Bh, __half* __restrict__ Ch, int M, int N, int K)
{
    extern __shared__ char smg[];
    OutF16 o{Ch, N};
    gemm_h2_body(Ah, Al, Bh, o, M, N, K, smg);
}

// ---------------- skinny adapter GEMM (M=20, fp32, split-K) ----------------
__global__ __launch_bounds__(128) void gemm_skinny(
    const float* __restrict__ Aad, const float* __restrict__ wk, const float* __restrict__ wv)
{
    __shared__ float As[20][33];
    __shared__ float Bs[128][33];
    const int t = threadIdx.x;
    const int n0 = blockIdx.x * 128;
    const int kz = blockIdx.y;
    const float* W = blockIdx.z ? wv : wk;
    float* P = (blockIdx.z ? g_pv : g_pk) + (size_t)kz * (20*4096);

    float acc[20];
    #pragma unroll
    for (int m = 0; m < 20; m++) acc[m] = 0.f;

    for (int k0 = kz*512; k0 < kz*512 + 512; k0 += 32) {
        for (int i = t; i < 640; i += 128) {
            int r = i >> 5, c = i & 31;
            As[r][c] = Aad[(size_t)r*4096 + k0 + c];
        }
        #pragma unroll
        for (int i = 0; i < 8; i++) {
            int idx = t + i*128;
            int r = idx >> 3, cq = idx & 7;
            float4 v = *(const float4*)&W[(size_t)(n0 + r)*4096 + k0 + cq*4];
            Bs[r][cq*4+0] = v.x; Bs[r][cq*4+1] = v.y;
            Bs[r][cq*4+2] = v.z; Bs[r][cq*4+3] = v.w;
        }
        __syncthreads();
        #pragma unroll
        for (int k = 0; k < 32; k++) {
            float bv = Bs[t][k];
            #pragma unroll
            for (int m = 0; m < 20; m++) acc[m] += As[m][k] * bv;
        }
        __syncthreads();
    }
    #pragma unroll
    for (int m = 0; m < 20; m++) P[(size_t)m*4096 + n0 + t] = acc[m];
}

__global__ void skinny_reduce()
{
    int i = blockIdx.x*256 + threadIdx.x;
    if (i >= 20*4096) return;
    float sk = 0.f, sv = 0.f;
    #pragma unroll
    for (int z = 0; z < KSPL; z++) {
        sk += g_pk[(size_t)z*(20*4096) + i];
        sv += g_pv[(size_t)z*(20*4096) + i];
    }
    g_ak[i] = sk;
    g_av[i] = sv;
}

// ---------------- RoPE (fp32 in place) + split to fp16 hi/lo ----------------
__global__ void rope_split(float* __restrict__ T, __half* __restrict__ Th, __half* __restrict__ Tl,
                           const float* __restrict__ cosT, const float* __restrict__ sinT)
{
    int idx = blockIdx.x * blockDim.x + threadIdx.x;
    if (idx >= Bb*Ss*Hh*HALFh) return;
    int p = idx & (HALFh - 1);
    int s = (idx >> 11) & (Ss - 1);
    float c  = cosT[s*HALFh + p];
    float sn = sinT[s*HALFh + p];
    float2 v = *(float2*)&T[2*(size_t)idx];
    float2 r;
    r.x = v.x * c - v.y * sn;
    r.y = v.x * sn + v.y * c;
    *(float2*)&T[2*(size_t)idx] = r;
    __half h0 = __float2half_rn(r.x), h1 = __float2half_rn(r.y);
    *(__half2*)(Th + 2*(size_t)idx) = __halves2half2(h0, h1);
    *(__half2*)(Tl + 2*(size_t)idx) = __halves2half2(__float2half_rn(r.x - __half2float(h0)),
                                                     __float2half_rn(r.y - __half2float(h1)));
}

// ---------------- flash attention: FQ=64, 128 threads, 2 CTAs/SM ----------------
__global__ __launch_bounds__(128, 2) void flash_h()
{
    extern __shared__ char fsm[];
    const uint32_t sb = s2u(fsm);
    const int t = threadIdx.x, lane = t & 31, w = t >> 5;   // w in 0..3
    const int bh = blockIdx.y, b = bh >> 5, h = bh & 31;
    const int q0 = (int)(gridDim.x - 1 - blockIdx.x) * FQ;
    const size_t headbase = (size_t)b * Ss * Dd + (size_t)h * HDh;
    const int g = lane >> 2, tq = lane & 3;
    const float rscale = 0.08838834764831844f;
    const float NEGINF = __int_as_float(0xff800000);
    const int niter = (q0 + FQ) / FKV;

    // prologue: Q hi/lo (64 rows x 16 chunks each -> 8 iters/thread per operand)
    {
        const __half* qh = g_qh + headbase + (size_t)q0 * Dd;
        const __half* ql = g_ql + headbase + (size_t)q0 * Dd;
        #pragma unroll
        for (int i = 0; i < 8; i++) {
            int idx = t + i*128;
            int r = idx >> 4, cq = idx & 15;
            uint32_t so = (uint32_t)(r*FROWB + cq*16);
            size_t go = (size_t)r*Dd + cq*8;
            asm volatile("cp.async.cg.shared.global [%0], [%1], 16;" :: "r"(sb + QHOFF + so), "l"(qh + go));
            asm volatile("cp.async.cg.shared.global [%0], [%1], 16;" :: "r"(sb + QLOFF + so), "l"(ql + go));
        }
        asm volatile("cp.async.commit_group;" ::: "memory");
    }

    const uint32_t aRow = (uint32_t)(w*16 + (lane & 7) + ((lane >> 3) & 1)*8);
    const uint32_t aKof = (uint32_t)(((lane >> 4) & 1) << 4);
    const uint32_t bRow = (uint32_t)((lane & 7) + ((lane >> 4) & 1)*8);
    const uint32_t bKof = (uint32_t)(((lane >> 3) & 1) << 4);
    const uint32_t vRow = (uint32_t)((lane & 7) + ((lane >> 3) & 1)*8);
    const uint32_t vDof = (uint32_t)(((lane >> 4) & 1) << 4);

    float o[16][4];
    #pragma unroll
    for (int nt = 0; nt < 16; nt++) { o[nt][0]=o[nt][1]=o[nt][2]=o[nt][3]=0.f; }
    float m0r = -1e30f, m1r = -1e30f, l0r = 0.f, l1r = 0.f;

    const int ig0 = q0 + w*16 + g;
    const int ig1 = ig0 + 8;

    const uint32_t kv = sb + KV0;

    for (int n = 0; n < niter; n++) {
        const int j0 = n * FKV;

        __syncthreads();   // prior iteration's reads of KV done before overwrite
        {
            const __half* kh = g_kh + headbase + (size_t)j0 * Dd;
            const __half* kl = g_kl + headbase + (size_t)j0 * Dd;
            const __half* vh = g_vh + headbase + (size_t)j0 * Dd;
            #pragma unroll
            for (int i = 0; i < 8; i++) {
                int idx = t + i*128;
                int r = idx >> 4, cq = idx & 15;
                uint32_t so = (uint32_t)(r*FROWB + cq*16);
                size_t go = (size_t)r*Dd + cq*8;
                asm volatile("cp.async.cg.shared.global [%0], [%1], 16;" :: "r"(kv + so),       "l"(kh + go));
                asm volatile("cp.async.cg.shared.global [%0], [%1], 16;" :: "r"(kv + KLO + so), "l"(kl + go));
                asm volatile("cp.async.cg.shared.global [%0], [%1], 16;" :: "r"(kv + VHO + so), "l"(vh + go));
            }
            asm volatile("cp.async.commit_group;" ::: "memory");
        }
        asm volatile("cp.async.wait_group 0;" ::: "memory");
        __syncthreads();

        // ---- S = Q K^T : qh*kh + qh*kl + ql*kh ----
        float s[8][4];
        #pragma unroll
        for (int nt = 0; nt < 8; nt++) { s[nt][0]=s[nt][1]=s[nt][2]=s[nt][3]=0.f; }
        #pragma unroll
        for (int ks = 0; ks < 8; ks++) {
            const uint32_t kb = (uint32_t)ks * 32u;
            uint32_t ah[4], al_[4];
            ldsm_x4(ah,  sb + QHOFF + aRow*FROWB + aKof + kb);
            ldsm_x4(al_, sb + QLOFF + aRow*FROWB + aKof + kb);
            #pragma unroll
            for (int np = 0; np < 4; np++) {
                uint32_t bhf[4], blf[4];
                ldsm_x4(bhf, kv + (bRow + np*16u)*FROWB + bKof + kb);
                ldsm_x4(blf, kv + KLO + (bRow + np*16u)*FROWB + bKof + kb);
                mma_h(s[2*np],   ah,  bhf[0], bhf[1]);
                mma_h(s[2*np],   ah,  blf[0], blf[1]);
                mma_h(s[2*np],   al_, bhf[0], bhf[1]);
                mma_h(s[2*np+1], ah,  bhf[2], bhf[3]);
                mma_h(s[2*np+1], ah,  blf[2], blf[3]);
                mma_h(s[2*np+1], al_, bhf[2], bhf[3]);
            }
        }

        float mx0 = -1e30f, mx1 = -1e30f;
        #pragma unroll
        for (int nt = 0; nt < 8; nt++) {
            int jg = j0 + nt*8 + 2*tq;
            s[nt][0] = (jg   > ig0) ? NEGINF : s[nt][0]*rscale;
            s[nt][1] = (jg+1 > ig0) ? NEGINF : s[nt][1]*rscale;
            s[nt][2] = (jg   > ig1) ? NEGINF : s[nt][2]*rscale;
            s[nt][3] = (jg+1 > ig1) ? NEGINF : s[nt][3]*rscale;
            mx0 = fmaxf(mx0, fmaxf(s[nt][0], s[nt][1]));
            mx1 = fmaxf(mx1, fmaxf(s[nt][2], s[nt][3]));
        }
        mx0 = fmaxf(mx0, __shfl_xor_sync(0xffffffffu, mx0, 1));
        mx0 = fmaxf(mx0, __shfl_xor_sync(0xffffffffu, mx0, 2));
        mx1 = fmaxf(mx1, __shfl_xor_sync(0xffffffffu, mx1, 1));
        mx1 = fmaxf(mx1, __shfl_xor_sync(0xffffffffu, mx1, 2));
        float mn0 = fmaxf(m0r, mx0), mn1 = fmaxf(m1r, mx1);
        float co0 = __expf(m0r - mn0), co1 = __expf(m1r - mn1);
        float sum0 = 0.f, sum1 = 0.f;
        #pragma unroll
        for (int nt = 0; nt < 8; nt++) {
            s[nt][0] = __expf(s[nt][0] - mn0);
            s[nt][1] = __expf(s[nt][1] - mn0);
            s[nt][2] = __expf(s[nt][2] - mn1);
            s[nt][3] = __expf(s[nt][3] - mn1);
            sum0 += s[nt][0] + s[nt][1];
            sum1 += s[nt][2] + s[nt][3];
        }
        sum0 += __shfl_xor_sync(0xffffffffu, sum0, 1);
        sum0 += __shfl_xor_sync(0xffffffffu, sum0, 2);
        sum1 += __shfl_xor_sync(0xffffffffu, sum1, 1);
        sum1 += __shfl_xor_sync(0xffffffffu, sum1, 2);
        l0r = l0r * co0 + sum0;  m0r = mn0;
        l1r = l1r * co1 + sum1;  m1r = mn1;

        #pragma unroll
        for (int nt = 0; nt < 16; nt++) {
            o[nt][0] *= co0; o[nt][1] *= co0;
            o[nt][2] *= co1; o[nt][3] *= co1;
        }

        // ---- O += P Vh : ph*Vh + pl*Vh ----
        #pragma unroll
        for (int ks = 0; ks < 4; ks++) {
            uint32_t ph[4], pl[4];
            split_pack(s[2*ks][0],   s[2*ks][1],   ph[0], pl[0]);
            split_pack(s[2*ks][2],   s[2*ks][3],   ph[1], pl[1]);
            split_pack(s[2*ks+1][0], s[2*ks+1][1], ph[2], pl[2]);
            split_pack(s[2*ks+1][2], s[2*ks+1][3], ph[3], pl[3]);
            const uint32_t krow = (uint32_t)(ks*16) + vRow;
            #pragma unroll
            for (int np = 0; np < 8; np++) {
                uint32_t vhf[4];
                ldsm_x4t(vhf, kv + VHO + krow*FROWB + (uint32_t)(np*32) + vDof);
                mma_h(o[2*np],   ph, vhf[0], vhf[1]);
                mma_h(o[2*np],   pl, vhf[0], vhf[1]);
                mma_h(o[2*np+1], ph, vhf[2], vhf[3]);
                mma_h(o[2*np+1], pl, vhf[2], vhf[3]);
            }
        }
    }

    float inv0 = 1.f / l0r, inv1 = 1.f / l1r;
    float* Og = g_attn + headbase + (size_t)(q0 + w*16) * Dd;
    #pragma unroll
    for (int nt = 0; nt < 16; nt++) {
        *(float2*)&Og[(size_t)g*Dd     + nt*8 + 2*tq] = make_float2(o[nt][0]*inv0, o[nt][1]*inv0);
        *(float2*)&Og[(size_t)(g+8)*Dd + nt*8 + 2*tq] = make_float2(o[nt][2]*inv1, o[nt][3]*inv1);
    }
}

// ---------------- adapter attention (+ writes fp16 split of final attn) ----------------
__global__ __launch_bounds__(128) void adapter_kernel(const float* __restrict__ gate)
{
    __shared__ __align__(16) float ak[ALa][HDh];
    __shared__ __align__(16) float av[ALa][HDh];
    const int t = threadIdx.x;
    const int bh = blockIdx.y;
    const int b = bh >> 5, h = bh & 31;
    const int s0 = blockIdx.x * 4;

    #pragma unroll
    for (int r = 0; r < ALa; r++) {
        int idx = t + r*128;
        int j = idx >> 7, d = idx & 127;
        ak[j][d] = g_ak[(size_t)(b*ALa + j) * Dd + h*HDh + d];
        av[j][d] = g_av[(size_t)(b*ALa + j) * Dd + h*HDh + d];
    }
    __syncthreads();

    const int w = t >> 5, lane = t & 31;
    const int s = s0 + w;
    const size_t base = (size_t)(b*Ss + s) * Dd + h*HDh;
    const float rscale = 0.08838834764831844f;

    float4 qv = *(const float4*)&g_q[base + lane*4];
    float sc[ALa];
    #pragma unroll
    for (int j = 0; j < ALa; j++) {
        float d0 = qv.x*ak[j][lane*4+0] + qv.y*ak[j][lane*4+1]
                 + qv.z*ak[j][lane*4+2] + qv.w*ak[j][lane*4+3];
        #pragma unroll
        for (int off = 16; off >= 1; off >>= 1)
            d0 += __shfl_xor_sync(0xffffffffu, d0, off);
        sc[j] = d0 * rscale;
    }
    float mx = sc[0];
    #pragma unroll
    for (int j = 1; j < ALa; j++) mx = fmaxf(mx, sc[j]);
    float sum = 0.f;
    #pragma unroll
    for (int j = 0; j < ALa; j++) { sc[j] = __expf(sc[j] - mx); sum += sc[j]; }
    float inv = 1.f / sum;
    float gg = tanhf(gate[h]);

    float acc[4] = {0.f, 0.f, 0.f, 0.f};
    #pragma unroll
    for (int j = 0; j < ALa; j++) {
        float p = sc[j] * inv;
        acc[0] += p * av[j][lane*4+0];
        acc[1] += p * av[j][lane*4+1];
        acc[2] += p * av[j][lane*4+2];
        acc[3] += p * av[j][lane*4+3];
    }
    float4 ov = *(float4*)&g_attn[base + lane*4];
    ov.x += gg*acc[0]; ov.y += gg*acc[1]; ov.z += gg*acc[2]; ov.w += gg*acc[3];
    *(float4*)&g_attn[base + lane*4] = ov;

    __half h0 = __float2half_rn(ov.x), h1 = __float2half_rn(ov.y);
    __half h2 = __float2half_rn(ov.z), h3 = __float2half_rn(ov.w);
    *(__half2*)(g_ah + base + lane*4)     = __halves2half2(h0, h1);
    *(__half2*)(g_ah + base + lane*4 + 2) = __halves2half2(h2, h3);
    *(__half2*)(g_al + base + lane*4)     = __halves2half2(__float2half_rn(ov.x - __half2float(h0)),
                                                           __float2half_rn(ov.y - __half2float(h1)));
    *(__half2*)(g_al + base + lane*4 + 2) = __halves2half2(__float2half_rn(ov.z - __half2float(h2)),
                                                           __float2half_rn(ov.w - __half2float(h3)));
}

// ---------------- host ----------------
extern "C" void kernel_launch(void* const* d_in, const int* in_sizes, int n_in,
                              void* d_out, int out_size)
{
    (void)in_sizes; (void)n_in; (void)out_size;
    const float* x       = (const float*)d_in[0];
    const float* cosT    = (const float*)d_in[2];
    const float* sinT    = (const float*)d_in[3];
    const float* wq      = (const float*)d_in[4];
    const float* wk      = (const float*)d_in[5];
    const float* wv      = (const float*)d_in[6];
    const float* wo      = (const float*)d_in[7];
    const float* gate    = (const float*)d_in[8];
    const float* adapter = (const float*)d_in[9];
    float* out = (float*)d_out;

    float *qp, *kp;
    __half *ahp, *alp, *wqh, *wkh, *wvh, *woh;
    __half *qhp, *qlp, *khp, *klp, *vhp;
    cudaGetSymbolAddress((void**)&qp,    g_q);
    cudaGetSymbolAddress((void**)&kp,    g_k);
    cudaGetSymbolAddress((void**)&ahp,  g_ah);  cudaGetSymbolAddress((void**)&alp,  g_al);
    cudaGetSymbolAddress((void**)&wqh,  g_wqh);
    cudaGetSymbolAddress((void**)&wkh,  g_wkh);
    cudaGetSymbolAddress((void**)&wvh,  g_wvh);
    cudaGetSymbolAddress((void**)&woh,  g_woh);
    cudaGetSymbolAddress((void**)&qhp,  g_qh);  cudaGetSymbolAddress((void**)&qlp,  g_ql);
    cudaGetSymbolAddress((void**)&khp,  g_kh);  cudaGetSymbolAddress((void**)&klp,  g_kl);
    cudaGetSymbolAddress((void**)&vhp,  g_vh);

    cudaFuncSetAttribute(gemm_h2f, cudaFuncAttributeMaxDynamicSharedMemorySize, GEMM2_SMEM);
    cudaFuncSetAttribute(gemm_h2h, cudaFuncAttributeMaxDynamicSharedMemorySize, GEMM2_SMEM);
    cudaFuncSetAttribute(flash_h, cudaFuncAttributeMaxDynamicSharedMemorySize, FLASH_SMEM);

    const int nXW = Mtok*Dd;
    const int cgrid = nXW/4/256;

    conv_split<<<cgrid, 256>>>(x,  ahp, alp, nXW);
    conv_hi<<<cgrid, 256>>>(wq, wqh, Dd*Dd);
    conv_hi<<<cgrid, 256>>>(wk, wkh, Dd*Dd);
    conv_hi<<<cgrid, 256>>>(wv, wvh, Dd*Dd);
    conv_hi<<<cgrid, 256>>>(wo, woh, Dd*Dd);

    dim3 gbig(Dd/BN, Mtok/BM);
    gemm_h2f<<<gbig, 256, GEMM2_SMEM>>>(ahp, alp, wqh, qp, Mtok, Dd, Dd);
    gemm_h2f<<<gbig, 256, GEMM2_SMEM>>>(ahp, alp, wkh, kp, Mtok, Dd, Dd);
    gemm_h2h<<<gbig, 256, GEMM2_SMEM>>>(ahp, alp, wvh, vhp, Mtok, Dd, Dd);

    gemm_skinny<<<dim3(Dd/128, KSPL, 2), 128>>>(adapter, wk, wv);
    skinny_reduce<<<(20*4096 + 255)/256, 256>>>();

    int npairs = Bb*Ss*Hh*HALFh;
    rope_split<<<npairs/256, 256>>>(qp, qhp, qlp, cosT, sinT);
    rope_split<<<npairs/256, 256>>>(kp, khp, klp, cosT, sinT);

    flash_h<<<dim3(Ss/FQ, Bb*Hh), 128, FLASH_SMEM>>>();
    adapter_kernel<<<dim3(Ss/4, Bb*Hh), 128>>>(gate);

    gemm_h2f<<<gbig, 256, GEMM2_SMEM>>>(ahp, alp, woh, out, Mtok, Dd, Dd);
}

// round 16
// speedup vs baseline: 1.4856x; 1.0307x over previous
#include <cuda_runtime.h>
#include <cuda_fp16.h>
#include <math.h>
#include <stdint.h>

#define Bb 2
#define Ss 2048
#define Dd 4096
#define Hh 32
#define HDh 128
#define HALFh 64
#define ALa 10
#define Mtok (Bb*Ss)

// ---- fp16 GEMM common ----
#define BM 128
#define BN 128
#define BKh 64                       // halves per K-chunk = 128B row
#define HROWB 144                    // smem row bytes (128 data + 16 pad)
#define OPB (128*HROWB)              // one operand = 18432 B

// 2-term: Ah, Al, Bh; 4 stages
#define STAGE2_B (3*OPB)
#define NST2 4
#define GEMM2_SMEM (NST2*STAGE2_B)   // 221184 B

// ---- flash config: FQ=64, FKV=128, 128 threads, 2 CTAs/SM ----
#define FQ 64
#define FKV 128
#define FROWB 272                    // 128 halves + 8 pad
#define QHOFF 0
#define QLOFF (64*FROWB)
#define KH0 (2*64*FROWB)
#define VH0 (KH0 + 128*FROWB)
#define FLASH_SMEM (VH0 + 128*FROWB)   // 104448 B

#define KSPL 8

// ---------------- scratch (static device globals) ----------------
__device__ float g_q[Mtok*Dd];
__device__ float g_k[Mtok*Dd];
__device__ float g_attn[Mtok*Dd];
__device__ float g_ak[Bb*ALa*Dd];
__device__ float g_av[Bb*ALa*Dd];
__device__ float g_pk[KSPL*Bb*ALa*Dd];
__device__ float g_pv[KSPL*Bb*ALa*Dd];

__device__ __half g_ah[Mtok*Dd];   // x split; later holds attn split
__device__ __half g_al[Mtok*Dd];
__device__ __half g_wqh[Dd*Dd];
__device__ __half g_wkh[Dd*Dd];
__device__ __half g_wvh[Dd*Dd];
__device__ __half g_woh[Dd*Dd];
__device__ __half g_qh[Mtok*Dd], g_ql[Mtok*Dd];
__device__ __half g_kh[Mtok*Dd];
__device__ __half g_vh[Mtok*Dd];

// ---------------- helpers ----------------
__device__ __forceinline__ uint32_t s2u(const void* p){
    uint32_t r;
    asm("{ .reg .u64 t; cvta.to.shared.u64 t, %1; cvt.u32.u64 %0, t; }" : "=r"(r) : "l"(p));
    return r;
}

__device__ __forceinline__ void ldsm_x4(uint32_t* r, uint32_t addr){
    asm volatile("ldmatrix.sync.aligned.m8n8.x4.shared.b16 {%0,%1,%2,%3}, [%4];"
                 : "=r"(r[0]), "=r"(r[1]), "=r"(r[2]), "=r"(r[3]) : "r"(addr));
}
__device__ __forceinline__ void ldsm_x4t(uint32_t* r, uint32_t addr){
    asm volatile("ldmatrix.sync.aligned.m8n8.x4.trans.shared.b16 {%0,%1,%2,%3}, [%4];"
                 : "=r"(r[0]), "=r"(r[1]), "=r"(r[2]), "=r"(r[3]) : "r"(addr));
}

__device__ __forceinline__ void mma_h(float* d, const uint32_t* a, uint32_t b0, uint32_t b1){
    asm volatile(
        "mma.sync.aligned.m16n8k16.row.col.f32.f16.f16.f32 "
        "{%0,%1,%2,%3}, {%4,%5,%6,%7}, {%8,%9}, {%0,%1,%2,%3};"
        : "+f"(d[0]), "+f"(d[1]), "+f"(d[2]), "+f"(d[3])
        : "r"(a[0]), "r"(a[1]), "r"(a[2]), "r"(a[3]), "r"(b0), "r"(b1));
}

__device__ __forceinline__ uint32_t packh2(float lo, float hi){
    uint32_t r;
    asm("cvt.rn.f16x2.f32 %0, %1, %2;" : "=r"(r) : "f"(hi), "f"(lo));
    return r;
}

__device__ __forceinline__ void split_pack(float f0, float f1, uint32_t& hi, uint32_t& lo){
    __half h0 = __float2half_rn(f0), h1 = __float2half_rn(f1);
    __half2 hh = __halves2half2(h0, h1);
    hi = *reinterpret_cast<uint32_t*>(&hh);
    lo = packh2(f0 - __half2float(h0), f1 - __half2float(h1));
}

// epilogue functors
struct OutF32 {
    float* C; int N;
    __device__ __forceinline__ void operator()(int row, int col, float v0, float v1) const {
        *(float2*)&C[(size_t)row * N + col] = make_float2(v0, v1);
    }
};
struct OutF16 {
    __half* C; int N;
    __device__ __forceinline__ void operator()(int row, int col, float v0, float v1) const {
        *(__half2*)&C[(size_t)row * N + col] =
            __halves2half2(__float2half_rn(v0), __float2half_rn(v1));
    }
};

// ---------------- conversions ----------------
__global__ void conv_split(const float* __restrict__ s, __half* __restrict__ hi,
                           __half* __restrict__ lo, int n)
{
    int i = (blockIdx.x*256 + threadIdx.x) * 4;
    if (i >= n) return;
    float4 v = *(const float4*)(s + i);
    __half h0 = __float2half_rn(v.x), h1 = __float2half_rn(v.y);
    __half h2 = __float2half_rn(v.z), h3 = __float2half_rn(v.w);
    *(__half2*)(hi + i)     = __halves2half2(h0, h1);
    *(__half2*)(hi + i + 2) = __halves2half2(h2, h3);
    *(__half2*)(lo + i)     = __halves2half2(__float2half_rn(v.x - __half2float(h0)),
                                             __float2half_rn(v.y - __half2float(h1)));
    *(__half2*)(lo + i + 2) = __halves2half2(__float2half_rn(v.z - __half2float(h2)),
                                             __float2half_rn(v.w - __half2float(h3)));
}

__global__ void conv_hi(const float* __restrict__ s, __half* __restrict__ hi, int n)
{
    int i = (blockIdx.x*256 + threadIdx.x) * 4;
    if (i >= n) return;
    float4 v = *(const float4*)(s + i);
    *(__half2*)(hi + i)     = __halves2half2(__float2half_rn(v.x), __float2half_rn(v.y));
    *(__half2*)(hi + i + 2) = __halves2half2(__float2half_rn(v.z), __float2half_rn(v.w));
}

// ---------------- 2-term fp16 NT GEMM core (templated epilogue) ----------------
template<typename OUTW>
__device__ __forceinline__ void gemm_h2_body(
    const __half* __restrict__ Ah, const __half* __restrict__ Al,
    const __half* __restrict__ Bh, OUTW outw, int M, int N, int K, char* smg)
{
    const uint32_t sbase = s2u(smg);
    const int t = threadIdx.x;
    const int m0 = blockIdx.y * BM;
    const int n0 = blockIdx.x * BN;
    const int NCH = K / BKh;

    const int lane = t & 31;
    const int wid  = t >> 5;
    const int wm   = wid & 3;
    const int wn   = wid >> 2;

    float d[2][8][4];
    #pragma unroll
    for (int mt = 0; mt < 2; mt++)
        #pragma unroll
        for (int nt = 0; nt < 8; nt++)
            #pragma unroll
            for (int c = 0; c < 4; c++) d[mt][nt][c] = 0.f;

    const uint32_t aRow = (uint32_t)(wm*32 + (lane & 7) + ((lane >> 3) & 1)*8);
    const uint32_t aKof = (uint32_t)(((lane >> 4) & 1) << 4);
    const uint32_t bRow = (uint32_t)(wn*64 + (lane & 7) + ((lane >> 4) & 1)*8);
    const uint32_t bKof = (uint32_t)(((lane >> 3) & 1) << 4);

    const int ldr = t >> 3;
    const int ldq = t & 7;

    auto prefetch = [&](int chunk, int stage){
        const int k0 = chunk * BKh;
        const uint32_t st = sbase + (uint32_t)stage * STAGE2_B;
        #pragma unroll
        for (int i = 0; i < 4; i++) {
            int row = ldr + i*32;
            int ar = m0 + row; if (ar > M-1) ar = M-1;
            size_t goa = (size_t)ar * K + k0 + ldq*8;
            size_t gob = (size_t)(n0 + row) * K + k0 + ldq*8;
            uint32_t so = (uint32_t)row * HROWB + (uint32_t)ldq * 16u;
            asm volatile("cp.async.cg.shared.global [%0], [%1], 16;" :: "r"(st + 0*OPB + so), "l"(Ah + goa));
            asm volatile("cp.async.cg.shared.global [%0], [%1], 16;" :: "r"(st + 1*OPB + so), "l"(Al + goa));
            asm volatile("cp.async.cg.shared.global [%0], [%1], 16;" :: "r"(st + 2*OPB + so), "l"(Bh + gob));
        }
        asm volatile("cp.async.commit_group;" ::: "memory");
    };

    #pragma unroll
    for (int p = 0; p < NST2; p++) prefetch(p, p);

    int stage = 0;
    for (int n = 0; n < NCH; n++) {
        asm volatile("cp.async.wait_group %0;" :: "n"(NST2-1) : "memory");
        __syncthreads();

        const uint32_t st = sbase + (uint32_t)stage * STAGE2_B;
        const uint32_t sAh = st, sAl = st + OPB, sBh = st + 2*OPB;

        #pragma unroll
        for (int ks = 0; ks < 4; ks++) {
            const uint32_t kb = (uint32_t)ks * 32u;
            uint32_t ah[2][4], al[2][4];
            #pragma unroll
            for (int mt = 0; mt < 2; mt++) {
                ldsm_x4(ah[mt], sAh + (aRow + mt*16u)*HROWB + aKof + kb);
                ldsm_x4(al[mt], sAl + (aRow + mt*16u)*HROWB + aKof + kb);
            }
            #pragma unroll
            for (int np = 0; np < 4; np++) {
                uint32_t bh[4];
                ldsm_x4(bh, sBh + (bRow + np*16u)*HROWB + bKof + kb);
                #pragma unroll
                for (int mt = 0; mt < 2; mt++) {
                    mma_h(d[mt][2*np],   ah[mt], bh[0], bh[1]);
                    mma_h(d[mt][2*np],   al[mt], bh[0], bh[1]);
                    mma_h(d[mt][2*np+1], ah[mt], bh[2], bh[3]);
                    mma_h(d[mt][2*np+1], al[mt], bh[2], bh[3]);
                }
            }
        }
        __syncthreads();

        int pn = n + NST2; if (pn >= NCH) pn = 0;
        prefetch(pn, stage);
        stage++; if (stage == NST2) stage = 0;
    }

    const int g  = lane >> 2;
    const int tq = lane & 3;
    #pragma unroll
    for (int mt = 0; mt < 2; mt++) {
        int row = m0 + wm*32 + mt*16 + g;
        #pragma unroll
        for (int nt = 0; nt < 8; nt++) {
            int col = n0 + wn*64 + nt*8 + 2*tq;
            if (row < M)     outw(row,     col, d[mt][nt][0], d[mt][nt][1]);
            if (row + 8 < M) outw(row + 8, col, d[mt][nt][2], d[mt][nt][3]);
        }
    }
}

__global__ __launch_bounds__(256) void gemm_h2f(
    const __half* __restrict__ Ah, const __half* __restrict__ Al,
    const __half* __restrict__ Bh, float* __restrict__ C, int M, int N, int K)
{
    extern __shared__ char smg[];
    OutF32 o{C, N};
    gemm_h2_body(Ah, Al, Bh, o, M, N, K, smg);
}

__global__ __launch_bounds__(256) void gemm_h2h(
    const __half* __restrict__ Ah, const __half* __restrict__ Al,
    const __half* __restrict__ Bh, __half* __restrict__ Ch, int M, int N, int K)
{
    extern __shared__ char smg[];
    OutF16 o{Ch, N};
    gemm_h2_body(Ah, Al, Bh, o, M, N, K, smg);
}

// ---------------- skinny adapter GEMM (M=20, fp32, split-K) ----------------
__global__ __launch_bounds__(128) void gemm_skinny(
    const float* __restrict__ Aad, const float* __restrict__ wk, const float* __restrict__ wv)
{
    __shared__ float As[20][33];
    __shared__ float Bs[128][33];
    const int t = threadIdx.x;
    const int n0 = blockIdx.x * 128;
    const int kz = blockIdx.y;
    const float* W = blockIdx.z ? wv : wk;
    float* P = (blockIdx.z ? g_pv : g_pk) + (size_t)kz * (20*4096);

    float acc[20];
    #pragma unroll
    for (int m = 0; m < 20; m++) acc[m] = 0.f;

    for (int k0 = kz*512; k0 < kz*512 + 512; k0 += 32) {
        for (int i = t; i < 640; i += 128) {
            int r = i >> 5, c = i & 31;
            As[r][c] = Aad[(size_t)r*4096 + k0 + c];
        }
        #pragma unroll
        for (int i = 0; i < 8; i++) {
            int idx = t + i*128;
            int r = idx >> 3, cq = idx & 7;
            float4 v = *(const float4*)&W[(size_t)(n0 + r)*4096 + k0 + cq*4];
            Bs[r][cq*4+0] = v.x; Bs[r][cq*4+1] = v.y;
            Bs[r][cq*4+2] = v.z; Bs[r][cq*4+3] = v.w;
        }
        __syncthreads();
        #pragma unroll
        for (int k = 0; k < 32; k++) {
            float bv = Bs[t][k];
            #pragma unroll
            for (int m = 0; m < 20; m++) acc[m] += As[m][k] * bv;
        }
        __syncthreads();
    }
    #pragma unroll
    for (int m = 0; m < 20; m++) P[(size_t)m*4096 + n0 + t] = acc[m];
}

__global__ void skinny_reduce()
{
    int i = blockIdx.x*256 + threadIdx.x;
    if (i >= 20*4096) return;
    float sk = 0.f, sv = 0.f;
    #pragma unroll
    for (int z = 0; z < KSPL; z++) {
        sk += g_pk[(size_t)z*(20*4096) + i];
        sv += g_pv[(size_t)z*(20*4096) + i];
    }
    g_ak[i] = sk;
    g_av[i] = sv;
}

// ---------------- RoPE variants ----------------
// Q: fp32 writeback (adapter needs it) + hi/lo split
__global__ void rope_split(float* __restrict__ T, __half* __restrict__ Th, __half* __restrict__ Tl,
                           const float* __restrict__ cosT, const float* __restrict__ sinT)
{
    int idx = blockIdx.x * blockDim.x + threadIdx.x;
    if (idx >= Bb*Ss*Hh*HALFh) return;
    int p = idx & (HALFh - 1);
    int s = (idx >> 11) & (Ss - 1);
    float c  = cosT[s*HALFh + p];
    float sn = sinT[s*HALFh + p];
    float2 v = *(float2*)&T[2*(size_t)idx];
    float2 r;
    r.x = v.x * c - v.y * sn;
    r.y = v.x * sn + v.y * c;
    *(float2*)&T[2*(size_t)idx] = r;
    __half h0 = __float2half_rn(r.x), h1 = __float2half_rn(r.y);
    *(__half2*)(Th + 2*(size_t)idx) = __halves2half2(h0, h1);
    *(__half2*)(Tl + 2*(size_t)idx) = __halves2half2(__float2half_rn(r.x - __half2float(h0)),
                                                     __float2half_rn(r.y - __half2float(h1)));
}

// K: hi-only split, no fp32 writeback
__global__ void rope_hi(const float* __restrict__ T, __half* __restrict__ Th,
                        const float* __restrict__ cosT, const float* __restrict__ sinT)
{
    int idx = blockIdx.x * blockDim.x + threadIdx.x;
    if (idx >= Bb*Ss*Hh*HALFh) return;
    int p = idx & (HALFh - 1);
    int s = (idx >> 11) & (Ss - 1);
    float c  = cosT[s*HALFh + p];
    float sn = sinT[s*HALFh + p];
    float2 v = *(const float2*)&T[2*(size_t)idx];
    *(__half2*)(Th + 2*(size_t)idx) =
        __halves2half2(__float2half_rn(v.x * c - v.y * sn),
                       __float2half_rn(v.x * sn + v.y * c));
}

// ---------------- flash attention: QK 2-term (qh*kh + ql*kh), PV 2-term, FKV=128 ----------------
__global__ __launch_bounds__(128, 2) void flash_h()
{
    extern __shared__ char fsm[];
    const uint32_t sb = s2u(fsm);
    const int t = threadIdx.x, lane = t & 31, w = t >> 5;   // w in 0..3
    const int bh = blockIdx.y, b = bh >> 5, h = bh & 31;
    const int q0 = (int)(gridDim.x - 1 - blockIdx.x) * FQ;
    const size_t headbase = (size_t)b * Ss * Dd + (size_t)h * HDh;
    const int g = lane >> 2, tq = lane & 3;
    const float rscale = 0.08838834764831844f;
    const float NEGINF = __int_as_float(0xff800000);

    // prologue: Q hi/lo (64 rows x 16 chunks each)
    {
        const __half* qh = g_qh + headbase + (size_t)q0 * Dd;
        const __half* ql = g_ql + headbase + (size_t)q0 * Dd;
        #pragma unroll
        for (int i = 0; i < 8; i++) {
            int idx = t + i*128;
            int r = idx >> 4, cq = idx & 15;
            uint32_t so = (uint32_t)(r*FROWB + cq*16);
            size_t go = (size_t)r*Dd + cq*8;
            asm volatile("cp.async.cg.shared.global [%0], [%1], 16;" :: "r"(sb + QHOFF + so), "l"(qh + go));
            asm volatile("cp.async.cg.shared.global [%0], [%1], 16;" :: "r"(sb + QLOFF + so), "l"(ql + go));
        }
        asm volatile("cp.async.commit_group;" ::: "memory");
    }

    const uint32_t aRow = (uint32_t)(w*16 + (lane & 7) + ((lane >> 3) & 1)*8);
    const uint32_t aKof = (uint32_t)(((lane >> 4) & 1) << 4);
    const uint32_t bRow = (uint32_t)((lane & 7) + ((lane >> 4) & 1)*8);
    const uint32_t bKof = (uint32_t)(((lane >> 3) & 1) << 4);
    const uint32_t vRow = (uint32_t)((lane & 7) + ((lane >> 3) & 1)*8);
    const uint32_t vDof = (uint32_t)(((lane >> 4) & 1) << 4);

    float o[16][4];
    #pragma unroll
    for (int nt = 0; nt < 16; nt++) { o[nt][0]=o[nt][1]=o[nt][2]=o[nt][3]=0.f; }
    float m0r = -1e30f, m1r = -1e30f, l0r = 0.f, l1r = 0.f;

    const int ig0 = q0 + w*16 + g;
    const int ig1 = ig0 + 8;

    for (int j0 = 0; j0 < q0 + FQ; j0 += FKV) {
        __syncthreads();   // prior iteration's KV reads done before overwrite
        {
            const __half* kh = g_kh + headbase + (size_t)j0 * Dd;
            const __half* vh = g_vh + headbase + (size_t)j0 * Dd;
            #pragma unroll
            for (int i = 0; i < 16; i++) {
                int idx = t + i*128;
                int r = idx >> 4, cq = idx & 15;
                uint32_t so = (uint32_t)(r*FROWB + cq*16);
                size_t go = (size_t)r*Dd + cq*8;
                asm volatile("cp.async.cg.shared.global [%0], [%1], 16;" :: "r"(sb + KH0 + so), "l"(kh + go));
                asm volatile("cp.async.cg.shared.global [%0], [%1], 16;" :: "r"(sb + VH0 + so), "l"(vh + go));
            }
            asm volatile("cp.async.commit_group;" ::: "memory");
        }
        asm volatile("cp.async.wait_group 0;" ::: "memory");
        __syncthreads();

        // ---- S = Q K^T over 128 keys : qh*kh + ql*kh ----
        float s[16][4];
        #pragma unroll
        for (int nt = 0; nt < 16; nt++) { s[nt][0]=s[nt][1]=s[nt][2]=s[nt][3]=0.f; }
        #pragma unroll
        for (int ks = 0; ks < 8; ks++) {
            const uint32_t kb = (uint32_t)ks * 32u;
            uint32_t ah[4], al_[4];
            ldsm_x4(ah,  sb + QHOFF + aRow*FROWB + aKof + kb);
            ldsm_x4(al_, sb + QLOFF + aRow*FROWB + aKof + kb);
            #pragma unroll
            for (int np = 0; np < 8; np++) {
                uint32_t bhf[4];
                ldsm_x4(bhf, sb + KH0 + (bRow + np*16u)*FROWB + bKof + kb);
                mma_h(s[2*np],   ah,  bhf[0], bhf[1]);
                mma_h(s[2*np],   al_, bhf[0], bhf[1]);
                mma_h(s[2*np+1], ah,  bhf[2], bhf[3]);
                mma_h(s[2*np+1], al_, bhf[2], bhf[3]);
            }
        }

        // ---- mask + online softmax over 128 keys ----
        float mx0 = -1e30f, mx1 = -1e30f;
        #pragma unroll
        for (int nt = 0; nt < 16; nt++) {
            int jg = j0 + nt*8 + 2*tq;
            s[nt][0] = (jg   > ig0) ? NEGINF : s[nt][0]*rscale;
            s[nt][1] = (jg+1 > ig0) ? NEGINF : s[nt][1]*rscale;
            s[nt][2] = (jg   > ig1) ? NEGINF : s[nt][2]*rscale;
            s[nt][3] = (jg+1 > ig1) ? NEGINF : s[nt][3]*rscale;
            mx0 = fmaxf(mx0, fmaxf(s[nt][0], s[nt][1]));
            mx1 = fmaxf(mx1, fmaxf(s[nt][2], s[nt][3]));
        }
        mx0 = fmaxf(mx0, __shfl_xor_sync(0xffffffffu, mx0, 1));
        mx0 = fmaxf(mx0, __shfl_xor_sync(0xffffffffu, mx0, 2));
        mx1 = fmaxf(mx1, __shfl_xor_sync(0xffffffffu, mx1, 1));
        mx1 = fmaxf(mx1, __shfl_xor_sync(0xffffffffu, mx1, 2));
        float mn0 = fmaxf(m0r, mx0), mn1 = fmaxf(m1r, mx1);
        float co0 = __expf(m0r - mn0), co1 = __expf(m1r - mn1);
        float sum0 = 0.f, sum1 = 0.f;
        #pragma unroll
        for (int nt = 0; nt < 16; nt++) {
            s[nt][0] = __expf(s[nt][0] - mn0);
            s[nt][1] = __expf(s[nt][1] - mn0);
            s[nt][2] = __expf(s[nt][2] - mn1);
            s[nt][3] = __expf(s[nt][3] - mn1);
            sum0 += s[nt][0] + s[nt][1];
            sum1 += s[nt][2] + s[nt][3];
        }
        sum0 += __shfl_xor_sync(0xffffffffu, sum0, 1);
        sum0 += __shfl_xor_sync(0xffffffffu, sum0, 2);
        sum1 += __shfl_xor_sync(0xffffffffu, sum1, 1);
        sum1 += __shfl_xor_sync(0xffffffffu, sum1, 2);
        l0r = l0r * co0 + sum0;  m0r = mn0;
        l1r = l1r * co1 + sum1;  m1r = mn1;

        #pragma unroll
        for (int nt = 0; nt < 16; nt++) {
            o[nt][0] *= co0; o[nt][1] *= co0;
            o[nt][2] *= co1; o[nt][3] *= co1;
        }

        // ---- O += P Vh : ph*Vh + pl*Vh ----
        #pragma unroll
        for (int ks = 0; ks < 8; ks++) {
            uint32_t ph[4], pl[4];
            split_pack(s[2*ks][0],   s[2*ks][1],   ph[0], pl[0]);
            split_pack(s[2*ks][2],   s[2*ks][3],   ph[1], pl[1]);
            split_pack(s[2*ks+1][0], s[2*ks+1][1], ph[2], pl[2]);
            split_pack(s[2*ks+1][2], s[2*ks+1][3], ph[3], pl[3]);
            const uint32_t krow = (uint32_t)(ks*16) + vRow;
            #pragma unroll
            for (int np = 0; np < 8; np++) {
                uint32_t vhf[4];
                ldsm_x4t(vhf, sb + VH0 + krow*FROWB + (uint32_t)(np*32) + vDof);
                mma_h(o[2*np],   ph, vhf[0], vhf[1]);
                mma_h(o[2*np],   pl, vhf[0], vhf[1]);
                mma_h(o[2*np+1], ph, vhf[2], vhf[3]);
                mma_h(o[2*np+1], pl, vhf[2], vhf[3]);
            }
        }
    }

    float inv0 = 1.f / l0r, inv1 = 1.f / l1r;
    float* Og = g_attn + headbase + (size_t)(q0 + w*16) * Dd;
    #pragma unroll
    for (int nt = 0; nt < 16; nt++) {
        *(float2*)&Og[(size_t)g*Dd     + nt*8 + 2*tq] = make_float2(o[nt][0]*inv0, o[nt][1]*inv0);
        *(float2*)&Og[(size_t)(g+8)*Dd + nt*8 + 2*tq] = make_float2(o[nt][2]*inv1, o[nt][3]*inv1);
    }
}

// ---------------- adapter attention (+ writes fp16 split of final attn) ----------------
__global__ __launch_bounds__(128) void adapter_kernel(const float* __restrict__ gate)
{
    __shared__ __align__(16) float ak[ALa][HDh];
    __shared__ __align__(16) float av[ALa][HDh];
    const int t = threadIdx.x;
    const int bh = blockIdx.y;
    const int b = bh >> 5, h = bh & 31;
    const int s0 = blockIdx.x * 4;

    #pragma unroll
    for (int r = 0; r < ALa; r++) {
        int idx = t + r*128;
        int j = idx >> 7, d = idx & 127;
        ak[j][d] = g_ak[(size_t)(b*ALa + j) * Dd + h*HDh + d];
        av[j][d] = g_av[(size_t)(b*ALa + j) * Dd + h*HDh + d];
    }
    __syncthreads();

    const int w = t >> 5, lane = t & 31;
    const int s = s0 + w;
    const size_t base = (size_t)(b*Ss + s) * Dd + h*HDh;
    const float rscale = 0.08838834764831844f;

    float4 qv = *(const float4*)&g_q[base + lane*4];
    float sc[ALa];
    #pragma unroll
    for (int j = 0; j < ALa; j++) {
        float d0 = qv.x*ak[j][lane*4+0] + qv.y*ak[j][lane*4+1]
                 + qv.z*ak[j][lane*4+2] + qv.w*ak[j][lane*4+3];
        #pragma unroll
        for (int off = 16; off >= 1; off >>= 1)
            d0 += __shfl_xor_sync(0xffffffffu, d0, off);
        sc[j] = d0 * rscale;
    }
    float mx = sc[0];
    #pragma unroll
    for (int j = 1; j < ALa; j++) mx = fmaxf(mx, sc[j]);
    float sum = 0.f;
    #pragma unroll
    for (int j = 0; j < ALa; j++) { sc[j] = __expf(sc[j] - mx); sum += sc[j]; }
    float inv = 1.f / sum;
    float gg = tanhf(gate[h]);

    float acc[4] = {0.f, 0.f, 0.f, 0.f};
    #pragma unroll
    for (int j = 0; j < ALa; j++) {
        float p = sc[j] * inv;
        acc[0] += p * av[j][lane*4+0];
        acc[1] += p * av[j][lane*4+1];
        acc[2] += p * av[j][lane*4+2];
        acc[3] += p * av[j][lane*4+3];
    }
    float4 ov = *(float4*)&g_attn[base + lane*4];
    ov.x += gg*acc[0]; ov.y += gg*acc[1]; ov.z += gg*acc[2]; ov.w += gg*acc[3];
    *(float4*)&g_attn[base + lane*4] = ov;

    __half h0 = __float2half_rn(ov.x), h1 = __float2half_rn(ov.y);
    __half h2 = __float2half_rn(ov.z), h3 = __float2half_rn(ov.w);
    *(__half2*)(g_ah + base + lane*4)     = __halves2half2(h0, h1);
    *(__half2*)(g_ah + base + lane*4 + 2) = __halves2half2(h2, h3);
    *(__half2*)(g_al + base + lane*4)     = __halves2half2(__float2half_rn(ov.x - __half2float(h0)),
                                                           __float2half_rn(ov.y - __half2float(h1)));
    *(__half2*)(g_al + base + lane*4 + 2) = __halves2half2(__float2half_rn(ov.z - __half2float(h2)),
                                                           __float2half_rn(ov.w - __half2float(h3)));
}

// ---------------- host ----------------
extern "C" void kernel_launch(void* const* d_in, const int* in_sizes, int n_in,
                              void* d_out, int out_size)
{
    (void)in_sizes; (void)n_in; (void)out_size;
    const float* x       = (const float*)d_in[0];
    const float* cosT    = (const float*)d_in[2];
    const float* sinT    = (const float*)d_in[3];
    const float* wq      = (const float*)d_in[4];
    const float* wk      = (const float*)d_in[5];
    const float* wv      = (const float*)d_in[6];
    const float* wo      = (const float*)d_in[7];
    const float* gate    = (const float*)d_in[8];
    const float* adapter = (const float*)d_in[9];
    float* out = (float*)d_out;

    float *qp, *kp;
    __half *ahp, *alp, *wqh, *wkh, *wvh, *woh;
    __half *qhp, *qlp, *khp, *vhp;
    cudaGetSymbolAddress((void**)&qp,    g_q);
    cudaGetSymbolAddress((void**)&kp,    g_k);
    cudaGetSymbolAddress((void**)&ahp,  g_ah);  cudaGetSymbolAddress((void**)&alp,  g_al);
    cudaGetSymbolAddress((void**)&wqh,  g_wqh);
    cudaGetSymbolAddress((void**)&wkh,  g_wkh);
    cudaGetSymbolAddress((void**)&wvh,  g_wvh);
    cudaGetSymbolAddress((void**)&woh,  g_woh);
    cudaGetSymbolAddress((void**)&qhp,  g_qh);  cudaGetSymbolAddress((void**)&qlp,  g_ql);
    cudaGetSymbolAddress((void**)&khp,  g_kh);
    cudaGetSymbolAddress((void**)&vhp,  g_vh);

    cudaFuncSetAttribute(gemm_h2f, cudaFuncAttributeMaxDynamicSharedMemorySize, GEMM2_SMEM);
    cudaFuncSetAttribute(gemm_h2h, cudaFuncAttributeMaxDynamicSharedMemorySize, GEMM2_SMEM);
    cudaFuncSetAttribute(flash_h, cudaFuncAttributeMaxDynamicSharedMemorySize, FLASH_SMEM);

    const int nXW = Mtok*Dd;
    const int cgrid = nXW/4/256;

    conv_split<<<cgrid, 256>>>(x,  ahp, alp, nXW);
    conv_hi<<<cgrid, 256>>>(wq, wqh, Dd*Dd);
    conv_hi<<<cgrid, 256>>>(wk, wkh, Dd*Dd);
    conv_hi<<<cgrid, 256>>>(wv, wvh, Dd*Dd);
    conv_hi<<<cgrid, 256>>>(wo, woh, Dd*Dd);

    dim3 gbig(Dd/BN, Mtok/BM);
    gemm_h2f<<<gbig, 256, GEMM2_SMEM>>>(ahp, alp, wqh, qp, Mtok, Dd, Dd);
    gemm_h2f<<<gbig, 256, GEMM2_SMEM>>>(ahp, alp, wkh, kp, Mtok, Dd, Dd);
    gemm_h2h<<<gbig, 256, GEMM2_SMEM>>>(ahp, alp, wvh, vhp, Mtok, Dd, Dd);

    gemm_skinny<<<dim3(Dd/128, KSPL, 2), 128>>>(adapter, wk, wv);
    skinny_reduce<<<(20*4096 + 255)/256, 256>>>();

    int npairs = Bb*Ss*Hh*HALFh;
    rope_split<<<npairs/256, 256>>>(qp, qhp, qlp, cosT, sinT);
    rope_hi<<<npairs/256, 256>>>(kp, khp, cosT, sinT);

    flash_h<<<dim3(Ss/FQ, Bb*Hh), 128, FLASH_SMEM>>>();
    adapter_kernel<<<dim3(Ss/4, Bb*Hh), 128>>>(gate);

    gemm_h2f<<<gbig, 256, GEMM2_SMEM>>>(ahp, alp, woh, out, Mtok, Dd, Dd);
}

// round 17
// speedup vs baseline: 1.7586x; 1.1837x over previous
#include <cuda_runtime.h>
#include <cuda_fp16.h>
#include <math.h>
#include <stdint.h>

#define Bb 2
#define Ss 2048
#define Dd 4096
#define Hh 32
#define HDh 128
#define HALFh 64
#define ALa 10
#define Mtok (Bb*Ss)

// ---- fp16 GEMM common ----
#define BM 128
#define BN 128
#define BKh 64                       // halves per K-chunk = 128B row
#define HROWB 144                    // smem row bytes (128 data + 16 pad)
#define OPB (128*HROWB)              // one operand = 18432 B

// 2-term: Ah, Al, Bh; 4 stages
#define STAGE2_B (3*OPB)
#define NST2 4
#define GEMM2_SMEM (NST2*STAGE2_B)   // 221184 B

// 1-term: Ah, Bh; 4 stages
#define STAGE1_B (2*OPB)
#define NST1 4
#define GEMM1_SMEM (NST1*STAGE1_B)   // 147456 B

// ---- flash config: FQ=64, FKV=128, 128 threads, 2 CTAs/SM ----
#define FQ 64
#define FKV 128
#define FROWB 272                    // 128 halves + 8 pad
#define QHOFF 0
#define QLOFF (64*FROWB)
#define KH0 (2*64*FROWB)
#define VH0 (KH0 + 128*FROWB)
#define FLASH_SMEM (VH0 + 128*FROWB)   // 104448 B

#define KSPL 8

// ---------------- scratch (static device globals) ----------------
__device__ float g_q[Mtok*Dd];
__device__ float g_k[Mtok*Dd];
__device__ float g_attn[Mtok*Dd];
__device__ float g_ak[Bb*ALa*Dd];
__device__ float g_av[Bb*ALa*Dd];
__device__ float g_pk[KSPL*Bb*ALa*Dd];
__device__ float g_pv[KSPL*Bb*ALa*Dd];

__device__ __half g_ah[Mtok*Dd];   // x split; later holds attn split
__device__ __half g_al[Mtok*Dd];
__device__ __half g_wqh[Dd*Dd];
__device__ __half g_wkh[Dd*Dd];
__device__ __half g_wvh[Dd*Dd];
__device__ __half g_woh[Dd*Dd];
__device__ __half g_qh[Mtok*Dd], g_ql[Mtok*Dd];
__device__ __half g_kh[Mtok*Dd];
__device__ __half g_vh[Mtok*Dd];

// ---------------- helpers ----------------
__device__ __forceinline__ uint32_t s2u(const void* p){
    uint32_t r;
    asm("{ .reg .u64 t; cvta.to.shared.u64 t, %1; cvt.u32.u64 %0, t; }" : "=r"(r) : "l"(p));
    return r;
}

__device__ __forceinline__ void ldsm_x4(uint32_t* r, uint32_t addr){
    asm volatile("ldmatrix.sync.aligned.m8n8.x4.shared.b16 {%0,%1,%2,%3}, [%4];"
                 : "=r"(r[0]), "=r"(r[1]), "=r"(r[2]), "=r"(r[3]) : "r"(addr));
}
__device__ __forceinline__ void ldsm_x4t(uint32_t* r, uint32_t addr){
    asm volatile("ldmatrix.sync.aligned.m8n8.x4.trans.shared.b16 {%0,%1,%2,%3}, [%4];"
                 : "=r"(r[0]), "=r"(r[1]), "=r"(r[2]), "=r"(r[3]) : "r"(addr));
}

__device__ __forceinline__ void mma_h(float* d, const uint32_t* a, uint32_t b0, uint32_t b1){
    asm volatile(
        "mma.sync.aligned.m16n8k16.row.col.f32.f16.f16.f32 "
        "{%0,%1,%2,%3}, {%4,%5,%6,%7}, {%8,%9}, {%0,%1,%2,%3};"
        : "+f"(d[0]), "+f"(d[1]), "+f"(d[2]), "+f"(d[3])
        : "r"(a[0]), "r"(a[1]), "r"(a[2]), "r"(a[3]), "r"(b0), "r"(b1));
}

__device__ __forceinline__ uint32_t packh2(float lo, float hi){
    uint32_t r;
    asm("cvt.rn.f16x2.f32 %0, %1, %2;" : "=r"(r) : "f"(hi), "f"(lo));
    return r;
}

__device__ __forceinline__ void split_pack(float f0, float f1, uint32_t& hi, uint32_t& lo){
    __half h0 = __float2half_rn(f0), h1 = __float2half_rn(f1);
    __half2 hh = __halves2half2(h0, h1);
    hi = *reinterpret_cast<uint32_t*>(&hh);
    lo = packh2(f0 - __half2float(h0), f1 - __half2float(h1));
}

// epilogue functors
struct OutF32 {
    float* C; int N;
    __device__ __forceinline__ void operator()(int row, int col, float v0, float v1) const {
        *(float2*)&C[(size_t)row * N + col] = make_float2(v0, v1);
    }
};
struct OutF16 {
    __half* C; int N;
    __device__ __forceinline__ void operator()(int row, int col, float v0, float v1) const {
        *(__half2*)&C[(size_t)row * N + col] =
            __halves2half2(__float2half_rn(v0), __float2half_rn(v1));
    }
};

// ---------------- conversions ----------------
__global__ void conv_split(const float* __restrict__ s, __half* __restrict__ hi,
                           __half* __restrict__ lo, int n)
{
    int i = (blockIdx.x*256 + threadIdx.x) * 4;
    if (i >= n) return;
    float4 v = *(const float4*)(s + i);
    __half h0 = __float2half_rn(v.x), h1 = __float2half_rn(v.y);
    __half h2 = __float2half_rn(v.z), h3 = __float2half_rn(v.w);
    *(__half2*)(hi + i)     = __halves2half2(h0, h1);
    *(__half2*)(hi + i + 2) = __halves2half2(h2, h3);
    *(__half2*)(lo + i)     = __halves2half2(__float2half_rn(v.x - __half2float(h0)),
                                             __float2half_rn(v.y - __half2float(h1)));
    *(__half2*)(lo + i + 2) = __halves2half2(__float2half_rn(v.z - __half2float(h2)),
                                             __float2half_rn(v.w - __half2float(h3)));
}

__global__ void conv_hi(const float* __restrict__ s, __half* __restrict__ hi, int n)
{
    int i = (blockIdx.x*256 + threadIdx.x) * 4;
    if (i >= n) return;
    float4 v = *(const float4*)(s + i);
    *(__half2*)(hi + i)     = __halves2half2(__float2half_rn(v.x), __float2half_rn(v.y));
    *(__half2*)(hi + i + 2) = __halves2half2(__float2half_rn(v.z), __float2half_rn(v.w));
}

// ---------------- 2-term fp16 NT GEMM core (templated epilogue) ----------------
template<typename OUTW>
__device__ __forceinline__ void gemm_h2_body(
    const __half* __restrict__ Ah, const __half* __restrict__ Al,
    const __half* __restrict__ Bh, OUTW outw, int M, int N, int K, char* smg)
{
    const uint32_t sbase = s2u(smg);
    const int t = threadIdx.x;
    const int m0 = blockIdx.y * BM;
    const int n0 = blockIdx.x * BN;
    const int NCH = K / BKh;

    const int lane = t & 31;
    const int wid  = t >> 5;
    const int wm   = wid & 3;
    const int wn   = wid >> 2;

    float d[2][8][4];
    #pragma unroll
    for (int mt = 0; mt < 2; mt++)
        #pragma unroll
        for (int nt = 0; nt < 8; nt++)
            #pragma unroll
            for (int c = 0; c < 4; c++) d[mt][nt][c] = 0.f;

    const uint32_t aRow = (uint32_t)(wm*32 + (lane & 7) + ((lane >> 3) & 1)*8);
    const uint32_t aKof = (uint32_t)(((lane >> 4) & 1) << 4);
    const uint32_t bRow = (uint32_t)(wn*64 + (lane & 7) + ((lane >> 4) & 1)*8);
    const uint32_t bKof = (uint32_t)(((lane >> 3) & 1) << 4);

    const int ldr = t >> 3;
    const int ldq = t & 7;

    auto prefetch = [&](int chunk, int stage){
        const int k0 = chunk * BKh;
        const uint32_t st = sbase + (uint32_t)stage * STAGE2_B;
        #pragma unroll
        for (int i = 0; i < 4; i++) {
            int row = ldr + i*32;
            int ar = m0 + row; if (ar > M-1) ar = M-1;
            size_t goa = (size_t)ar * K + k0 + ldq*8;
            size_t gob = (size_t)(n0 + row) * K + k0 + ldq*8;
            uint32_t so = (uint32_t)row * HROWB + (uint32_t)ldq * 16u;
            asm volatile("cp.async.cg.shared.global [%0], [%1], 16;" :: "r"(st + 0*OPB + so), "l"(Ah + goa));
            asm volatile("cp.async.cg.shared.global [%0], [%1], 16;" :: "r"(st + 1*OPB + so), "l"(Al + goa));
            asm volatile("cp.async.cg.shared.global [%0], [%1], 16;" :: "r"(st + 2*OPB + so), "l"(Bh + gob));
        }
        asm volatile("cp.async.commit_group;" ::: "memory");
    };

    #pragma unroll
    for (int p = 0; p < NST2; p++) prefetch(p, p);

    int stage = 0;
    for (int n = 0; n < NCH; n++) {
        asm volatile("cp.async.wait_group %0;" :: "n"(NST2-1) : "memory");
        __syncthreads();

        const uint32_t st = sbase + (uint32_t)stage * STAGE2_B;
        const uint32_t sAh = st, sAl = st + OPB, sBh = st + 2*OPB;

        #pragma unroll
        for (int ks = 0; ks < 4; ks++) {
            const uint32_t kb = (uint32_t)ks * 32u;
            uint32_t ah[2][4], al[2][4];
            #pragma unroll
            for (int mt = 0; mt < 2; mt++) {
                ldsm_x4(ah[mt], sAh + (aRow + mt*16u)*HROWB + aKof + kb);
                ldsm_x4(al[mt], sAl + (aRow + mt*16u)*HROWB + aKof + kb);
            }
            #pragma unroll
            for (int np = 0; np < 4; np++) {
                uint32_t bh[4];
                ldsm_x4(bh, sBh + (bRow + np*16u)*HROWB + bKof + kb);
                #pragma unroll
                for (int mt = 0; mt < 2; mt++) {
                    mma_h(d[mt][2*np],   ah[mt], bh[0], bh[1]);
                    mma_h(d[mt][2*np],   al[mt], bh[0], bh[1]);
                    mma_h(d[mt][2*np+1], ah[mt], bh[2], bh[3]);
                    mma_h(d[mt][2*np+1], al[mt], bh[2], bh[3]);
                }
            }
        }
        __syncthreads();

        int pn = n + NST2; if (pn >= NCH) pn = 0;
        prefetch(pn, stage);
        stage++; if (stage == NST2) stage = 0;
    }

    const int g  = lane >> 2;
    const int tq = lane & 3;
    #pragma unroll
    for (int mt = 0; mt < 2; mt++) {
        int row = m0 + wm*32 + mt*16 + g;
        #pragma unroll
        for (int nt = 0; nt < 8; nt++) {
            int col = n0 + wn*64 + nt*8 + 2*tq;
            if (row < M)     outw(row,     col, d[mt][nt][0], d[mt][nt][1]);
            if (row + 8 < M) outw(row + 8, col, d[mt][nt][2], d[mt][nt][3]);
        }
    }
}

__global__ __launch_bounds__(256) void gemm_h2f(
    const __half* __restrict__ Ah, const __half* __restrict__ Al,
    const __half* __restrict__ Bh, float* __restrict__ C, int M, int N, int K)
{
    extern __shared__ char smg[];
    OutF32 o{C, N};
    gemm_h2_body(Ah, Al, Bh, o, M, N, K, smg);
}

__global__ __launch_bounds__(256) void gemm_h2h(
    const __half* __restrict__ Ah, const __half* __restrict__ Al,
    const __half* __restrict__ Bh, __half* __restrict__ Ch, int M, int N, int K)
{
    extern __shared__ char smg[];
    OutF16 o{Ch, N};
    gemm_h2_body(Ah, Al, Bh, o, M, N, K, smg);
}

// ---------------- 1-term fp16 NT GEMM (Q/K projections): C = Ah @ Bh^T ----------------
__global__ __launch_bounds__(256) void gemm_h1f(
    const __half* __restrict__ Ah, const __half* __restrict__ Bh,
    float* __restrict__ C, int M, int N, int K)
{
    extern __shared__ char smg[];
    const uint32_t sbase = s2u(smg);
    const int t = threadIdx.x;
    const int m0 = blockIdx.y * BM;
    const int n0 = blockIdx.x * BN;
    const int NCH = K / BKh;

    const int lane = t & 31;
    const int wid  = t >> 5;
    const int wm   = wid & 3;
    const int wn   = wid >> 2;

    float d[2][8][4];
    #pragma unroll
    for (int mt = 0; mt < 2; mt++)
        #pragma unroll
        for (int nt = 0; nt < 8; nt++)
            #pragma unroll
            for (int c = 0; c < 4; c++) d[mt][nt][c] = 0.f;

    const uint32_t aRow = (uint32_t)(wm*32 + (lane & 7) + ((lane >> 3) & 1)*8);
    const uint32_t aKof = (uint32_t)(((lane >> 4) & 1) << 4);
    const uint32_t bRow = (uint32_t)(wn*64 + (lane & 7) + ((lane >> 4) & 1)*8);
    const uint32_t bKof = (uint32_t)(((lane >> 3) & 1) << 4);

    const int ldr = t >> 3;
    const int ldq = t & 7;

    auto prefetch = [&](int chunk, int stage){
        const int k0 = chunk * BKh;
        const uint32_t st = sbase + (uint32_t)stage * STAGE1_B;
        #pragma unroll
        for (int i = 0; i < 4; i++) {
            int row = ldr + i*32;
            int ar = m0 + row; if (ar > M-1) ar = M-1;
            size_t goa = (size_t)ar * K + k0 + ldq*8;
            size_t gob = (size_t)(n0 + row) * K + k0 + ldq*8;
            uint32_t so = (uint32_t)row * HROWB + (uint32_t)ldq * 16u;
            asm volatile("cp.async.cg.shared.global [%0], [%1], 16;" :: "r"(st + so), "l"(Ah + goa));
            asm volatile("cp.async.cg.shared.global [%0], [%1], 16;" :: "r"(st + OPB + so), "l"(Bh + gob));
        }
        asm volatile("cp.async.commit_group;" ::: "memory");
    };

    #pragma unroll
    for (int p = 0; p < NST1; p++) prefetch(p, p);

    int stage = 0;
    for (int n = 0; n < NCH; n++) {
        asm volatile("cp.async.wait_group %0;" :: "n"(NST1-1) : "memory");
        __syncthreads();

        const uint32_t st = sbase + (uint32_t)stage * STAGE1_B;
        const uint32_t sAh = st, sBh = st + OPB;

        #pragma unroll
        for (int ks = 0; ks < 4; ks++) {
            const uint32_t kb = (uint32_t)ks * 32u;
            uint32_t ah[2][4];
            #pragma unroll
            for (int mt = 0; mt < 2; mt++)
                ldsm_x4(ah[mt], sAh + (aRow + mt*16u)*HROWB + aKof + kb);
            #pragma unroll
            for (int np = 0; np < 4; np++) {
                uint32_t bh[4];
                ldsm_x4(bh, sBh + (bRow + np*16u)*HROWB + bKof + kb);
                #pragma unroll
                for (int mt = 0; mt < 2; mt++) {
                    mma_h(d[mt][2*np],   ah[mt], bh[0], bh[1]);
                    mma_h(d[mt][2*np+1], ah[mt], bh[2], bh[3]);
                }
            }
        }
        __syncthreads();

        int pn = n + NST1; if (pn >= NCH) pn = 0;
        prefetch(pn, stage);
        stage++; if (stage == NST1) stage = 0;
    }

    const int g  = lane >> 2;
    const int tq = lane & 3;
    #pragma unroll
    for (int mt = 0; mt < 2; mt++) {
        int row = m0 + wm*32 + mt*16 + g;
        #pragma unroll
        for (int nt = 0; nt < 8; nt++) {
            int col = n0 + wn*64 + nt*8 + 2*tq;
            if (row < M)
                *(float2*)&C[(size_t)row * N + col] = make_float2(d[mt][nt][0], d[mt][nt][1]);
            if (row + 8 < M)
                *(float2*)&C[(size_t)(row+8) * N + col] = make_float2(d[mt][nt][2], d[mt][nt][3]);
        }
    }
}

// ---------------- skinny adapter GEMM (M=20, fp32, split-K) ----------------
__global__ __launch_bounds__(128) void gemm_skinny(
    const float* __restrict__ Aad, const float* __restrict__ wk, const float* __restrict__ wv)
{
    __shared__ float As[20][33];
    __shared__ float Bs[128][33];
    const int t = threadIdx.x;
    const int n0 = blockIdx.x * 128;
    const int kz = blockIdx.y;
    const float* W = blockIdx.z ? wv : wk;
    float* P = (blockIdx.z ? g_pv : g_pk) + (size_t)kz * (20*4096);

    float acc[20];
    #pragma unroll
    for (int m = 0; m < 20; m++) acc[m] = 0.f;

    for (int k0 = kz*512; k0 < kz*512 + 512; k0 += 32) {
        for (int i = t; i < 640; i += 128) {
            int r = i >> 5, c = i & 31;
            As[r][c] = Aad[(size_t)r*4096 + k0 + c];
        }
        #pragma unroll
        for (int i = 0; i < 8; i++) {
            int idx = t + i*128;
            int r = idx >> 3, cq = idx & 7;
            float4 v = *(const float4*)&W[(size_t)(n0 + r)*4096 + k0 + cq*4];
            Bs[r][cq*4+0] = v.x; Bs[r][cq*4+1] = v.y;
            Bs[r][cq*4+2] = v.z; Bs[r][cq*4+3] = v.w;
        }
        __syncthreads();
        #pragma unroll
        for (int k = 0; k < 32; k++) {
            float bv = Bs[t][k];
            #pragma unroll
            for (int m = 0; m < 20; m++) acc[m] += As[m][k] * bv;
        }
        __syncthreads();
    }
    #pragma unroll
    for (int m = 0; m < 20; m++) P[(size_t)m*4096 + n0 + t] = acc[m];
}

__global__ void skinny_reduce()
{
    int i = blockIdx.x*256 + threadIdx.x;
    if (i >= 20*4096) return;
    float sk = 0.f, sv = 0.f;
    #pragma unroll
    for (int z = 0; z < KSPL; z++) {
        sk += g_pk[(size_t)z*(20*4096) + i];
        sv += g_pv[(size_t)z*(20*4096) + i];
    }
    g_ak[i] = sk;
    g_av[i] = sv;
}

// ---------------- RoPE variants ----------------
__global__ void rope_split(float* __restrict__ T, __half* __restrict__ Th, __half* __restrict__ Tl,
                           const float* __restrict__ cosT, const float* __restrict__ sinT)
{
    int idx = blockIdx.x * blockDim.x + threadIdx.x;
    if (idx >= Bb*Ss*Hh*HALFh) return;
    int p = idx & (HALFh - 1);
    int s = (idx >> 11) & (Ss - 1);
    float c  = cosT[s*HALFh + p];
    float sn = sinT[s*HALFh + p];
    float2 v = *(float2*)&T[2*(size_t)idx];
    float2 r;
    r.x = v.x * c - v.y * sn;
    r.y = v.x * sn + v.y * c;
    *(float2*)&T[2*(size_t)idx] = r;
    __half h0 = __float2half_rn(r.x), h1 = __float2half_rn(r.y);
    *(__half2*)(Th + 2*(size_t)idx) = __halves2half2(h0, h1);
    *(__half2*)(Tl + 2*(size_t)idx) = __halves2half2(__float2half_rn(r.x - __half2float(h0)),
                                                     __float2half_rn(r.y - __half2float(h1)));
}

__global__ void rope_hi(const float* __restrict__ T, __half* __restrict__ Th,
                        const float* __restrict__ cosT, const float* __restrict__ sinT)
{
    int idx = blockIdx.x * blockDim.x + threadIdx.x;
    if (idx >= Bb*Ss*Hh*HALFh) return;
    int p = idx & (HALFh - 1);
    int s = (idx >> 11) & (Ss - 1);
    float c  = cosT[s*HALFh + p];
    float sn = sinT[s*HALFh + p];
    float2 v = *(const float2*)&T[2*(size_t)idx];
    *(__half2*)(Th + 2*(size_t)idx) =
        __halves2half2(__float2half_rn(v.x * c - v.y * sn),
                       __float2half_rn(v.x * sn + v.y * c));
}

// ---------------- flash attention: QK 2-term (qh*kh + ql*kh), PV 2-term, FKV=128 ----------------
__global__ __launch_bounds__(128, 2) void flash_h()
{
    extern __shared__ char fsm[];
    const uint32_t sb = s2u(fsm);
    const int t = threadIdx.x, lane = t & 31, w = t >> 5;
    const int bh = blockIdx.y, b = bh >> 5, h = bh & 31;
    const int q0 = (int)(gridDim.x - 1 - blockIdx.x) * FQ;
    const size_t headbase = (size_t)b * Ss * Dd + (size_t)h * HDh;
    const int g = lane >> 2, tq = lane & 3;
    const float rscale = 0.08838834764831844f;
    const float NEGINF = __int_as_float(0xff800000);

    {
        const __half* qh = g_qh + headbase + (size_t)q0 * Dd;
        const __half* ql = g_ql + headbase + (size_t)q0 * Dd;
        #pragma unroll
        for (int i = 0; i < 8; i++) {
            int idx = t + i*128;
            int r = idx >> 4, cq = idx & 15;
            uint32_t so = (uint32_t)(r*FROWB + cq*16);
            size_t go = (size_t)r*Dd + cq*8;
            asm volatile("cp.async.cg.shared.global [%0], [%1], 16;" :: "r"(sb + QHOFF + so), "l"(qh + go));
            asm volatile("cp.async.cg.shared.global [%0], [%1], 16;" :: "r"(sb + QLOFF + so), "l"(ql + go));
        }
        asm volatile("cp.async.commit_group;" ::: "memory");
    }

    const uint32_t aRow = (uint32_t)(w*16 + (lane & 7) + ((lane >> 3) & 1)*8);
    const uint32_t aKof = (uint32_t)(((lane >> 4) & 1) << 4);
    const uint32_t bRow = (uint32_t)((lane & 7) + ((lane >> 4) & 1)*8);
    const uint32_t bKof = (uint32_t)(((lane >> 3) & 1) << 4);
    const uint32_t vRow = (uint32_t)((lane & 7) + ((lane >> 3) & 1)*8);
    const uint32_t vDof = (uint32_t)(((lane >> 4) & 1) << 4);

    float o[16][4];
    #pragma unroll
    for (int nt = 0; nt < 16; nt++) { o[nt][0]=o[nt][1]=o[nt][2]=o[nt][3]=0.f; }
    float m0r = -1e30f, m1r = -1e30f, l0r = 0.f, l1r = 0.f;

    const int ig0 = q0 + w*16 + g;
    const int ig1 = ig0 + 8;

    for (int j0 = 0; j0 < q0 + FQ; j0 += FKV) {
        __syncthreads();
        {
            const __half* kh = g_kh + headbase + (size_t)j0 * Dd;
            const __half* vh = g_vh + headbase + (size_t)j0 * Dd;
            #pragma unroll
            for (int i = 0; i < 16; i++) {
                int idx = t + i*128;
                int r = idx >> 4, cq = idx & 15;
                uint32_t so = (uint32_t)(r*FROWB + cq*16);
                size_t go = (size_t)r*Dd + cq*8;
                asm volatile("cp.async.cg.shared.global [%0], [%1], 16;" :: "r"(sb + KH0 + so), "l"(kh + go));
                asm volatile("cp.async.cg.shared.global [%0], [%1], 16;" :: "r"(sb + VH0 + so), "l"(vh + go));
            }
            asm volatile("cp.async.commit_group;" ::: "memory");
        }
        asm volatile("cp.async.wait_group 0;" ::: "memory");
        __syncthreads();

        float s[16][4];
        #pragma unroll
        for (int nt = 0; nt < 16; nt++) { s[nt][0]=s[nt][1]=s[nt][2]=s[nt][3]=0.f; }
        #pragma unroll
        for (int ks = 0; ks < 8; ks++) {
            const uint32_t kb = (uint32_t)ks * 32u;
            uint32_t ah[4], al_[4];
            ldsm_x4(ah,  sb + QHOFF + aRow*FROWB + aKof + kb);
            ldsm_x4(al_, sb + QLOFF + aRow*FROWB + aKof + kb);
            #pragma unroll
            for (int np = 0; np < 8; np++) {
                uint32_t bhf[4];
                ldsm_x4(bhf, sb + KH0 + (bRow + np*16u)*FROWB + bKof + kb);
                mma_h(s[2*np],   ah,  bhf[0], bhf[1]);
                mma_h(s[2*np],   al_, bhf[0], bhf[1]);
                mma_h(s[2*np+1], ah,  bhf[2], bhf[3]);
                mma_h(s[2*np+1], al_, bhf[2], bhf[3]);
            }
        }

        float mx0 = -1e30f, mx1 = -1e30f;
        #pragma unroll
        for (int nt = 0; nt < 16; nt++) {
            int jg = j0 + nt*8 + 2*tq;
            s[nt][0] = (jg   > ig0) ? NEGINF : s[nt][0]*rscale;
            s[nt][1] = (jg+1 > ig0) ? NEGINF : s[nt][1]*rscale;
            s[nt][2] = (jg   > ig1) ? NEGINF : s[nt][2]*rscale;
            s[nt][3] = (jg+1 > ig1) ? NEGINF : s[nt][3]*rscale;
            mx0 = fmaxf(mx0, fmaxf(s[nt][0], s[nt][1]));
            mx1 = fmaxf(mx1, fmaxf(s[nt][2], s[nt][3]));
        }
        mx0 = fmaxf(mx0, __shfl_xor_sync(0xffffffffu, mx0, 1));
        mx0 = fmaxf(mx0, __shfl_xor_sync(0xffffffffu, mx0, 2));
        mx1 = fmaxf(mx1, __shfl_xor_sync(0xffffffffu, mx1, 1));
        mx1 = fmaxf(mx1, __shfl_xor_sync(0xffffffffu, mx1, 2));
        float mn0 = fmaxf(m0r, mx0), mn1 = fmaxf(m1r, mx1);
        float co0 = __expf(m0r - mn0), co1 = __expf(m1r - mn1);
        float sum0 = 0.f, sum1 = 0.f;
        #pragma unroll
        for (int nt = 0; nt < 16; nt++) {
            s[nt][0] = __expf(s[nt][0] - mn0);
            s[nt][1] = __expf(s[nt][1] - mn0);
            s[nt][2] = __expf(s[nt][2] - mn1);
            s[nt][3] = __expf(s[nt][3] - mn1);
            sum0 += s[nt][0] + s[nt][1];
            sum1 += s[nt][2] + s[nt][3];
        }
        sum0 += __shfl_xor_sync(0xffffffffu, sum0, 1);
        sum0 += __shfl_xor_sync(0xffffffffu, sum0, 2);
        sum1 += __shfl_xor_sync(0xffffffffu, sum1, 1);
        sum1 += __shfl_xor_sync(0xffffffffu, sum1, 2);
        l0r = l0r * co0 + sum0;  m0r = mn0;
        l1r = l1r * co1 + sum1;  m1r = mn1;

        #pragma unroll
        for (int nt = 0; nt < 16; nt++) {
            o[nt][0] *= co0; o[nt][1] *= co0;
            o[nt][2] *= co1; o[nt][3] *= co1;
        }

        #pragma unroll
        for (int ks = 0; ks < 8; ks++) {
            uint32_t ph[4], pl[4];
            split_pack(s[2*ks][0],   s[2*ks][1],   ph[0], pl[0]);
            split_pack(s[2*ks][2],   s[2*ks][3],   ph[1], pl[1]);
            split_pack(s[2*ks+1][0], s[2*ks+1][1], ph[2], pl[2]);
            split_pack(s[2*ks+1][2], s[2*ks+1][3], ph[3], pl[3]);
            const uint32_t krow = (uint32_t)(ks*16) + vRow;
            #pragma unroll
            for (int np = 0; np < 8; np++) {
                uint32_t vhf[4];
                ldsm_x4t(vhf, sb + VH0 + krow*FROWB + (uint32_t)(np*32) + vDof);
                mma_h(o[2*np],   ph, vhf[0], vhf[1]);
                mma_h(o[2*np],   pl, vhf[0], vhf[1]);
                mma_h(o[2*np+1], ph, vhf[2], vhf[3]);
                mma_h(o[2*np+1], pl, vhf[2], vhf[3]);
            }
        }
    }

    float inv0 = 1.f / l0r, inv1 = 1.f / l1r;
    float* Og = g_attn + headbase + (size_t)(q0 + w*16) * Dd;
    #pragma unroll
    for (int nt = 0; nt < 16; nt++) {
        *(float2*)&Og[(size_t)g*Dd     + nt*8 + 2*tq] = make_float2(o[nt][0]*inv0, o[nt][1]*inv0);
        *(float2*)&Og[(size_t)(g+8)*Dd + nt*8 + 2*tq] = make_float2(o[nt][2]*inv1, o[nt][3]*inv1);
    }
}

// ---------------- adapter attention (+ writes fp16 split of final attn) ----------------
__global__ __launch_bounds__(128) void adapter_kernel(const float* __restrict__ gate)
{
    __shared__ __align__(16) float ak[ALa][HDh];
    __shared__ __align__(16) float av[ALa][HDh];
    const int t = threadIdx.x;
    const int bh = blockIdx.y;
    const int b = bh >> 5, h = bh & 31;
    const int s0 = blockIdx.x * 4;

    #pragma unroll
    for (int r = 0; r < ALa; r++) {
        int idx = t + r*128;
        int j = idx >> 7, d = idx & 127;
        ak[j][d] = g_ak[(size_t)(b*ALa + j) * Dd + h*HDh + d];
        av[j][d] = g_av[(size_t)(b*ALa + j) * Dd + h*HDh + d];
    }
    __syncthreads();

    const int w = t >> 5, lane = t & 31;
    const int s = s0 + w;
    const size_t base = (size_t)(b*Ss + s) * Dd + h*HDh;
    const float rscale = 0.08838834764831844f;

    float4 qv = *(const float4*)&g_q[base + lane*4];
    float sc[ALa];
    #pragma unroll
    for (int j = 0; j < ALa; j++) {
        float d0 = qv.x*ak[j][lane*4+0] + qv.y*ak[j][lane*4+1]
                 + qv.z*ak[j][lane*4+2] + qv.w*ak[j][lane*4+3];
        #pragma unroll
        for (int off = 16; off >= 1; off >>= 1)
            d0 += __shfl_xor_sync(0xffffffffu, d0, off);
        sc[j] = d0 * rscale;
    }
    float mx = sc[0];
    #pragma unroll
    for (int j = 1; j < ALa; j++) mx = fmaxf(mx, sc[j]);
    float sum = 0.f;
    #pragma unroll
    for (int j = 0; j < ALa; j++) { sc[j] = __expf(sc[j] - mx); sum += sc[j]; }
    float inv = 1.f / sum;
    float gg = tanhf(gate[h]);

    float acc[4] = {0.f, 0.f, 0.f, 0.f};
    #pragma unroll
    for (int j = 0; j < ALa; j++) {
        float p = sc[j] * inv;
        acc[0] += p * av[j][lane*4+0];
        acc[1] += p * av[j][lane*4+1];
        acc[2] += p * av[j][lane*4+2];
        acc[3] += p * av[j][lane*4+3];
    }
    float4 ov = *(float4*)&g_attn[base + lane*4];
    ov.x += gg*acc[0]; ov.y += gg*acc[1]; ov.z += gg*acc[2]; ov.w += gg*acc[3];
    *(float4*)&g_attn[base + lane*4] = ov;

    __half h0 = __float2half_rn(ov.x), h1 = __float2half_rn(ov.y);
    __half h2 = __float2half_rn(ov.z), h3 = __float2half_rn(ov.w);
    *(__half2*)(g_ah + base + lane*4)     = __halves2half2(h0, h1);
    *(__half2*)(g_ah + base + lane*4 + 2) = __halves2half2(h2, h3);
    *(__half2*)(g_al + base + lane*4)     = __halves2half2(__float2half_rn(ov.x - __half2float(h0)),
                                                           __float2half_rn(ov.y - __half2float(h1)));
    *(__half2*)(g_al + base + lane*4 + 2) = __halves2half2(__float2half_rn(ov.z - __half2float(h2)),
                                                           __float2half_rn(ov.w - __half2float(h3)));
}

// ---------------- host ----------------
extern "C" void kernel_launch(void* const* d_in, const int* in_sizes, int n_in,
                              void* d_out, int out_size)
{
    (void)in_sizes; (void)n_in; (void)out_size;
    const float* x       = (const float*)d_in[0];
    const float* cosT    = (const float*)d_in[2];
    const float* sinT    = (const float*)d_in[3];
    const float* wq      = (const float*)d_in[4];
    const float* wk      = (const float*)d_in[5];
    const float* wv      = (const float*)d_in[6];
    const float* wo      = (const float*)d_in[7];
    const float* gate    = (const float*)d_in[8];
    const float* adapter = (const float*)d_in[9];
    float* out = (float*)d_out;

    float *qp, *kp;
    __half *ahp, *alp, *wqh, *wkh, *wvh, *woh;
    __half *qhp, *qlp, *khp, *vhp;
    cudaGetSymbolAddress((void**)&qp,    g_q);
    cudaGetSymbolAddress((void**)&kp,    g_k);
    cudaGetSymbolAddress((void**)&ahp,  g_ah);  cudaGetSymbolAddress((void**)&alp,  g_al);
    cudaGetSymbolAddress((void**)&wqh,  g_wqh);
    cudaGetSymbolAddress((void**)&wkh,  g_wkh);
    cudaGetSymbolAddress((void**)&wvh,  g_wvh);
    cudaGetSymbolAddress((void**)&woh,  g_woh);
    cudaGetSymbolAddress((void**)&qhp,  g_qh);  cudaGetSymbolAddress((void**)&qlp,  g_ql);
    cudaGetSymbolAddress((void**)&khp,  g_kh);
    cudaGetSymbolAddress((void**)&vhp,  g_vh);

    cudaFuncSetAttribute(gemm_h2f, cudaFuncAttributeMaxDynamicSharedMemorySize, GEMM2_SMEM);
    cudaFuncSetAttribute(gemm_h2h, cudaFuncAttributeMaxDynamicSharedMemorySize, GEMM2_SMEM);
    cudaFuncSetAttribute(gemm_h1f, cudaFuncAttributeMaxDynamicSharedMemorySize, GEMM1_SMEM);
    cudaFuncSetAttribute(flash_h, cudaFuncAttributeMaxDynamicSharedMemorySize, FLASH_SMEM);

    const int nXW = Mtok*Dd;
    const int cgrid = nXW/4/256;

    conv_split<<<cgrid, 256>>>(x,  ahp, alp, nXW);
    conv_hi<<<cgrid, 256>>>(wq, wqh, Dd*Dd);
    conv_hi<<<cgrid, 256>>>(wk, wkh, Dd*Dd);
    conv_hi<<<cgrid, 256>>>(wv, wvh, Dd*Dd);
    conv_hi<<<cgrid, 256>>>(wo, woh, Dd*Dd);

    dim3 gbig(Dd/BN, Mtok/BM);
    gemm_h1f<<<gbig, 256, GEMM1_SMEM>>>(ahp, wqh, qp, Mtok, Dd, Dd);
    gemm_h1f<<<gbig, 256, GEMM1_SMEM>>>(ahp, wkh, kp, Mtok, Dd, Dd);
    gemm_h2h<<<gbig, 256, GEMM2_SMEM>>>(ahp, alp, wvh, vhp, Mtok, Dd, Dd);

    gemm_skinny<<<dim3(Dd/128, KSPL, 2), 128>>>(adapter, wk, wv);
    skinny_reduce<<<(20*4096 + 255)/256, 256>>>();

    int npairs = Bb*Ss*Hh*HALFh;
    rope_split<<<npairs/256, 256>>>(qp, qhp, qlp, cosT, sinT);
    rope_hi<<<npairs/256, 256>>>(kp, khp, cosT, sinT);

    flash_h<<<dim3(Ss/FQ, Bb*Hh), 128, FLASH_SMEM>>>();
    adapter_kernel<<<dim3(Ss/4, Bb*Hh), 128>>>(gate);

    gemm_h2f<<<gbig, 256, GEMM2_SMEM>>>(ahp, alp, woh, out, Mtok, Dd, Dd);
}